// round 13
// baseline (speedup 1.0000x reference)
#include <cuda_runtime.h>
#include <cuda_bf16.h>
#include <math.h>
#include <stdint.h>

// Problem constants
#define BB 4
#define TT 2048
#define BT 8192      // B*T
#define DD 256
#define NN 8192
#define HH 4
#define MM 2048      // N/H
#define LL 6
#define VOCAB 256
#define EPS 1e-5f
#define SPLITK 8

// single dynamic-smem declaration shared by all kernels
extern __shared__ char dynsm[];

// ---------------- scratch buffers (device globals, no allocations) --------
__device__ float g_v[BT * DD];
__device__ float g_upart[SPLITK * BT * DD];                   // split-K partials
__device__ __nv_bfloat16 g_vhi[BT * DD], g_vlo[BT * DD];
__device__ __nv_bfloat16 g_Rhi[BT * DD], g_Rlo[BT * DD];
__device__ __nv_bfloat16 g_alnhi[BT * DD], g_alnlo[BT * DD];
__device__ __nv_bfloat16 g_wxhi[NN * DD], g_wxlo[NN * DD];
__device__ __nv_bfloat16 g_wyhi[NN * DD], g_wylo[NN * DD];
__device__ __nv_bfloat16 g_enchi[DD * NN], g_enclo[DD * NN];
__device__ __nv_bfloat16 g_rdhi[VOCAB * DD], g_rdlo[VOCAB * DD];
__device__ __nv_bfloat16 g_Yhi[(size_t)BT * NN];              // 128 MB
__device__ __nv_bfloat16 g_Ylo[(size_t)BT * NN];              // 128 MB
// linear-attention scratch
__device__ __nv_bfloat16 g_RThi[BB * DD * TT], g_RTlo[BB * DD * TT];
__device__ __nv_bfloat16 g_VThi[BB * DD * TT], g_VTlo[BB * DD * TT];
__device__ float g_H[(size_t)BB * 32 * DD * DD];
__device__ __nv_bfloat16 g_Mhi[(size_t)BB * 32 * DD * DD];
__device__ __nv_bfloat16 g_Mlo[(size_t)BB * 32 * DD * DD];

// ---------------- PTX helpers ----------------------------------------------
__device__ __forceinline__ uint32_t smem_u32(const void* p) {
    uint32_t a;
    asm("{ .reg .u64 t; cvta.to.shared.u64 t, %1; cvt.u32.u64 %0, t; }"
        : "=r"(a) : "l"(p));
    return a;
}

#define LDSM_X4(r0, r1, r2, r3, addr) \
    asm volatile("ldmatrix.sync.aligned.m8n8.x4.shared.b16 {%0,%1,%2,%3}, [%4];" \
        : "=r"(r0), "=r"(r1), "=r"(r2), "=r"(r3) : "r"(addr))

#define MMA_BF16(d, a, b) \
    asm volatile( \
        "mma.sync.aligned.m16n8k16.row.col.f32.bf16.bf16.f32 " \
        "{%0,%1,%2,%3}, {%4,%5,%6,%7}, {%8,%9}, {%0,%1,%2,%3};" \
        : "+f"((d)[0]), "+f"((d)[1]), "+f"((d)[2]), "+f"((d)[3]) \
        : "r"((a)[0]), "r"((a)[1]), "r"((a)[2]), "r"((a)[3]), \
          "r"((b)[0]), "r"((b)[1]))

#define CP_ASYNC16(dst, src) \
    asm volatile("cp.async.cg.shared.global [%0], [%1], 16;" \
        :: "r"(dst), "l"(src) : "memory")
#define CP_COMMIT() asm volatile("cp.async.commit_group;" ::: "memory")
#define CP_WAIT(N)  asm volatile("cp.async.wait_group %0;" :: "n"(N) : "memory")

// ---------------- misc helpers ----------------------------------------------
__device__ __forceinline__ float warp_sum(float v) {
#pragma unroll
    for (int o = 16; o > 0; o >>= 1) v += __shfl_xor_sync(0xffffffffu, v, o);
    return v;
}
__device__ __forceinline__ void split2(float x, __nv_bfloat16& h, __nv_bfloat16& l) {
    __nv_bfloat16 hh = __float2bfloat16(x);
    h = hh;
    l = __float2bfloat16(x - __bfloat162float(hh));
}
__device__ __forceinline__ float rope_val(const float* rowbuf, int d, int t) {
    float x = rowbuf[d];
    float xr = (d < 128) ? -rowbuf[d + 128] : rowbuf[d - 128];
    int j = d & 127;
    float inv = expf(-(float)j * (2.f / 256.f) * 9.210340371976184f);
    float ang = (float)t * inv;
    const float TWO_PI_HI = 6.28318548202514648f;
    const float TWO_PI_LO = -1.74845553e-7f;
    float k = rintf(ang * 0.15915494309189535f);
    float r = fmaf(-k, TWO_PI_HI, ang);
    r = fmaf(-k, TWO_PI_LO, r);
    float sn = sinf(r), cs = cosf(r);
    return x * cs + xr * sn;
}

// ---------------- all weight conversions in one kernel ----------------------
__global__ void conv_all_kernel(const float* __restrict__ dec_x,
                                const float* __restrict__ dec_y,
                                const float* __restrict__ enc,
                                const float* __restrict__ rd,
                                __nv_bfloat16* __restrict__ wxhi, __nv_bfloat16* __restrict__ wxlo,
                                __nv_bfloat16* __restrict__ wyhi, __nv_bfloat16* __restrict__ wylo,
                                __nv_bfloat16* __restrict__ enchi, __nv_bfloat16* __restrict__ enclo,
                                __nv_bfloat16* __restrict__ rdhi, __nv_bfloat16* __restrict__ rdlo) {
    int bid = blockIdx.x;
    if (bid < 8192) {
        size_t i = (size_t)bid * 256 + threadIdx.x;
        int d = (int)(i & 255);
        size_t n = i >> 8;
        int h = (int)(n >> 11), m = (int)(n & 2047);
        split2(dec_x[((size_t)h * DD + d) * MM + m], wxhi[i], wxlo[i]);
    } else if (bid < 16384) {
        size_t i = (size_t)(bid - 8192) * 256 + threadIdx.x;
        int d = (int)(i & 255);
        size_t n = i >> 8;
        int h = (int)(n >> 11), m = (int)(n & 2047);
        split2(dec_y[((size_t)h * DD + d) * MM + m], wyhi[i], wylo[i]);
    } else if (bid < 24576) {
        size_t i = (size_t)(bid - 16384) * 256 + threadIdx.x;
        int n = (int)(i & 8191);
        int d = (int)(i >> 13);
        split2(enc[(size_t)n * DD + d], enchi[i], enclo[i]);
    } else {
        size_t i = (size_t)(bid - 24576) * 256 + threadIdx.x;
        int d = (int)(i & 255);
        int v = (int)(i >> 8);
        split2(rd[(size_t)d * VOCAB + v], rdhi[i], rdlo[i]);
    }
}

// ---------------- embed + LN + RoPE ------------------------------------------
__global__ void embed_ln_rope_kernel(const int* __restrict__ idx,
                                     const float* __restrict__ wte,
                                     float* __restrict__ out,
                                     __nv_bfloat16* __restrict__ ohi,
                                     __nv_bfloat16* __restrict__ olo,
                                     __nv_bfloat16* __restrict__ Rhi,
                                     __nv_bfloat16* __restrict__ Rlo) {
    __shared__ float sh[8];
    __shared__ float rowbuf[256];
    int row = blockIdx.x;
    int d = threadIdx.x;
    float x = wte[idx[row] * DD + d];
    int wid = d >> 5, lane = d & 31;
    float s = warp_sum(x);
    if (lane == 0) sh[wid] = s;
    __syncthreads();
    float tot = 0.f;
#pragma unroll
    for (int i = 0; i < 8; i++) tot += sh[i];
    float mu = tot * (1.f / 256.f);
    __syncthreads();
    float dx = x - mu;
    s = warp_sum(dx * dx);
    if (lane == 0) sh[wid] = s;
    __syncthreads();
    tot = 0.f;
#pragma unroll
    for (int i = 0; i < 8; i++) tot += sh[i];
    float r = dx * rsqrtf(tot * (1.f / 256.f) + EPS);
    out[row * DD + d] = r;
    split2(r, ohi[row * DD + d], olo[row * DD + d]);
    rowbuf[d] = r;
    __syncthreads();
    float val = rope_val(rowbuf, d, row & (TT - 1));
    split2(val, Rhi[row * DD + d], Rlo[row * DD + d]);
}

// ---------------- LN + residual add (sums SPLITK partials) + RoPE -----------
__global__ void ln_add_rope_kernel(const float* __restrict__ up,
                                   float* __restrict__ v,
                                   __nv_bfloat16* __restrict__ vhi,
                                   __nv_bfloat16* __restrict__ vlo,
                                   __nv_bfloat16* __restrict__ Rhi,
                                   __nv_bfloat16* __restrict__ Rlo) {
    __shared__ float sh[8];
    __shared__ float rowbuf[256];
    int row = blockIdx.x;
    int d = threadIdx.x;
    int o = row * DD + d;
    float x = 0.f;
#pragma unroll
    for (int p = 0; p < SPLITK; p++) x += up[(size_t)p * BT * DD + o];
    int wid = d >> 5, lane = d & 31;
    float s = warp_sum(x);
    if (lane == 0) sh[wid] = s;
    __syncthreads();
    float tot = 0.f;
#pragma unroll
    for (int i = 0; i < 8; i++) tot += sh[i];
    float mu = tot * (1.f / 256.f);
    __syncthreads();
    float dx = x - mu;
    s = warp_sum(dx * dx);
    if (lane == 0) sh[wid] = s;
    __syncthreads();
    tot = 0.f;
#pragma unroll
    for (int i = 0; i < 8; i++) tot += sh[i];
    float nv = v[o] + dx * rsqrtf(tot * (1.f / 256.f) + EPS);
    v[o] = nv;
    split2(nv, vhi[o], vlo[o]);
    rowbuf[d] = nv;
    __syncthreads();
    float val = rope_val(rowbuf, d, row & (TT - 1));
    split2(val, Rhi[o], Rlo[o]);
}

// ---------------- transpose (pure bf16 permute) for R and v hi/lo -----------
__global__ void split_T_both_kernel(const __nv_bfloat16* __restrict__ Rhi,
                                    const __nv_bfloat16* __restrict__ Rlo,
                                    const __nv_bfloat16* __restrict__ vhi,
                                    const __nv_bfloat16* __restrict__ vlo,
                                    __nv_bfloat16* __restrict__ RThi,
                                    __nv_bfloat16* __restrict__ RTlo,
                                    __nv_bfloat16* __restrict__ VThi,
                                    __nv_bfloat16* __restrict__ VTlo) {
    __shared__ __nv_bfloat16 th[32][34];
    __shared__ __nv_bfloat16 tl[32][34];
    int zb = blockIdx.z;
    int b = zb & 3;
    const __nv_bfloat16* hi_in = (zb < 4) ? Rhi : vhi;
    const __nv_bfloat16* lo_in = (zb < 4) ? Rlo : vlo;
    __nv_bfloat16* hi_out = (zb < 4) ? RThi : VThi;
    __nv_bfloat16* lo_out = (zb < 4) ? RTlo : VTlo;
    int t0 = blockIdx.x * 32;
    int d0 = blockIdx.y * 32;
    int tx = threadIdx.x & 31, ty = threadIdx.x >> 5;
#pragma unroll
    for (int i = 0; i < 4; i++) {
        int t = ty + i * 8;
        size_t g = ((size_t)(b * TT + t0 + t)) * DD + d0 + tx;
        th[t][tx] = hi_in[g];
        tl[t][tx] = lo_in[g];
    }
    __syncthreads();
#pragma unroll
    for (int i = 0; i < 4; i++) {
        int d = ty + i * 8;
        size_t o = ((size_t)(b * DD + d0 + d)) * TT + t0 + tx;
        hi_out[o] = th[tx][d];
        lo_out[o] = tl[tx][d];
    }
}

// ---------------- kv_outer: H[b][i] = V_i^T K_i (256x256, k=64) -------------
#define KVO_SMEM 110592
__global__ void __launch_bounds__(512, 1)
kv_outer_kernel(const __nv_bfloat16* __restrict__ VThi,
                const __nv_bfloat16* __restrict__ VTlo,
                const __nv_bfloat16* __restrict__ RThi,
                const __nv_bfloat16* __restrict__ RTlo,
                float* __restrict__ H) {
    char* smc = dynsm;
    uint32_t sb = smem_u32(smc);
    int i = blockIdx.x, b = blockIdx.y, e0 = blockIdx.z * 128;
    int s0 = i * 64;
    int tid = threadIdx.x;
    int wid = tid >> 5, lane = tid & 31;
    int wm = wid & 3, wn = wid >> 2;

    for (int l = tid; l < 1024; l += 512) {
        int r = l >> 3, c = l & 7;
        size_t g = ((size_t)(b * DD + e0 + r)) * TT + s0 + c * 8;
        uint32_t so = (uint32_t)(r * 144 + c * 16);
        *(uint4*)(smc + so) = *(const uint4*)(VThi + g);
        *(uint4*)(smc + 18432 + so) = *(const uint4*)(VTlo + g);
    }
    for (int l = tid; l < 2048; l += 512) {
        int r = l >> 3, c = l & 7;
        size_t g = ((size_t)(b * DD + r)) * TT + s0 + c * 8;
        uint32_t so = (uint32_t)(36864 + r * 144 + c * 16);
        *(uint4*)(smc + so) = *(const uint4*)(RThi + g);
        *(uint4*)(smc + 36864 + so) = *(const uint4*)(RTlo + g);
    }
    __syncthreads();

    uint32_t a_row_l = (uint32_t)(lane & 15);
    uint32_t a_col_l = (uint32_t)((lane >> 4) << 3);
    uint32_t b_row_l = (uint32_t)(((lane & 16) >> 1) + (lane & 7));
    uint32_t b_col_l = (uint32_t)(lane & 8);

    float acc[2][8][4] = {};
#pragma unroll
    for (int ks = 0; ks < 4; ks++) {
        uint32_t ah[2][4], al[2][4];
#pragma unroll
        for (int mi = 0; mi < 2; mi++) {
            uint32_t ad = sb + (uint32_t)(wm * 32 + mi * 16 + a_row_l) * 144
                        + (uint32_t)(ks * 16 + a_col_l) * 2;
            LDSM_X4(ah[mi][0], ah[mi][1], ah[mi][2], ah[mi][3], ad);
            LDSM_X4(al[mi][0], al[mi][1], al[mi][2], al[mi][3], ad + 18432);
        }
        uint32_t bh[8][2], bl[8][2];
#pragma unroll
        for (int p = 0; p < 4; p++) {
            uint32_t bd = sb + 36864 + (uint32_t)(wn * 64 + p * 16 + b_row_l) * 144
                        + (uint32_t)(ks * 16 + b_col_l) * 2;
            uint32_t q0, q1, q2, q3;
            LDSM_X4(q0, q1, q2, q3, bd);
            bh[2 * p][0] = q0; bh[2 * p][1] = q1;
            bh[2 * p + 1][0] = q2; bh[2 * p + 1][1] = q3;
            LDSM_X4(q0, q1, q2, q3, bd + 36864);
            bl[2 * p][0] = q0; bl[2 * p][1] = q1;
            bl[2 * p + 1][0] = q2; bl[2 * p + 1][1] = q3;
        }
#pragma unroll
        for (int mi = 0; mi < 2; mi++)
#pragma unroll
            for (int nt = 0; nt < 8; nt++)
                MMA_BF16(acc[mi][nt], ah[mi], bh[nt]);
#pragma unroll
        for (int mi = 0; mi < 2; mi++)
#pragma unroll
            for (int nt = 0; nt < 8; nt++)
                MMA_BF16(acc[mi][nt], ah[mi], bl[nt]);
#pragma unroll
        for (int mi = 0; mi < 2; mi++)
#pragma unroll
            for (int nt = 0; nt < 8; nt++)
                MMA_BF16(acc[mi][nt], al[mi], bh[nt]);
    }

    int tr = lane >> 2, tc = (lane & 3) * 2;
    size_t base = ((size_t)(b * 32 + i)) * 65536;
#pragma unroll
    for (int mi = 0; mi < 2; mi++) {
        int e = e0 + wm * 32 + mi * 16 + tr;
#pragma unroll
        for (int nt = 0; nt < 8; nt++) {
            int d = wn * 64 + nt * 8 + tc;
            *(float2*)&H[base + (size_t)e * 256 + d] =
                make_float2(acc[mi][nt][0], acc[mi][nt][1]);
            *(float2*)&H[base + (size_t)(e + 8) * 256 + d] =
                make_float2(acc[mi][nt][2], acc[mi][nt][3]);
        }
    }
}

// ---------------- exclusive prefix over chunks + bf16 split -----------------
__global__ void prefix_split_kernel(const float* __restrict__ H,
                                    __nv_bfloat16* __restrict__ Mhi,
                                    __nv_bfloat16* __restrict__ Mlo) {
    int b = blockIdx.y;
    int j = blockIdx.x * 256 + threadIdx.x;
    size_t base = (size_t)b * 32 * 65536 + j;
    float acc = 0.f;
#pragma unroll 4
    for (int i = 0; i < 32; i++) {
        size_t off = base + (size_t)i * 65536;
        __nv_bfloat16 h, l;
        split2(acc, h, l);
        Mhi[off] = h;
        Mlo[off] = l;
        acc += H[off];
    }
}

// ---------------- attn_out + fused row-LN ------------------------------------
#define AO_Q    0
#define AO_QLO  33792
#define AO_B    67584
#define AO_BLO  104448
#define AO_S    141312
#define AO_SLO  150528
#define AO_OBUF 67584
#define AO_SMEM 159744
__global__ void __launch_bounds__(256, 1)
attn_out_kernel(const __nv_bfloat16* __restrict__ Rhi,
                const __nv_bfloat16* __restrict__ Rlo,
                const __nv_bfloat16* __restrict__ VThi,
                const __nv_bfloat16* __restrict__ VTlo,
                const __nv_bfloat16* __restrict__ Mhi,
                const __nv_bfloat16* __restrict__ Mlo,
                __nv_bfloat16* __restrict__ alnhi,
                __nv_bfloat16* __restrict__ alnlo) {
    char* smc = dynsm;
    uint32_t sb = smem_u32(smc);
    int i = blockIdx.x, b = blockIdx.y;
    int q0 = i * 64;
    int tid = threadIdx.x;
    int wid = tid >> 5, lane = tid & 31;

    for (int l = tid; l < 2048; l += 256) {
        int r = l >> 5, c = l & 31;
        size_t g = ((size_t)(b * TT + q0 + r)) * DD + c * 8;
        uint32_t so = (uint32_t)(r * 528 + c * 16);
        *(uint4*)(smc + AO_Q + so) = *(const uint4*)(Rhi + g);
        *(uint4*)(smc + AO_QLO + so) = *(const uint4*)(Rlo + g);
    }
    for (int l = tid; l < 2048; l += 256) {
        int r = l >> 3, c = l & 7;
        size_t g = ((size_t)(b * DD + r)) * TT + q0 + c * 8;
        uint32_t so = (uint32_t)(r * 144 + c * 16);
        *(uint4*)(smc + AO_B + so) = *(const uint4*)(VThi + g);
        *(uint4*)(smc + AO_BLO + so) = *(const uint4*)(VTlo + g);
    }
    __syncthreads();

    uint32_t a_row_l = (uint32_t)(lane & 15);
    uint32_t a_col_l = (uint32_t)((lane >> 4) << 3);
    uint32_t b_row_l = (uint32_t)(((lane & 16) >> 1) + (lane & 7));
    uint32_t b_col_l = (uint32_t)(lane & 8);
    int tr = lane >> 2, tc = (lane & 3) * 2;

    int wt = wid & 1, ws = wid >> 1;
    {
        float sacc[2][2][4] = {};
#pragma unroll
        for (int ks = 0; ks < 16; ks++) {
            uint32_t ah[2][4], al[2][4];
#pragma unroll
            for (int mi = 0; mi < 2; mi++) {
                uint32_t ad = sb + AO_Q + (uint32_t)(wt * 32 + mi * 16 + a_row_l) * 528
                            + (uint32_t)(ks * 16 + a_col_l) * 2;
                LDSM_X4(ah[mi][0], ah[mi][1], ah[mi][2], ah[mi][3], ad);
                LDSM_X4(al[mi][0], al[mi][1], al[mi][2], al[mi][3], ad + 33792);
            }
            uint32_t bh[2][2], bl[2][2];
            {
                uint32_t bd = sb + AO_Q + (uint32_t)(ws * 16 + b_row_l) * 528
                            + (uint32_t)(ks * 16 + b_col_l) * 2;
                uint32_t p0, p1, p2, p3;
                LDSM_X4(p0, p1, p2, p3, bd);
                bh[0][0] = p0; bh[0][1] = p1; bh[1][0] = p2; bh[1][1] = p3;
                LDSM_X4(p0, p1, p2, p3, bd + 33792);
                bl[0][0] = p0; bl[0][1] = p1; bl[1][0] = p2; bl[1][1] = p3;
            }
#pragma unroll
            for (int mi = 0; mi < 2; mi++)
#pragma unroll
                for (int ni = 0; ni < 2; ni++) {
                    MMA_BF16(sacc[mi][ni], ah[mi], bh[ni]);
                    MMA_BF16(sacc[mi][ni], ah[mi], bl[ni]);
                    MMA_BF16(sacc[mi][ni], al[mi], bh[ni]);
                }
        }
#pragma unroll
        for (int mi = 0; mi < 2; mi++)
#pragma unroll
            for (int ni = 0; ni < 2; ni++) {
                int t0l = wt * 32 + mi * 16 + tr;
                int sl = ws * 16 + ni * 8 + tc;
                float s0v = (sl > t0l) ? 0.f : sacc[mi][ni][0];
                float s1v = (sl + 1 > t0l) ? 0.f : sacc[mi][ni][1];
                float s2v = (sl > t0l + 8) ? 0.f : sacc[mi][ni][2];
                float s3v = (sl + 1 > t0l + 8) ? 0.f : sacc[mi][ni][3];
                __nv_bfloat16 h0, l0, h1, l1;
                split2(s0v, h0, l0); split2(s1v, h1, l1);
                *(__nv_bfloat162*)(smc + AO_S + t0l * 144 + sl * 2) = __halves2bfloat162(h0, h1);
                *(__nv_bfloat162*)(smc + AO_SLO + t0l * 144 + sl * 2) = __halves2bfloat162(l0, l1);
                split2(s2v, h0, l0); split2(s3v, h1, l1);
                *(__nv_bfloat162*)(smc + AO_S + (t0l + 8) * 144 + sl * 2) = __halves2bfloat162(h0, h1);
                *(__nv_bfloat162*)(smc + AO_SLO + (t0l + 8) * 144 + sl * 2) = __halves2bfloat162(l0, l1);
            }
    }
    __syncthreads();

    int we = wid >> 1;
    float oacc[2][8][4] = {};
#pragma unroll
    for (int ks = 0; ks < 4; ks++) {
        uint32_t ah[2][4], al[2][4];
#pragma unroll
        for (int mi = 0; mi < 2; mi++) {
            uint32_t ad = sb + AO_S + (uint32_t)(wt * 32 + mi * 16 + a_row_l) * 144
                        + (uint32_t)(ks * 16 + a_col_l) * 2;
            LDSM_X4(ah[mi][0], ah[mi][1], ah[mi][2], ah[mi][3], ad);
            LDSM_X4(al[mi][0], al[mi][1], al[mi][2], al[mi][3], ad + 9216);
        }
        uint32_t bh[8][2], bl[8][2];
#pragma unroll
        for (int p = 0; p < 4; p++) {
            uint32_t bd = sb + AO_B + (uint32_t)(we * 64 + p * 16 + b_row_l) * 144
                        + (uint32_t)(ks * 16 + b_col_l) * 2;
            uint32_t p0, p1, p2, p3;
            LDSM_X4(p0, p1, p2, p3, bd);
            bh[2 * p][0] = p0; bh[2 * p][1] = p1;
            bh[2 * p + 1][0] = p2; bh[2 * p + 1][1] = p3;
            LDSM_X4(p0, p1, p2, p3, bd + 36864);
            bl[2 * p][0] = p0; bl[2 * p][1] = p1;
            bl[2 * p + 1][0] = p2; bl[2 * p + 1][1] = p3;
        }
#pragma unroll
        for (int mi = 0; mi < 2; mi++)
#pragma unroll
            for (int nt = 0; nt < 8; nt++) {
                MMA_BF16(oacc[mi][nt], ah[mi], bh[nt]);
                MMA_BF16(oacc[mi][nt], ah[mi], bl[nt]);
                MMA_BF16(oacc[mi][nt], al[mi], bh[nt]);
            }
    }
    __syncthreads();

    size_t mbase = ((size_t)(b * 32 + i)) * 65536;
    for (int dc = 0; dc < 4; dc++) {
        for (int l = tid; l < 2048; l += 256) {
            int r = l >> 3, c = l & 7;
            size_t g = mbase + (size_t)r * 256 + dc * 64 + c * 8;
            uint32_t so = (uint32_t)(r * 144 + c * 16);
            *(uint4*)(smc + AO_B + so) = *(const uint4*)(Mhi + g);
            *(uint4*)(smc + AO_BLO + so) = *(const uint4*)(Mlo + g);
        }
        __syncthreads();
#pragma unroll
        for (int ks = 0; ks < 4; ks++) {
            int ksg = dc * 4 + ks;
            uint32_t ah[2][4], al[2][4];
#pragma unroll
            for (int mi = 0; mi < 2; mi++) {
                uint32_t ad = sb + AO_Q + (uint32_t)(wt * 32 + mi * 16 + a_row_l) * 528
                            + (uint32_t)(ksg * 16 + a_col_l) * 2;
                LDSM_X4(ah[mi][0], ah[mi][1], ah[mi][2], ah[mi][3], ad);
                LDSM_X4(al[mi][0], al[mi][1], al[mi][2], al[mi][3], ad + 33792);
            }
            uint32_t bh[8][2], bl[8][2];
#pragma unroll
            for (int p = 0; p < 4; p++) {
                uint32_t bd = sb + AO_B + (uint32_t)(we * 64 + p * 16 + b_row_l) * 144
                            + (uint32_t)(ks * 16 + b_col_l) * 2;
                uint32_t p0, p1, p2, p3;
                LDSM_X4(p0, p1, p2, p3, bd);
                bh[2 * p][0] = p0; bh[2 * p][1] = p1;
                bh[2 * p + 1][0] = p2; bh[2 * p + 1][1] = p3;
                LDSM_X4(p0, p1, p2, p3, bd + 36864);
                bl[2 * p][0] = p0; bl[2 * p][1] = p1;
                bl[2 * p + 1][0] = p2; bl[2 * p + 1][1] = p3;
            }
#pragma unroll
            for (int mi = 0; mi < 2; mi++)
#pragma unroll
                for (int nt = 0; nt < 8; nt++) {
                    MMA_BF16(oacc[mi][nt], ah[mi], bh[nt]);
                    MMA_BF16(oacc[mi][nt], ah[mi], bl[nt]);
                    MMA_BF16(oacc[mi][nt], al[mi], bh[nt]);
                }
        }
        __syncthreads();
    }

    float* obuf = (float*)(smc + AO_OBUF);
#pragma unroll
    for (int mi = 0; mi < 2; mi++) {
        int rl = wt * 32 + mi * 16 + tr;
#pragma unroll
        for (int nt = 0; nt < 8; nt++) {
            int col = we * 64 + nt * 8 + tc;
            obuf[rl * 260 + col] = oacc[mi][nt][0];
            obuf[rl * 260 + col + 1] = oacc[mi][nt][1];
            obuf[(rl + 8) * 260 + col] = oacc[mi][nt][2];
            obuf[(rl + 8) * 260 + col + 1] = oacc[mi][nt][3];
        }
    }
    __syncthreads();

    for (int rr2 = 0; rr2 < 8; rr2++) {
        int r = wid * 8 + rr2;
        float vals[8];
        float s = 0.f;
#pragma unroll
        for (int k = 0; k < 8; k++) {
            vals[k] = obuf[r * 260 + lane + 32 * k];
            s += vals[k];
        }
        s = warp_sum(s);
        float mu = s * (1.f / 256.f);
        float q = 0.f;
#pragma unroll
        for (int k = 0; k < 8; k++) {
            float dxx = vals[k] - mu;
            q += dxx * dxx;
        }
        q = warp_sum(q);
        float rstd = rsqrtf(q * (1.f / 256.f) + EPS);
        size_t gbase = ((size_t)(b * TT + q0 + r)) * DD;
#pragma unroll
        for (int k = 0; k < 8; k++) {
            __nv_bfloat16 h, l;
            split2((vals[k] - mu) * rstd, h, l);
            alnhi[gbase + lane + 32 * k] = h;
            alnlo[gbase + lane + 32 * k] = l;
        }
    }
}

// ---------------- fused XY GEMM (256 threads, warp tile 32x64) ---------------
// grid: (BT/128, NN/128) — row-block fastest for L2-resident waves.
#define XT 10240                // 128 rows * 80B (32 bf16 cols padded)
#define XSTG (8 * XT)           // 81920
#define XY_SMEM (2 * XSTG)      // 163840
__global__ void __launch_bounds__(256, 1)
xy_gemm(const __nv_bfloat16* __restrict__ vhi, const __nv_bfloat16* __restrict__ vlo,
        const __nv_bfloat16* __restrict__ alnhi, const __nv_bfloat16* __restrict__ alnlo,
        const __nv_bfloat16* __restrict__ wxhi, const __nv_bfloat16* __restrict__ wxlo,
        const __nv_bfloat16* __restrict__ wyhi, const __nv_bfloat16* __restrict__ wylo,
        __nv_bfloat16* __restrict__ Yhi, __nv_bfloat16* __restrict__ Ylo) {
    char* smc = dynsm;
    uint32_t sb = smem_u32(smc);

    int tid = threadIdx.x;
    int wid = tid >> 5;
    int lane = tid & 31;
    int warp_m = wid & 3;
    int warp_n = wid >> 2;

    int m0 = blockIdx.x * 128;   // row block (fastest grid dim)
    int n0 = blockIdx.y * 128;   // weight/col block

    float accx[2][8][4] = {};
    float accy[2][8][4] = {};

    uint32_t a_row_l = (uint32_t)(lane & 15);
    uint32_t a_col_l = (uint32_t)((lane >> 4) << 3);
    uint32_t b_row_l = (uint32_t)(((lane & 16) >> 1) + (lane & 7));
    uint32_t b_col_l = (uint32_t)(lane & 8);

    int rr = tid >> 2;
    int cc = tid & 3;

#define XY_ISSUE(st, kc) do {                                                  \
    uint32_t sbase = sb + (uint32_t)(st) * XSTG;                               \
    _Pragma("unroll")                                                          \
    for (int q = 0; q < 16; q++) {                                             \
        int tile = q >> 1;                                                     \
        int r = ((q & 1) << 6) + rr;                                           \
        const __nv_bfloat16* mat;                                              \
        int rb;                                                                \
        switch (tile) {                                                        \
            case 0: mat = vhi;   rb = m0; break;                               \
            case 1: mat = vlo;   rb = m0; break;                               \
            case 2: mat = alnhi; rb = m0; break;                               \
            case 3: mat = alnlo; rb = m0; break;                               \
            case 4: mat = wxhi;  rb = n0; break;                               \
            case 5: mat = wxlo;  rb = n0; break;                               \
            case 6: mat = wyhi;  rb = n0; break;                               \
            default: mat = wylo; rb = n0; break;                               \
        }                                                                      \
        size_t g = (size_t)(rb + r) * DD + (kc) + cc * 8;                      \
        uint32_t dst = sbase + (uint32_t)tile * XT + (uint32_t)(r * 80 + cc * 16); \
        CP_ASYNC16(dst, (const void*)(mat + g));                               \
    }                                                                          \
} while (0)

    XY_ISSUE(0, 0);
    CP_COMMIT();

    for (int ch = 0; ch < 8; ch++) {
        if (ch + 1 < 8) {
            XY_ISSUE((ch + 1) & 1, (ch + 1) << 5);
            CP_COMMIT();
            CP_WAIT(1);
        } else {
            CP_WAIT(0);
        }
        __syncthreads();

        uint32_t S = sb + (uint32_t)(ch & 1) * XSTG;
#pragma unroll
        for (int ks = 0; ks < 2; ks++) {
            uint32_t arow_off = (uint32_t)(warp_m * 32 + a_row_l) * 80
                              + (uint32_t)(ks * 16 + a_col_l) * 2;
            uint32_t brow_off = (uint32_t)(warp_n * 64 + b_row_l) * 80
                              + (uint32_t)(ks * 16 + b_col_l) * 2;
            uint32_t ah[2][4], al[2][4], bh[8][2], bl[8][2];
            // ---- X: A = v, B = wx ----
#pragma unroll
            for (int mt = 0; mt < 2; mt++) {
                uint32_t ad = S + arow_off + (uint32_t)(mt * 16 * 80);
                LDSM_X4(ah[mt][0], ah[mt][1], ah[mt][2], ah[mt][3], ad);
                LDSM_X4(al[mt][0], al[mt][1], al[mt][2], al[mt][3], ad + XT);
            }
#pragma unroll
            for (int p = 0; p < 4; p++) {
                uint32_t bd = S + 4 * XT + brow_off + (uint32_t)(p * 16 * 80);
                uint32_t q0, q1, q2, q3;
                LDSM_X4(q0, q1, q2, q3, bd);
                bh[2 * p][0] = q0; bh[2 * p][1] = q1;
                bh[2 * p + 1][0] = q2; bh[2 * p + 1][1] = q3;
                LDSM_X4(q0, q1, q2, q3, bd + XT);
                bl[2 * p][0] = q0; bl[2 * p][1] = q1;
                bl[2 * p + 1][0] = q2; bl[2 * p + 1][1] = q3;
            }
#pragma unroll
            for (int mt = 0; mt < 2; mt++)
#pragma unroll
                for (int nt = 0; nt < 8; nt++)
                    MMA_BF16(accx[mt][nt], ah[mt], bh[nt]);
#pragma unroll
            for (int mt = 0; mt < 2; mt++)
#pragma unroll
                for (int nt = 0; nt < 8; nt++)
                    MMA_BF16(accx[mt][nt], ah[mt], bl[nt]);
#pragma unroll
            for (int mt = 0; mt < 2; mt++)
#pragma unroll
                for (int nt = 0; nt < 8; nt++)
                    MMA_BF16(accx[mt][nt], al[mt], bh[nt]);
            // ---- Y: A = aln, B = wy ----
#pragma unroll
            for (int mt = 0; mt < 2; mt++) {
                uint32_t ad = S + 2 * XT + arow_off + (uint32_t)(mt * 16 * 80);
                LDSM_X4(ah[mt][0], ah[mt][1], ah[mt][2], ah[mt][3], ad);
                LDSM_X4(al[mt][0], al[mt][1], al[mt][2], al[mt][3], ad + XT);
            }
#pragma unroll
            for (int p = 0; p < 4; p++) {
                uint32_t bd = S + 6 * XT + brow_off + (uint32_t)(p * 16 * 80);
                uint32_t q0, q1, q2, q3;
                LDSM_X4(q0, q1, q2, q3, bd);
                bh[2 * p][0] = q0; bh[2 * p][1] = q1;
                bh[2 * p + 1][0] = q2; bh[2 * p + 1][1] = q3;
                LDSM_X4(q0, q1, q2, q3, bd + XT);
                bl[2 * p][0] = q0; bl[2 * p][1] = q1;
                bl[2 * p + 1][0] = q2; bl[2 * p + 1][1] = q3;
            }
#pragma unroll
            for (int mt = 0; mt < 2; mt++)
#pragma unroll
                for (int nt = 0; nt < 8; nt++)
                    MMA_BF16(accy[mt][nt], ah[mt], bh[nt]);
#pragma unroll
            for (int mt = 0; mt < 2; mt++)
#pragma unroll
                for (int nt = 0; nt < 8; nt++)
                    MMA_BF16(accy[mt][nt], ah[mt], bl[nt]);
#pragma unroll
            for (int mt = 0; mt < 2; mt++)
#pragma unroll
                for (int nt = 0; nt < 8; nt++)
                    MMA_BF16(accy[mt][nt], al[mt], bh[nt]);
        }
        __syncthreads();
    }

    int tr = lane >> 2;
    int tc = (lane & 3) * 2;
#pragma unroll
    for (int mt = 0; mt < 2; mt++) {
        int row = m0 + warp_m * 32 + mt * 16 + tr;
#pragma unroll
        for (int nt = 0; nt < 8; nt++) {
            int col = n0 + warp_n * 64 + nt * 8 + tc;
            size_t i0 = (size_t)row * NN + col;
            size_t i1 = (size_t)(row + 8) * NN + col;
            float g0 = fmaxf(accx[mt][nt][0], 0.f) * fmaxf(accy[mt][nt][0], 0.f);
            float g1 = fmaxf(accx[mt][nt][1], 0.f) * fmaxf(accy[mt][nt][1], 0.f);
            float g2 = fmaxf(accx[mt][nt][2], 0.f) * fmaxf(accy[mt][nt][2], 0.f);
            float g3 = fmaxf(accx[mt][nt][3], 0.f) * fmaxf(accy[mt][nt][3], 0.f);
            __nv_bfloat16 h0, l0, h1, l1;
            split2(g0, h0, l0); split2(g1, h1, l1);
            *(__nv_bfloat162*)(Yhi + i0) = __halves2bfloat162(h0, h1);
            *(__nv_bfloat162*)(Ylo + i0) = __halves2bfloat162(l0, l1);
            split2(g2, h0, l0); split2(g3, h1, l1);
            *(__nv_bfloat162*)(Yhi + i1) = __halves2bfloat162(h0, h1);
            *(__nv_bfloat162*)(Ylo + i1) = __halves2bfloat162(l0, l1);
        }
    }
}

// ---------------- HMMA GEMM (256 threads, 32x64 warp tile, 3-stage, split-K) -
#define TILE_B 18432
#define STAGE_B (4 * TILE_B)
#define TCG_STAGES 3
#define TCG_SMEM (TCG_STAGES * STAGE_B)     // 221184
__global__ void __launch_bounds__(256, 1)
tc_gemm(const __nv_bfloat16* __restrict__ Ahi, const __nv_bfloat16* __restrict__ Alo,
        const __nv_bfloat16* __restrict__ Bhi, const __nv_bfloat16* __restrict__ Blo,
        int Kslice, int lda, int ldb,
        float* __restrict__ C, int ldc, size_t cstride) {
    char* smc = dynsm;
    uint32_t sb = smem_u32(smc);

    int tid = threadIdx.x;
    int wid = tid >> 5;
    int lane = tid & 31;
    int warp_m = wid & 3;
    int warp_n = wid >> 2;

    int m0 = blockIdx.y * 128;
    int n0 = blockIdx.x * 128;
    int koff = blockIdx.z * Kslice;
    C += (size_t)blockIdx.z * cstride;

    float acc[2][8][4] = {};

    uint32_t a_row_l = (uint32_t)(lane & 15);
    uint32_t a_col_l = (uint32_t)((lane >> 4) << 3);
    uint32_t b_row_l = (uint32_t)(((lane & 16) >> 1) + (lane & 7));
    uint32_t b_col_l = (uint32_t)(lane & 8);

    int lr[4], lcc[4];
#pragma unroll
    for (int q = 0; q < 4; q++) {
        int l = tid + q * 256;
        lr[q] = l >> 3;
        lcc[q] = l & 7;
    }

    int nchunks = Kslice >> 6;

    auto issue = [&](int st, int kc) {
        uint32_t sbase = sb + (uint32_t)st * STAGE_B;
#pragma unroll
        for (int q = 0; q < 4; q++) {
            int r = lr[q], c = lcc[q];
            uint32_t so = sbase + (uint32_t)(r * 144 + c * 16);
            size_t ga = (size_t)(m0 + r) * lda + koff + kc + c * 8;
            size_t gb = (size_t)(n0 + r) * ldb + koff + kc + c * 8;
            CP_ASYNC16(so + 0 * TILE_B, (const void*)(Ahi + ga));
            CP_ASYNC16(so + 1 * TILE_B, (const void*)(Alo + ga));
            CP_ASYNC16(so + 2 * TILE_B, (const void*)(Bhi + gb));
            CP_ASYNC16(so + 3 * TILE_B, (const void*)(Blo + gb));
        }
    };

    // prologue: issue up to 2 chunks ahead
    issue(0, 0);
    CP_COMMIT();
    if (nchunks > 1) {
        issue(1, 64);
        CP_COMMIT();
    }

    for (int ch = 0; ch < nchunks; ch++) {
        if (ch + 2 < nchunks) {
            issue((ch + 2) % TCG_STAGES, (ch + 2) << 6);
            CP_COMMIT();
            CP_WAIT(2);
        } else if (ch + 1 < nchunks) {
            CP_WAIT(1);
        } else {
            CP_WAIT(0);
        }
        __syncthreads();

        uint32_t sA = sb + (uint32_t)(ch % TCG_STAGES) * STAGE_B;
        uint32_t sB = sA + 2 * TILE_B;
#pragma unroll
        for (int ks = 0; ks < 4; ks++) {
            uint32_t ah[2][4], al[2][4];
#pragma unroll
            for (int mt = 0; mt < 2; mt++) {
                uint32_t ad = sA + (uint32_t)(warp_m * 32 + mt * 16 + a_row_l) * 144
                            + (uint32_t)(ks * 16 + a_col_l) * 2;
                LDSM_X4(ah[mt][0], ah[mt][1], ah[mt][2], ah[mt][3], ad);
                LDSM_X4(al[mt][0], al[mt][1], al[mt][2], al[mt][3], ad + TILE_B);
            }
            uint32_t bh[8][2], bl[8][2];
#pragma unroll
            for (int p = 0; p < 4; p++) {
                uint32_t bd = sB + (uint32_t)(warp_n * 64 + p * 16 + b_row_l) * 144
                            + (uint32_t)(ks * 16 + b_col_l) * 2;
                uint32_t q0, q1, q2, q3;
                LDSM_X4(q0, q1, q2, q3, bd);
                bh[2 * p][0] = q0; bh[2 * p][1] = q1;
                bh[2 * p + 1][0] = q2; bh[2 * p + 1][1] = q3;
                LDSM_X4(q0, q1, q2, q3, bd + TILE_B);
                bl[2 * p][0] = q0; bl[2 * p][1] = q1;
                bl[2 * p + 1][0] = q2; bl[2 * p + 1][1] = q3;
            }
#pragma unroll
            for (int mt = 0; mt < 2; mt++)
#pragma unroll
                for (int nt = 0; nt < 8; nt++)
                    MMA_BF16(acc[mt][nt], ah[mt], bh[nt]);
#pragma unroll
            for (int mt = 0; mt < 2; mt++)
#pragma unroll
                for (int nt = 0; nt < 8; nt++)
                    MMA_BF16(acc[mt][nt], ah[mt], bl[nt]);
#pragma unroll
            for (int mt = 0; mt < 2; mt++)
#pragma unroll
                for (int nt = 0; nt < 8; nt++)
                    MMA_BF16(acc[mt][nt], al[mt], bh[nt]);
        }
        __syncthreads();
    }

    int tr = lane >> 2;
    int tc = (lane & 3) * 2;
#pragma unroll
    for (int mt = 0; mt < 2; mt++) {
        int row = m0 + warp_m * 32 + mt * 16 + tr;
#pragma unroll
        for (int nt = 0; nt < 8; nt++) {
            int col = n0 + warp_n * 64 + nt * 8 + tc;
            *(float2*)&C[(size_t)row * ldc + col] =
                make_float2(acc[mt][nt][0], acc[mt][nt][1]);
            *(float2*)&C[(size_t)(row + 8) * ldc + col] =
                make_float2(acc[mt][nt][2], acc[mt][nt][3]);
        }
    }
}

// ---------------- launch -----------------------------------------------------
extern "C" void kernel_launch(void* const* d_in, const int* in_sizes, int n_in,
                              void* d_out, int out_size) {
    const int* idx = (const int*)d_in[0];
    const float* wte = (const float*)d_in[1];
    const float* encoder = (const float*)d_in[2];
    const float* dec_x = (const float*)d_in[3];
    const float* dec_y = (const float*)d_in[4];
    const float* readout = (const float*)d_in[5];
    float* out = (float*)d_out;

    float *pv, *pH, *pup;
    __nv_bfloat16 *pvhi, *pvlo, *pRhi, *pRlo, *palnhi, *palnlo;
    __nv_bfloat16 *pwxhi, *pwxlo, *pwyhi, *pwylo, *penchi, *penclo, *prdhi, *prdlo;
    __nv_bfloat16 *pYhi, *pYlo, *pRThi, *pRTlo, *pVThi, *pVTlo, *pMhi, *pMlo;
    cudaGetSymbolAddress((void**)&pv, g_v);
    cudaGetSymbolAddress((void**)&pH, g_H);
    cudaGetSymbolAddress((void**)&pup, g_upart);
    cudaGetSymbolAddress((void**)&pvhi, g_vhi);
    cudaGetSymbolAddress((void**)&pvlo, g_vlo);
    cudaGetSymbolAddress((void**)&pRhi, g_Rhi);
    cudaGetSymbolAddress((void**)&pRlo, g_Rlo);
    cudaGetSymbolAddress((void**)&palnhi, g_alnhi);
    cudaGetSymbolAddress((void**)&palnlo, g_alnlo);
    cudaGetSymbolAddress((void**)&pwxhi, g_wxhi);
    cudaGetSymbolAddress((void**)&pwxlo, g_wxlo);
    cudaGetSymbolAddress((void**)&pwyhi, g_wyhi);
    cudaGetSymbolAddress((void**)&pwylo, g_wylo);
    cudaGetSymbolAddress((void**)&penchi, g_enchi);
    cudaGetSymbolAddress((void**)&penclo, g_enclo);
    cudaGetSymbolAddress((void**)&prdhi, g_rdhi);
    cudaGetSymbolAddress((void**)&prdlo, g_rdlo);
    cudaGetSymbolAddress((void**)&pYhi, g_Yhi);
    cudaGetSymbolAddress((void**)&pYlo, g_Ylo);
    cudaGetSymbolAddress((void**)&pRThi, g_RThi);
    cudaGetSymbolAddress((void**)&pRTlo, g_RTlo);
    cudaGetSymbolAddress((void**)&pVThi, g_VThi);
    cudaGetSymbolAddress((void**)&pVTlo, g_VTlo);
    cudaGetSymbolAddress((void**)&pMhi, g_Mhi);
    cudaGetSymbolAddress((void**)&pMlo, g_Mlo);

    cudaFuncSetAttribute(tc_gemm,
                         cudaFuncAttributeMaxDynamicSharedMemorySize, TCG_SMEM);
    cudaFuncSetAttribute(xy_gemm,
                         cudaFuncAttributeMaxDynamicSharedMemorySize, XY_SMEM);
    cudaFuncSetAttribute(kv_outer_kernel,
                         cudaFuncAttributeMaxDynamicSharedMemorySize, KVO_SMEM);
    cudaFuncSetAttribute(attn_out_kernel,
                         cudaFuncAttributeMaxDynamicSharedMemorySize, AO_SMEM);

    embed_ln_rope_kernel<<<BT, 256>>>(idx, wte, pv, pvhi, pvlo, pRhi, pRlo);
    conv_all_kernel<<<24832, 256>>>(dec_x, dec_y, encoder, readout,
                                    pwxhi, pwxlo, pwyhi, pwylo,
                                    penchi, penclo, prdhi, prdlo);

    for (int layer = 0; layer < LL; layer++) {
        split_T_both_kernel<<<dim3(TT / 32, DD / 32, 2 * BB), 256>>>(
            pRhi, pRlo, pvhi, pvlo, pRThi, pRTlo, pVThi, pVTlo);
        kv_outer_kernel<<<dim3(32, BB, 2), 512, KVO_SMEM>>>(pVThi, pVTlo,
                                                            pRThi, pRTlo, pH);
        prefix_split_kernel<<<dim3(256, BB), 256>>>(pH, pMhi, pMlo);
        attn_out_kernel<<<dim3(32, BB), 256, AO_SMEM>>>(pRhi, pRlo, pVThi, pVTlo,
                                                        pMhi, pMlo, palnhi, palnlo);
        xy_gemm<<<dim3(BT / 128, NN / 128), 256, XY_SMEM>>>(
            pvhi, pvlo, palnhi, palnlo, pwxhi, pwxlo, pwyhi, pwylo, pYhi, pYlo);
        tc_gemm<<<dim3(DD / 128, BT / 128, SPLITK), 256, TCG_SMEM>>>(
            pYhi, pYlo, penchi, penclo, NN / SPLITK, NN, NN, pup, DD,
            (size_t)BT * DD);
        ln_add_rope_kernel<<<BT, 256>>>(pup, pv, pvhi, pvlo, pRhi, pRlo);
    }

    tc_gemm<<<dim3(VOCAB / 128, BT / 128, 1), 256, TCG_SMEM>>>(
        pvhi, pvlo, prdhi, prdlo, DD, DD, DD, out, VOCAB, 0);
}

// round 14
// speedup vs baseline: 1.1288x; 1.1288x over previous
#include <cuda_runtime.h>
#include <cuda_bf16.h>
#include <cuda_fp16.h>
#include <math.h>
#include <stdint.h>

// Problem constants
#define BB 4
#define TT 2048
#define BT 8192      // B*T
#define DD 256
#define NN 8192
#define HH 4
#define MM 2048      // N/H
#define LL 6
#define VOCAB 256
#define EPS 1e-5f
#define SPLITK 8

// single dynamic-smem declaration shared by all kernels
extern __shared__ char dynsm[];

// ---------------- scratch buffers (device globals, no allocations) --------
__device__ float g_v[BT * DD];
__device__ float g_upart[SPLITK * BT * DD];                   // split-K partials
__device__ __nv_bfloat16 g_vhi[BT * DD], g_vlo[BT * DD];
__device__ __nv_bfloat16 g_Rhi[BT * DD], g_Rlo[BT * DD];
__device__ __nv_bfloat16 g_alnhi[BT * DD], g_alnlo[BT * DD];
__device__ __nv_bfloat16 g_wxhi[NN * DD], g_wxlo[NN * DD];
__device__ __nv_bfloat16 g_wyhi[NN * DD], g_wylo[NN * DD];
__device__ __half g_ench[DD * NN], g_encl[DD * NN];           // fp16 enc hi/lo
__device__ __nv_bfloat16 g_rdhi[VOCAB * DD], g_rdlo[VOCAB * DD];
__device__ __half g_Yf[(size_t)BT * NN];                      // 128 MB, fp16 Y
// linear-attention scratch
__device__ __nv_bfloat16 g_RThi[BB * DD * TT], g_RTlo[BB * DD * TT];
__device__ __nv_bfloat16 g_VThi[BB * DD * TT], g_VTlo[BB * DD * TT];
__device__ float g_H[(size_t)BB * 32 * DD * DD];
__device__ __nv_bfloat16 g_Mhi[(size_t)BB * 32 * DD * DD];
__device__ __nv_bfloat16 g_Mlo[(size_t)BB * 32 * DD * DD];

// ---------------- PTX helpers ----------------------------------------------
__device__ __forceinline__ uint32_t smem_u32(const void* p) {
    uint32_t a;
    asm("{ .reg .u64 t; cvta.to.shared.u64 t, %1; cvt.u32.u64 %0, t; }"
        : "=r"(a) : "l"(p));
    return a;
}

#define LDSM_X4(r0, r1, r2, r3, addr) \
    asm volatile("ldmatrix.sync.aligned.m8n8.x4.shared.b16 {%0,%1,%2,%3}, [%4];" \
        : "=r"(r0), "=r"(r1), "=r"(r2), "=r"(r3) : "r"(addr))

#define MMA_BF16(d, a, b) \
    asm volatile( \
        "mma.sync.aligned.m16n8k16.row.col.f32.bf16.bf16.f32 " \
        "{%0,%1,%2,%3}, {%4,%5,%6,%7}, {%8,%9}, {%0,%1,%2,%3};" \
        : "+f"((d)[0]), "+f"((d)[1]), "+f"((d)[2]), "+f"((d)[3]) \
        : "r"((a)[0]), "r"((a)[1]), "r"((a)[2]), "r"((a)[3]), \
          "r"((b)[0]), "r"((b)[1]))

#define MMA_F16(d, a, b) \
    asm volatile( \
        "mma.sync.aligned.m16n8k16.row.col.f32.f16.f16.f32 " \
        "{%0,%1,%2,%3}, {%4,%5,%6,%7}, {%8,%9}, {%0,%1,%2,%3};" \
        : "+f"((d)[0]), "+f"((d)[1]), "+f"((d)[2]), "+f"((d)[3]) \
        : "r"((a)[0]), "r"((a)[1]), "r"((a)[2]), "r"((a)[3]), \
          "r"((b)[0]), "r"((b)[1]))

#define CP_ASYNC16(dst, src) \
    asm volatile("cp.async.cg.shared.global [%0], [%1], 16;" \
        :: "r"(dst), "l"(src) : "memory")
#define CP_COMMIT() asm volatile("cp.async.commit_group;" ::: "memory")
#define CP_WAIT(N)  asm volatile("cp.async.wait_group %0;" :: "n"(N) : "memory")

// ---------------- misc helpers ----------------------------------------------
__device__ __forceinline__ float warp_sum(float v) {
#pragma unroll
    for (int o = 16; o > 0; o >>= 1) v += __shfl_xor_sync(0xffffffffu, v, o);
    return v;
}
__device__ __forceinline__ void split2(float x, __nv_bfloat16& h, __nv_bfloat16& l) {
    __nv_bfloat16 hh = __float2bfloat16(x);
    h = hh;
    l = __float2bfloat16(x - __bfloat162float(hh));
}
__device__ __forceinline__ float rope_val(const float* rowbuf, int d, int t) {
    float x = rowbuf[d];
    float xr = (d < 128) ? -rowbuf[d + 128] : rowbuf[d - 128];
    int j = d & 127;
    float inv = expf(-(float)j * (2.f / 256.f) * 9.210340371976184f);
    float ang = (float)t * inv;
    const float TWO_PI_HI = 6.28318548202514648f;
    const float TWO_PI_LO = -1.74845553e-7f;
    float k = rintf(ang * 0.15915494309189535f);
    float r = fmaf(-k, TWO_PI_HI, ang);
    r = fmaf(-k, TWO_PI_LO, r);
    float sn = sinf(r), cs = cosf(r);
    return x * cs + xr * sn;
}

// ---------------- all weight conversions in one kernel ----------------------
__global__ void conv_all_kernel(const float* __restrict__ dec_x,
                                const float* __restrict__ dec_y,
                                const float* __restrict__ enc,
                                const float* __restrict__ rd,
                                __nv_bfloat16* __restrict__ wxhi, __nv_bfloat16* __restrict__ wxlo,
                                __nv_bfloat16* __restrict__ wyhi, __nv_bfloat16* __restrict__ wylo,
                                __half* __restrict__ ench, __half* __restrict__ encl,
                                __nv_bfloat16* __restrict__ rdhi, __nv_bfloat16* __restrict__ rdlo) {
    int bid = blockIdx.x;
    if (bid < 8192) {
        size_t i = (size_t)bid * 256 + threadIdx.x;
        int d = (int)(i & 255);
        size_t n = i >> 8;
        int h = (int)(n >> 11), m = (int)(n & 2047);
        split2(dec_x[((size_t)h * DD + d) * MM + m], wxhi[i], wxlo[i]);
    } else if (bid < 16384) {
        size_t i = (size_t)(bid - 8192) * 256 + threadIdx.x;
        int d = (int)(i & 255);
        size_t n = i >> 8;
        int h = (int)(n >> 11), m = (int)(n & 2047);
        split2(dec_y[((size_t)h * DD + d) * MM + m], wyhi[i], wylo[i]);
    } else if (bid < 24576) {
        size_t i = (size_t)(bid - 16384) * 256 + threadIdx.x;
        int n = (int)(i & 8191);
        int d = (int)(i >> 13);
        float x = enc[(size_t)n * DD + d];
        __half hh = __float2half(x);
        ench[i] = hh;
        encl[i] = __float2half(x - __half2float(hh));
    } else {
        size_t i = (size_t)(bid - 24576) * 256 + threadIdx.x;
        int d = (int)(i & 255);
        int v = (int)(i >> 8);
        split2(rd[(size_t)d * VOCAB + v], rdhi[i], rdlo[i]);
    }
}

// ---------------- embed + LN + RoPE ------------------------------------------
__global__ void embed_ln_rope_kernel(const int* __restrict__ idx,
                                     const float* __restrict__ wte,
                                     float* __restrict__ out,
                                     __nv_bfloat16* __restrict__ ohi,
                                     __nv_bfloat16* __restrict__ olo,
                                     __nv_bfloat16* __restrict__ Rhi,
                                     __nv_bfloat16* __restrict__ Rlo) {
    __shared__ float sh[8];
    __shared__ float rowbuf[256];
    int row = blockIdx.x;
    int d = threadIdx.x;
    float x = wte[idx[row] * DD + d];
    int wid = d >> 5, lane = d & 31;
    float s = warp_sum(x);
    if (lane == 0) sh[wid] = s;
    __syncthreads();
    float tot = 0.f;
#pragma unroll
    for (int i = 0; i < 8; i++) tot += sh[i];
    float mu = tot * (1.f / 256.f);
    __syncthreads();
    float dx = x - mu;
    s = warp_sum(dx * dx);
    if (lane == 0) sh[wid] = s;
    __syncthreads();
    tot = 0.f;
#pragma unroll
    for (int i = 0; i < 8; i++) tot += sh[i];
    float r = dx * rsqrtf(tot * (1.f / 256.f) + EPS);
    out[row * DD + d] = r;
    split2(r, ohi[row * DD + d], olo[row * DD + d]);
    rowbuf[d] = r;
    __syncthreads();
    float val = rope_val(rowbuf, d, row & (TT - 1));
    split2(val, Rhi[row * DD + d], Rlo[row * DD + d]);
}

// ---------------- LN + residual add (sums SPLITK partials) + RoPE -----------
__global__ void ln_add_rope_kernel(const float* __restrict__ up,
                                   float* __restrict__ v,
                                   __nv_bfloat16* __restrict__ vhi,
                                   __nv_bfloat16* __restrict__ vlo,
                                   __nv_bfloat16* __restrict__ Rhi,
                                   __nv_bfloat16* __restrict__ Rlo) {
    __shared__ float sh[8];
    __shared__ float rowbuf[256];
    int row = blockIdx.x;
    int d = threadIdx.x;
    int o = row * DD + d;
    float x = 0.f;
#pragma unroll
    for (int p = 0; p < SPLITK; p++) x += up[(size_t)p * BT * DD + o];
    int wid = d >> 5, lane = d & 31;
    float s = warp_sum(x);
    if (lane == 0) sh[wid] = s;
    __syncthreads();
    float tot = 0.f;
#pragma unroll
    for (int i = 0; i < 8; i++) tot += sh[i];
    float mu = tot * (1.f / 256.f);
    __syncthreads();
    float dx = x - mu;
    s = warp_sum(dx * dx);
    if (lane == 0) sh[wid] = s;
    __syncthreads();
    tot = 0.f;
#pragma unroll
    for (int i = 0; i < 8; i++) tot += sh[i];
    float nv = v[o] + dx * rsqrtf(tot * (1.f / 256.f) + EPS);
    v[o] = nv;
    split2(nv, vhi[o], vlo[o]);
    rowbuf[d] = nv;
    __syncthreads();
    float val = rope_val(rowbuf, d, row & (TT - 1));
    split2(val, Rhi[o], Rlo[o]);
}

// ---------------- transpose (pure bf16 permute) for R and v hi/lo -----------
__global__ void split_T_both_kernel(const __nv_bfloat16* __restrict__ Rhi,
                                    const __nv_bfloat16* __restrict__ Rlo,
                                    const __nv_bfloat16* __restrict__ vhi,
                                    const __nv_bfloat16* __restrict__ vlo,
                                    __nv_bfloat16* __restrict__ RThi,
                                    __nv_bfloat16* __restrict__ RTlo,
                                    __nv_bfloat16* __restrict__ VThi,
                                    __nv_bfloat16* __restrict__ VTlo) {
    __shared__ __nv_bfloat16 th[32][34];
    __shared__ __nv_bfloat16 tl[32][34];
    int zb = blockIdx.z;
    int b = zb & 3;
    const __nv_bfloat16* hi_in = (zb < 4) ? Rhi : vhi;
    const __nv_bfloat16* lo_in = (zb < 4) ? Rlo : vlo;
    __nv_bfloat16* hi_out = (zb < 4) ? RThi : VThi;
    __nv_bfloat16* lo_out = (zb < 4) ? RTlo : VTlo;
    int t0 = blockIdx.x * 32;
    int d0 = blockIdx.y * 32;
    int tx = threadIdx.x & 31, ty = threadIdx.x >> 5;
#pragma unroll
    for (int i = 0; i < 4; i++) {
        int t = ty + i * 8;
        size_t g = ((size_t)(b * TT + t0 + t)) * DD + d0 + tx;
        th[t][tx] = hi_in[g];
        tl[t][tx] = lo_in[g];
    }
    __syncthreads();
#pragma unroll
    for (int i = 0; i < 4; i++) {
        int d = ty + i * 8;
        size_t o = ((size_t)(b * DD + d0 + d)) * TT + t0 + tx;
        hi_out[o] = th[tx][d];
        lo_out[o] = tl[tx][d];
    }
}

// ---------------- kv_outer: H[b][i] = V_i^T K_i (256x256, k=64) -------------
#define KVO_SMEM 110592
__global__ void __launch_bounds__(512, 1)
kv_outer_kernel(const __nv_bfloat16* __restrict__ VThi,
                const __nv_bfloat16* __restrict__ VTlo,
                const __nv_bfloat16* __restrict__ RThi,
                const __nv_bfloat16* __restrict__ RTlo,
                float* __restrict__ H) {
    char* smc = dynsm;
    uint32_t sb = smem_u32(smc);
    int i = blockIdx.x, b = blockIdx.y, e0 = blockIdx.z * 128;
    int s0 = i * 64;
    int tid = threadIdx.x;
    int wid = tid >> 5, lane = tid & 31;
    int wm = wid & 3, wn = wid >> 2;

    for (int l = tid; l < 1024; l += 512) {
        int r = l >> 3, c = l & 7;
        size_t g = ((size_t)(b * DD + e0 + r)) * TT + s0 + c * 8;
        uint32_t so = (uint32_t)(r * 144 + c * 16);
        *(uint4*)(smc + so) = *(const uint4*)(VThi + g);
        *(uint4*)(smc + 18432 + so) = *(const uint4*)(VTlo + g);
    }
    for (int l = tid; l < 2048; l += 512) {
        int r = l >> 3, c = l & 7;
        size_t g = ((size_t)(b * DD + r)) * TT + s0 + c * 8;
        uint32_t so = (uint32_t)(36864 + r * 144 + c * 16);
        *(uint4*)(smc + so) = *(const uint4*)(RThi + g);
        *(uint4*)(smc + 36864 + so) = *(const uint4*)(RTlo + g);
    }
    __syncthreads();

    uint32_t a_row_l = (uint32_t)(lane & 15);
    uint32_t a_col_l = (uint32_t)((lane >> 4) << 3);
    uint32_t b_row_l = (uint32_t)(((lane & 16) >> 1) + (lane & 7));
    uint32_t b_col_l = (uint32_t)(lane & 8);

    float acc[2][8][4] = {};
#pragma unroll
    for (int ks = 0; ks < 4; ks++) {
        uint32_t ah[2][4], al[2][4];
#pragma unroll
        for (int mi = 0; mi < 2; mi++) {
            uint32_t ad = sb + (uint32_t)(wm * 32 + mi * 16 + a_row_l) * 144
                        + (uint32_t)(ks * 16 + a_col_l) * 2;
            LDSM_X4(ah[mi][0], ah[mi][1], ah[mi][2], ah[mi][3], ad);
            LDSM_X4(al[mi][0], al[mi][1], al[mi][2], al[mi][3], ad + 18432);
        }
        uint32_t bh[8][2], bl[8][2];
#pragma unroll
        for (int p = 0; p < 4; p++) {
            uint32_t bd = sb + 36864 + (uint32_t)(wn * 64 + p * 16 + b_row_l) * 144
                        + (uint32_t)(ks * 16 + b_col_l) * 2;
            uint32_t q0, q1, q2, q3;
            LDSM_X4(q0, q1, q2, q3, bd);
            bh[2 * p][0] = q0; bh[2 * p][1] = q1;
            bh[2 * p + 1][0] = q2; bh[2 * p + 1][1] = q3;
            LDSM_X4(q0, q1, q2, q3, bd + 36864);
            bl[2 * p][0] = q0; bl[2 * p][1] = q1;
            bl[2 * p + 1][0] = q2; bl[2 * p + 1][1] = q3;
        }
#pragma unroll
        for (int mi = 0; mi < 2; mi++)
#pragma unroll
            for (int nt = 0; nt < 8; nt++)
                MMA_BF16(acc[mi][nt], ah[mi], bh[nt]);
#pragma unroll
        for (int mi = 0; mi < 2; mi++)
#pragma unroll
            for (int nt = 0; nt < 8; nt++)
                MMA_BF16(acc[mi][nt], ah[mi], bl[nt]);
#pragma unroll
        for (int mi = 0; mi < 2; mi++)
#pragma unroll
            for (int nt = 0; nt < 8; nt++)
                MMA_BF16(acc[mi][nt], al[mi], bh[nt]);
    }

    int tr = lane >> 2, tc = (lane & 3) * 2;
    size_t base = ((size_t)(b * 32 + i)) * 65536;
#pragma unroll
    for (int mi = 0; mi < 2; mi++) {
        int e = e0 + wm * 32 + mi * 16 + tr;
#pragma unroll
        for (int nt = 0; nt < 8; nt++) {
            int d = wn * 64 + nt * 8 + tc;
            *(float2*)&H[base + (size_t)e * 256 + d] =
                make_float2(acc[mi][nt][0], acc[mi][nt][1]);
            *(float2*)&H[base + (size_t)(e + 8) * 256 + d] =
                make_float2(acc[mi][nt][2], acc[mi][nt][3]);
        }
    }
}

// ---------------- exclusive prefix over chunks + bf16 split -----------------
__global__ void prefix_split_kernel(const float* __restrict__ H,
                                    __nv_bfloat16* __restrict__ Mhi,
                                    __nv_bfloat16* __restrict__ Mlo) {
    int b = blockIdx.y;
    int j = blockIdx.x * 256 + threadIdx.x;
    size_t base = (size_t)b * 32 * 65536 + j;
    float acc = 0.f;
#pragma unroll 4
    for (int i = 0; i < 32; i++) {
        size_t off = base + (size_t)i * 65536;
        __nv_bfloat16 h, l;
        split2(acc, h, l);
        Mhi[off] = h;
        Mlo[off] = l;
        acc += H[off];
    }
}

// ---------------- attn_out + fused row-LN ------------------------------------
#define AO_Q    0
#define AO_QLO  33792
#define AO_B    67584
#define AO_BLO  104448
#define AO_S    141312
#define AO_SLO  150528
#define AO_OBUF 67584
#define AO_SMEM 159744
__global__ void __launch_bounds__(256, 1)
attn_out_kernel(const __nv_bfloat16* __restrict__ Rhi,
                const __nv_bfloat16* __restrict__ Rlo,
                const __nv_bfloat16* __restrict__ VThi,
                const __nv_bfloat16* __restrict__ VTlo,
                const __nv_bfloat16* __restrict__ Mhi,
                const __nv_bfloat16* __restrict__ Mlo,
                __nv_bfloat16* __restrict__ alnhi,
                __nv_bfloat16* __restrict__ alnlo) {
    char* smc = dynsm;
    uint32_t sb = smem_u32(smc);
    int i = blockIdx.x, b = blockIdx.y;
    int q0 = i * 64;
    int tid = threadIdx.x;
    int wid = tid >> 5, lane = tid & 31;

    for (int l = tid; l < 2048; l += 256) {
        int r = l >> 5, c = l & 31;
        size_t g = ((size_t)(b * TT + q0 + r)) * DD + c * 8;
        uint32_t so = (uint32_t)(r * 528 + c * 16);
        *(uint4*)(smc + AO_Q + so) = *(const uint4*)(Rhi + g);
        *(uint4*)(smc + AO_QLO + so) = *(const uint4*)(Rlo + g);
    }
    for (int l = tid; l < 2048; l += 256) {
        int r = l >> 3, c = l & 7;
        size_t g = ((size_t)(b * DD + r)) * TT + q0 + c * 8;
        uint32_t so = (uint32_t)(r * 144 + c * 16);
        *(uint4*)(smc + AO_B + so) = *(const uint4*)(VThi + g);
        *(uint4*)(smc + AO_BLO + so) = *(const uint4*)(VTlo + g);
    }
    __syncthreads();

    uint32_t a_row_l = (uint32_t)(lane & 15);
    uint32_t a_col_l = (uint32_t)((lane >> 4) << 3);
    uint32_t b_row_l = (uint32_t)(((lane & 16) >> 1) + (lane & 7));
    uint32_t b_col_l = (uint32_t)(lane & 8);
    int tr = lane >> 2, tc = (lane & 3) * 2;

    int wt = wid & 1, ws = wid >> 1;
    {
        float sacc[2][2][4] = {};
#pragma unroll
        for (int ks = 0; ks < 16; ks++) {
            uint32_t ah[2][4], al[2][4];
#pragma unroll
            for (int mi = 0; mi < 2; mi++) {
                uint32_t ad = sb + AO_Q + (uint32_t)(wt * 32 + mi * 16 + a_row_l) * 528
                            + (uint32_t)(ks * 16 + a_col_l) * 2;
                LDSM_X4(ah[mi][0], ah[mi][1], ah[mi][2], ah[mi][3], ad);
                LDSM_X4(al[mi][0], al[mi][1], al[mi][2], al[mi][3], ad + 33792);
            }
            uint32_t bh[2][2], bl[2][2];
            {
                uint32_t bd = sb + AO_Q + (uint32_t)(ws * 16 + b_row_l) * 528
                            + (uint32_t)(ks * 16 + b_col_l) * 2;
                uint32_t p0, p1, p2, p3;
                LDSM_X4(p0, p1, p2, p3, bd);
                bh[0][0] = p0; bh[0][1] = p1; bh[1][0] = p2; bh[1][1] = p3;
                LDSM_X4(p0, p1, p2, p3, bd + 33792);
                bl[0][0] = p0; bl[0][1] = p1; bl[1][0] = p2; bl[1][1] = p3;
            }
#pragma unroll
            for (int mi = 0; mi < 2; mi++)
#pragma unroll
                for (int ni = 0; ni < 2; ni++) {
                    MMA_BF16(sacc[mi][ni], ah[mi], bh[ni]);
                    MMA_BF16(sacc[mi][ni], ah[mi], bl[ni]);
                    MMA_BF16(sacc[mi][ni], al[mi], bh[ni]);
                }
        }
#pragma unroll
        for (int mi = 0; mi < 2; mi++)
#pragma unroll
            for (int ni = 0; ni < 2; ni++) {
                int t0l = wt * 32 + mi * 16 + tr;
                int sl = ws * 16 + ni * 8 + tc;
                float s0v = (sl > t0l) ? 0.f : sacc[mi][ni][0];
                float s1v = (sl + 1 > t0l) ? 0.f : sacc[mi][ni][1];
                float s2v = (sl > t0l + 8) ? 0.f : sacc[mi][ni][2];
                float s3v = (sl + 1 > t0l + 8) ? 0.f : sacc[mi][ni][3];
                __nv_bfloat16 h0, l0, h1, l1;
                split2(s0v, h0, l0); split2(s1v, h1, l1);
                *(__nv_bfloat162*)(smc + AO_S + t0l * 144 + sl * 2) = __halves2bfloat162(h0, h1);
                *(__nv_bfloat162*)(smc + AO_SLO + t0l * 144 + sl * 2) = __halves2bfloat162(l0, l1);
                split2(s2v, h0, l0); split2(s3v, h1, l1);
                *(__nv_bfloat162*)(smc + AO_S + (t0l + 8) * 144 + sl * 2) = __halves2bfloat162(h0, h1);
                *(__nv_bfloat162*)(smc + AO_SLO + (t0l + 8) * 144 + sl * 2) = __halves2bfloat162(l0, l1);
            }
    }
    __syncthreads();

    int we = wid >> 1;
    float oacc[2][8][4] = {};
#pragma unroll
    for (int ks = 0; ks < 4; ks++) {
        uint32_t ah[2][4], al[2][4];
#pragma unroll
        for (int mi = 0; mi < 2; mi++) {
            uint32_t ad = sb + AO_S + (uint32_t)(wt * 32 + mi * 16 + a_row_l) * 144
                        + (uint32_t)(ks * 16 + a_col_l) * 2;
            LDSM_X4(ah[mi][0], ah[mi][1], ah[mi][2], ah[mi][3], ad);
            LDSM_X4(al[mi][0], al[mi][1], al[mi][2], al[mi][3], ad + 9216);
        }
        uint32_t bh[8][2], bl[8][2];
#pragma unroll
        for (int p = 0; p < 4; p++) {
            uint32_t bd = sb + AO_B + (uint32_t)(we * 64 + p * 16 + b_row_l) * 144
                        + (uint32_t)(ks * 16 + b_col_l) * 2;
            uint32_t p0, p1, p2, p3;
            LDSM_X4(p0, p1, p2, p3, bd);
            bh[2 * p][0] = p0; bh[2 * p][1] = p1;
            bh[2 * p + 1][0] = p2; bh[2 * p + 1][1] = p3;
            LDSM_X4(p0, p1, p2, p3, bd + 36864);
            bl[2 * p][0] = p0; bl[2 * p][1] = p1;
            bl[2 * p + 1][0] = p2; bl[2 * p + 1][1] = p3;
        }
#pragma unroll
        for (int mi = 0; mi < 2; mi++)
#pragma unroll
            for (int nt = 0; nt < 8; nt++) {
                MMA_BF16(oacc[mi][nt], ah[mi], bh[nt]);
                MMA_BF16(oacc[mi][nt], ah[mi], bl[nt]);
                MMA_BF16(oacc[mi][nt], al[mi], bh[nt]);
            }
    }
    __syncthreads();

    size_t mbase = ((size_t)(b * 32 + i)) * 65536;
    for (int dc = 0; dc < 4; dc++) {
        for (int l = tid; l < 2048; l += 256) {
            int r = l >> 3, c = l & 7;
            size_t g = mbase + (size_t)r * 256 + dc * 64 + c * 8;
            uint32_t so = (uint32_t)(r * 144 + c * 16);
            *(uint4*)(smc + AO_B + so) = *(const uint4*)(Mhi + g);
            *(uint4*)(smc + AO_BLO + so) = *(const uint4*)(Mlo + g);
        }
        __syncthreads();
#pragma unroll
        for (int ks = 0; ks < 4; ks++) {
            int ksg = dc * 4 + ks;
            uint32_t ah[2][4], al[2][4];
#pragma unroll
            for (int mi = 0; mi < 2; mi++) {
                uint32_t ad = sb + AO_Q + (uint32_t)(wt * 32 + mi * 16 + a_row_l) * 528
                            + (uint32_t)(ksg * 16 + a_col_l) * 2;
                LDSM_X4(ah[mi][0], ah[mi][1], ah[mi][2], ah[mi][3], ad);
                LDSM_X4(al[mi][0], al[mi][1], al[mi][2], al[mi][3], ad + 33792);
            }
            uint32_t bh[8][2], bl[8][2];
#pragma unroll
            for (int p = 0; p < 4; p++) {
                uint32_t bd = sb + AO_B + (uint32_t)(we * 64 + p * 16 + b_row_l) * 144
                            + (uint32_t)(ks * 16 + b_col_l) * 2;
                uint32_t p0, p1, p2, p3;
                LDSM_X4(p0, p1, p2, p3, bd);
                bh[2 * p][0] = p0; bh[2 * p][1] = p1;
                bh[2 * p + 1][0] = p2; bh[2 * p + 1][1] = p3;
                LDSM_X4(p0, p1, p2, p3, bd + 36864);
                bl[2 * p][0] = p0; bl[2 * p][1] = p1;
                bl[2 * p + 1][0] = p2; bl[2 * p + 1][1] = p3;
            }
#pragma unroll
            for (int mi = 0; mi < 2; mi++)
#pragma unroll
                for (int nt = 0; nt < 8; nt++) {
                    MMA_BF16(oacc[mi][nt], ah[mi], bh[nt]);
                    MMA_BF16(oacc[mi][nt], ah[mi], bl[nt]);
                    MMA_BF16(oacc[mi][nt], al[mi], bh[nt]);
                }
        }
        __syncthreads();
    }

    float* obuf = (float*)(smc + AO_OBUF);
#pragma unroll
    for (int mi = 0; mi < 2; mi++) {
        int rl = wt * 32 + mi * 16 + tr;
#pragma unroll
        for (int nt = 0; nt < 8; nt++) {
            int col = we * 64 + nt * 8 + tc;
            obuf[rl * 260 + col] = oacc[mi][nt][0];
            obuf[rl * 260 + col + 1] = oacc[mi][nt][1];
            obuf[(rl + 8) * 260 + col] = oacc[mi][nt][2];
            obuf[(rl + 8) * 260 + col + 1] = oacc[mi][nt][3];
        }
    }
    __syncthreads();

    for (int rr2 = 0; rr2 < 8; rr2++) {
        int r = wid * 8 + rr2;
        float vals[8];
        float s = 0.f;
#pragma unroll
        for (int k = 0; k < 8; k++) {
            vals[k] = obuf[r * 260 + lane + 32 * k];
            s += vals[k];
        }
        s = warp_sum(s);
        float mu = s * (1.f / 256.f);
        float q = 0.f;
#pragma unroll
        for (int k = 0; k < 8; k++) {
            float dxx = vals[k] - mu;
            q += dxx * dxx;
        }
        q = warp_sum(q);
        float rstd = rsqrtf(q * (1.f / 256.f) + EPS);
        size_t gbase = ((size_t)(b * TT + q0 + r)) * DD;
#pragma unroll
        for (int k = 0; k < 8; k++) {
            __nv_bfloat16 h, l;
            split2((vals[k] - mu) * rstd, h, l);
            alnhi[gbase + lane + 32 * k] = h;
            alnlo[gbase + lane + 32 * k] = l;
        }
    }
}

// ---------------- fused XY GEMM (256 threads, warp tile 32x64) ---------------
// grid: (BT/128, NN/128) — row-block fastest for L2-resident waves.
// Y = relu(v@Wx^T)*relu(aln@Wy^T) -> single fp16
#define XT 10240                // 128 rows * 80B (32 bf16 cols padded)
#define XSTG (8 * XT)           // 81920
#define XY_SMEM (2 * XSTG)      // 163840
__global__ void __launch_bounds__(256, 1)
xy_gemm(const __nv_bfloat16* __restrict__ vhi, const __nv_bfloat16* __restrict__ vlo,
        const __nv_bfloat16* __restrict__ alnhi, const __nv_bfloat16* __restrict__ alnlo,
        const __nv_bfloat16* __restrict__ wxhi, const __nv_bfloat16* __restrict__ wxlo,
        const __nv_bfloat16* __restrict__ wyhi, const __nv_bfloat16* __restrict__ wylo,
        __half* __restrict__ Yf) {
    char* smc = dynsm;
    uint32_t sb = smem_u32(smc);

    int tid = threadIdx.x;
    int wid = tid >> 5;
    int lane = tid & 31;
    int warp_m = wid & 3;
    int warp_n = wid >> 2;

    int m0 = blockIdx.x * 128;
    int n0 = blockIdx.y * 128;

    float accx[2][8][4] = {};
    float accy[2][8][4] = {};

    uint32_t a_row_l = (uint32_t)(lane & 15);
    uint32_t a_col_l = (uint32_t)((lane >> 4) << 3);
    uint32_t b_row_l = (uint32_t)(((lane & 16) >> 1) + (lane & 7));
    uint32_t b_col_l = (uint32_t)(lane & 8);

    int rr = tid >> 2;
    int cc = tid & 3;

#define XY_ISSUE(st, kc) do {                                                  \
    uint32_t sbase = sb + (uint32_t)(st) * XSTG;                               \
    _Pragma("unroll")                                                          \
    for (int q = 0; q < 16; q++) {                                             \
        int tile = q >> 1;                                                     \
        int r = ((q & 1) << 6) + rr;                                           \
        const __nv_bfloat16* mat;                                              \
        int rb;                                                                \
        switch (tile) {                                                        \
            case 0: mat = vhi;   rb = m0; break;                               \
            case 1: mat = vlo;   rb = m0; break;                               \
            case 2: mat = alnhi; rb = m0; break;                               \
            case 3: mat = alnlo; rb = m0; break;                               \
            case 4: mat = wxhi;  rb = n0; break;                               \
            case 5: mat = wxlo;  rb = n0; break;                               \
            case 6: mat = wyhi;  rb = n0; break;                               \
            default: mat = wylo; rb = n0; break;                               \
        }                                                                      \
        size_t g = (size_t)(rb + r) * DD + (kc) + cc * 8;                      \
        uint32_t dst = sbase + (uint32_t)tile * XT + (uint32_t)(r * 80 + cc * 16); \
        CP_ASYNC16(dst, (const void*)(mat + g));                               \
    }                                                                          \
} while (0)

    XY_ISSUE(0, 0);
    CP_COMMIT();

    for (int ch = 0; ch < 8; ch++) {
        if (ch + 1 < 8) {
            XY_ISSUE((ch + 1) & 1, (ch + 1) << 5);
            CP_COMMIT();
            CP_WAIT(1);
        } else {
            CP_WAIT(0);
        }
        __syncthreads();

        uint32_t S = sb + (uint32_t)(ch & 1) * XSTG;
#pragma unroll
        for (int ks = 0; ks < 2; ks++) {
            uint32_t arow_off = (uint32_t)(warp_m * 32 + a_row_l) * 80
                              + (uint32_t)(ks * 16 + a_col_l) * 2;
            uint32_t brow_off = (uint32_t)(warp_n * 64 + b_row_l) * 80
                              + (uint32_t)(ks * 16 + b_col_l) * 2;
            uint32_t ah[2][4], al[2][4], bh[8][2], bl[8][2];
            // ---- X: A = v, B = wx ----
#pragma unroll
            for (int mt = 0; mt < 2; mt++) {
                uint32_t ad = S + arow_off + (uint32_t)(mt * 16 * 80);
                LDSM_X4(ah[mt][0], ah[mt][1], ah[mt][2], ah[mt][3], ad);
                LDSM_X4(al[mt][0], al[mt][1], al[mt][2], al[mt][3], ad + XT);
            }
#pragma unroll
            for (int p = 0; p < 4; p++) {
                uint32_t bd = S + 4 * XT + brow_off + (uint32_t)(p * 16 * 80);
                uint32_t q0, q1, q2, q3;
                LDSM_X4(q0, q1, q2, q3, bd);
                bh[2 * p][0] = q0; bh[2 * p][1] = q1;
                bh[2 * p + 1][0] = q2; bh[2 * p + 1][1] = q3;
                LDSM_X4(q0, q1, q2, q3, bd + XT);
                bl[2 * p][0] = q0; bl[2 * p][1] = q1;
                bl[2 * p + 1][0] = q2; bl[2 * p + 1][1] = q3;
            }
#pragma unroll
            for (int mt = 0; mt < 2; mt++)
#pragma unroll
                for (int nt = 0; nt < 8; nt++)
                    MMA_BF16(accx[mt][nt], ah[mt], bh[nt]);
#pragma unroll
            for (int mt = 0; mt < 2; mt++)
#pragma unroll
                for (int nt = 0; nt < 8; nt++)
                    MMA_BF16(accx[mt][nt], ah[mt], bl[nt]);
#pragma unroll
            for (int mt = 0; mt < 2; mt++)
#pragma unroll
                for (int nt = 0; nt < 8; nt++)
                    MMA_BF16(accx[mt][nt], al[mt], bh[nt]);
            // ---- Y: A = aln, B = wy ----
#pragma unroll
            for (int mt = 0; mt < 2; mt++) {
                uint32_t ad = S + 2 * XT + arow_off + (uint32_t)(mt * 16 * 80);
                LDSM_X4(ah[mt][0], ah[mt][1], ah[mt][2], ah[mt][3], ad);
                LDSM_X4(al[mt][0], al[mt][1], al[mt][2], al[mt][3], ad + XT);
            }
#pragma unroll
            for (int p = 0; p < 4; p++) {
                uint32_t bd = S + 6 * XT + brow_off + (uint32_t)(p * 16 * 80);
                uint32_t q0, q1, q2, q3;
                LDSM_X4(q0, q1, q2, q3, bd);
                bh[2 * p][0] = q0; bh[2 * p][1] = q1;
                bh[2 * p + 1][0] = q2; bh[2 * p + 1][1] = q3;
                LDSM_X4(q0, q1, q2, q3, bd + XT);
                bl[2 * p][0] = q0; bl[2 * p][1] = q1;
                bl[2 * p + 1][0] = q2; bl[2 * p + 1][1] = q3;
            }
#pragma unroll
            for (int mt = 0; mt < 2; mt++)
#pragma unroll
                for (int nt = 0; nt < 8; nt++)
                    MMA_BF16(accy[mt][nt], ah[mt], bh[nt]);
#pragma unroll
            for (int mt = 0; mt < 2; mt++)
#pragma unroll
                for (int nt = 0; nt < 8; nt++)
                    MMA_BF16(accy[mt][nt], ah[mt], bl[nt]);
#pragma unroll
            for (int mt = 0; mt < 2; mt++)
#pragma unroll
                for (int nt = 0; nt < 8; nt++)
                    MMA_BF16(accy[mt][nt], al[mt], bh[nt]);
        }
        __syncthreads();
    }

    int tr = lane >> 2;
    int tc = (lane & 3) * 2;
#pragma unroll
    for (int mt = 0; mt < 2; mt++) {
        int row = m0 + warp_m * 32 + mt * 16 + tr;
#pragma unroll
        for (int nt = 0; nt < 8; nt++) {
            int col = n0 + warp_n * 64 + nt * 8 + tc;
            size_t i0 = (size_t)row * NN + col;
            size_t i1 = (size_t)(row + 8) * NN + col;
            float g0 = fmaxf(accx[mt][nt][0], 0.f) * fmaxf(accy[mt][nt][0], 0.f);
            float g1 = fmaxf(accx[mt][nt][1], 0.f) * fmaxf(accy[mt][nt][1], 0.f);
            float g2 = fmaxf(accx[mt][nt][2], 0.f) * fmaxf(accy[mt][nt][2], 0.f);
            float g3 = fmaxf(accx[mt][nt][3], 0.f) * fmaxf(accy[mt][nt][3], 0.f);
            *(__half2*)(Yf + i0) = __floats2half2_rn(g0, g1);
            *(__half2*)(Yf + i1) = __floats2half2_rn(g2, g3);
        }
    }
}

// ---------------- HMMA GEMM bf16 3-term (readout) ----------------------------
#define TILE_B 18432
#define STAGE_B (4 * TILE_B)
#define TCG_SMEM (2 * STAGE_B)
__global__ void __launch_bounds__(256, 1)
tc_gemm(const __nv_bfloat16* __restrict__ Ahi, const __nv_bfloat16* __restrict__ Alo,
        const __nv_bfloat16* __restrict__ Bhi, const __nv_bfloat16* __restrict__ Blo,
        int Kslice, int lda, int ldb,
        float* __restrict__ C, int ldc, size_t cstride) {
    char* smc = dynsm;
    uint32_t sb = smem_u32(smc);

    int tid = threadIdx.x;
    int wid = tid >> 5;
    int lane = tid & 31;
    int warp_m = wid & 3;
    int warp_n = wid >> 2;

    int m0 = blockIdx.y * 128;
    int n0 = blockIdx.x * 128;
    int koff = blockIdx.z * Kslice;
    C += (size_t)blockIdx.z * cstride;

    float acc[2][8][4] = {};

    uint32_t a_row_l = (uint32_t)(lane & 15);
    uint32_t a_col_l = (uint32_t)((lane >> 4) << 3);
    uint32_t b_row_l = (uint32_t)(((lane & 16) >> 1) + (lane & 7));
    uint32_t b_col_l = (uint32_t)(lane & 8);

    int lr[4], lcc[4];
#pragma unroll
    for (int q = 0; q < 4; q++) {
        int l = tid + q * 256;
        lr[q] = l >> 3;
        lcc[q] = l & 7;
    }

    int nchunks = Kslice >> 6;

    auto issue = [&](int st, int kc) {
        uint32_t sbase = sb + (uint32_t)st * STAGE_B;
#pragma unroll
        for (int q = 0; q < 4; q++) {
            int r = lr[q], c = lcc[q];
            uint32_t so = sbase + (uint32_t)(r * 144 + c * 16);
            size_t ga = (size_t)(m0 + r) * lda + koff + kc + c * 8;
            size_t gb = (size_t)(n0 + r) * ldb + koff + kc + c * 8;
            CP_ASYNC16(so + 0 * TILE_B, (const void*)(Ahi + ga));
            CP_ASYNC16(so + 1 * TILE_B, (const void*)(Alo + ga));
            CP_ASYNC16(so + 2 * TILE_B, (const void*)(Bhi + gb));
            CP_ASYNC16(so + 3 * TILE_B, (const void*)(Blo + gb));
        }
    };

    issue(0, 0);
    CP_COMMIT();

    for (int ch = 0; ch < nchunks; ch++) {
        if (ch + 1 < nchunks) {
            issue((ch + 1) & 1, (ch + 1) << 6);
            CP_COMMIT();
            CP_WAIT(1);
        } else {
            CP_WAIT(0);
        }
        __syncthreads();

        uint32_t sA = sb + (uint32_t)(ch & 1) * STAGE_B;
        uint32_t sB = sA + 2 * TILE_B;
#pragma unroll
        for (int ks = 0; ks < 4; ks++) {
            uint32_t ah[2][4], al[2][4];
#pragma unroll
            for (int mt = 0; mt < 2; mt++) {
                uint32_t ad = sA + (uint32_t)(warp_m * 32 + mt * 16 + a_row_l) * 144
                            + (uint32_t)(ks * 16 + a_col_l) * 2;
                LDSM_X4(ah[mt][0], ah[mt][1], ah[mt][2], ah[mt][3], ad);
                LDSM_X4(al[mt][0], al[mt][1], al[mt][2], al[mt][3], ad + TILE_B);
            }
            uint32_t bh[8][2], bl[8][2];
#pragma unroll
            for (int p = 0; p < 4; p++) {
                uint32_t bd = sB + (uint32_t)(warp_n * 64 + p * 16 + b_row_l) * 144
                            + (uint32_t)(ks * 16 + b_col_l) * 2;
                uint32_t q0, q1, q2, q3;
                LDSM_X4(q0, q1, q2, q3, bd);
                bh[2 * p][0] = q0; bh[2 * p][1] = q1;
                bh[2 * p + 1][0] = q2; bh[2 * p + 1][1] = q3;
                LDSM_X4(q0, q1, q2, q3, bd + TILE_B);
                bl[2 * p][0] = q0; bl[2 * p][1] = q1;
                bl[2 * p + 1][0] = q2; bl[2 * p + 1][1] = q3;
            }
#pragma unroll
            for (int mt = 0; mt < 2; mt++)
#pragma unroll
                for (int nt = 0; nt < 8; nt++)
                    MMA_BF16(acc[mt][nt], ah[mt], bh[nt]);
#pragma unroll
            for (int mt = 0; mt < 2; mt++)
#pragma unroll
                for (int nt = 0; nt < 8; nt++)
                    MMA_BF16(acc[mt][nt], ah[mt], bl[nt]);
#pragma unroll
            for (int mt = 0; mt < 2; mt++)
#pragma unroll
                for (int nt = 0; nt < 8; nt++)
                    MMA_BF16(acc[mt][nt], al[mt], bh[nt]);
        }
        __syncthreads();
    }

    int tr = lane >> 2;
    int tc = (lane & 3) * 2;
#pragma unroll
    for (int mt = 0; mt < 2; mt++) {
        int row = m0 + warp_m * 32 + mt * 16 + tr;
#pragma unroll
        for (int nt = 0; nt < 8; nt++) {
            int col = n0 + warp_n * 64 + nt * 8 + tc;
            *(float2*)&C[(size_t)row * ldc + col] =
                make_float2(acc[mt][nt][0], acc[mt][nt][1]);
            *(float2*)&C[(size_t)(row + 8) * ldc + col] =
                make_float2(acc[mt][nt][2], acc[mt][nt][3]);
        }
    }
}

// ---------------- fp16 HMMA GEMM, 2-term (upd: u = Y @ enc), split-K --------
// A = Yf [BT x NN] k-major fp16 (single); B = ench/encl [DD x NN] k-major fp16.
#define STAGE_F (3 * TILE_B)        // 55296
#define TCF_SMEM (2 * STAGE_F)      // 110592
__global__ void __launch_bounds__(256, 1)
tc_gemm_f16(const __half* __restrict__ A,
            const __half* __restrict__ Bhi, const __half* __restrict__ Blo,
            int Kslice, int lda, int ldb,
            float* __restrict__ C, int ldc, size_t cstride) {
    char* smc = dynsm;
    uint32_t sb = smem_u32(smc);

    int tid = threadIdx.x;
    int wid = tid >> 5;
    int lane = tid & 31;
    int warp_m = wid & 3;
    int warp_n = wid >> 2;

    int m0 = blockIdx.y * 128;
    int n0 = blockIdx.x * 128;
    int koff = blockIdx.z * Kslice;
    C += (size_t)blockIdx.z * cstride;

    float acc[2][8][4] = {};

    uint32_t a_row_l = (uint32_t)(lane & 15);
    uint32_t a_col_l = (uint32_t)((lane >> 4) << 3);
    uint32_t b_row_l = (uint32_t)(((lane & 16) >> 1) + (lane & 7));
    uint32_t b_col_l = (uint32_t)(lane & 8);

    int lr[4], lcc[4];
#pragma unroll
    for (int q = 0; q < 4; q++) {
        int l = tid + q * 256;
        lr[q] = l >> 3;
        lcc[q] = l & 7;
    }

    int nchunks = Kslice >> 6;

    auto issue = [&](int st, int kc) {
        uint32_t sbase = sb + (uint32_t)st * STAGE_F;
#pragma unroll
        for (int q = 0; q < 4; q++) {
            int r = lr[q], c = lcc[q];
            uint32_t so = sbase + (uint32_t)(r * 144 + c * 16);
            size_t ga = (size_t)(m0 + r) * lda + koff + kc + c * 8;
            size_t gb = (size_t)(n0 + r) * ldb + koff + kc + c * 8;
            CP_ASYNC16(so + 0 * TILE_B, (const void*)(A + ga));
            CP_ASYNC16(so + 1 * TILE_B, (const void*)(Bhi + gb));
            CP_ASYNC16(so + 2 * TILE_B, (const void*)(Blo + gb));
        }
    };

    issue(0, 0);
    CP_COMMIT();

    for (int ch = 0; ch < nchunks; ch++) {
        if (ch + 1 < nchunks) {
            issue((ch + 1) & 1, (ch + 1) << 6);
            CP_COMMIT();
            CP_WAIT(1);
        } else {
            CP_WAIT(0);
        }
        __syncthreads();

        uint32_t sA = sb + (uint32_t)(ch & 1) * STAGE_F;
        uint32_t sB = sA + TILE_B;
#pragma unroll
        for (int ks = 0; ks < 4; ks++) {
            uint32_t aa[2][4];
#pragma unroll
            for (int mt = 0; mt < 2; mt++) {
                uint32_t ad = sA + (uint32_t)(warp_m * 32 + mt * 16 + a_row_l) * 144
                            + (uint32_t)(ks * 16 + a_col_l) * 2;
                LDSM_X4(aa[mt][0], aa[mt][1], aa[mt][2], aa[mt][3], ad);
            }
            uint32_t bh[8][2], bl[8][2];
#pragma unroll
            for (int p = 0; p < 4; p++) {
                uint32_t bd = sB + (uint32_t)(warp_n * 64 + p * 16 + b_row_l) * 144
                            + (uint32_t)(ks * 16 + b_col_l) * 2;
                uint32_t q0, q1, q2, q3;
                LDSM_X4(q0, q1, q2, q3, bd);
                bh[2 * p][0] = q0; bh[2 * p][1] = q1;
                bh[2 * p + 1][0] = q2; bh[2 * p + 1][1] = q3;
                LDSM_X4(q0, q1, q2, q3, bd + TILE_B);
                bl[2 * p][0] = q0; bl[2 * p][1] = q1;
                bl[2 * p + 1][0] = q2; bl[2 * p + 1][1] = q3;
            }
#pragma unroll
            for (int mt = 0; mt < 2; mt++)
#pragma unroll
                for (int nt = 0; nt < 8; nt++)
                    MMA_F16(acc[mt][nt], aa[mt], bh[nt]);
#pragma unroll
            for (int mt = 0; mt < 2; mt++)
#pragma unroll
                for (int nt = 0; nt < 8; nt++)
                    MMA_F16(acc[mt][nt], aa[mt], bl[nt]);
        }
        __syncthreads();
    }

    int tr = lane >> 2;
    int tc = (lane & 3) * 2;
#pragma unroll
    for (int mt = 0; mt < 2; mt++) {
        int row = m0 + warp_m * 32 + mt * 16 + tr;
#pragma unroll
        for (int nt = 0; nt < 8; nt++) {
            int col = n0 + warp_n * 64 + nt * 8 + tc;
            *(float2*)&C[(size_t)row * ldc + col] =
                make_float2(acc[mt][nt][0], acc[mt][nt][1]);
            *(float2*)&C[(size_t)(row + 8) * ldc + col] =
                make_float2(acc[mt][nt][2], acc[mt][nt][3]);
        }
    }
}

// ---------------- launch -----------------------------------------------------
extern "C" void kernel_launch(void* const* d_in, const int* in_sizes, int n_in,
                              void* d_out, int out_size) {
    const int* idx = (const int*)d_in[0];
    const float* wte = (const float*)d_in[1];
    const float* encoder = (const float*)d_in[2];
    const float* dec_x = (const float*)d_in[3];
    const float* dec_y = (const float*)d_in[4];
    const float* readout = (const float*)d_in[5];
    float* out = (float*)d_out;

    float *pv, *pH, *pup;
    __nv_bfloat16 *pvhi, *pvlo, *pRhi, *pRlo, *palnhi, *palnlo;
    __nv_bfloat16 *pwxhi, *pwxlo, *pwyhi, *pwylo, *prdhi, *prdlo;
    __half *pench, *pencl, *pYf;
    __nv_bfloat16 *pRThi, *pRTlo, *pVThi, *pVTlo, *pMhi, *pMlo;
    cudaGetSymbolAddress((void**)&pv, g_v);
    cudaGetSymbolAddress((void**)&pH, g_H);
    cudaGetSymbolAddress((void**)&pup, g_upart);
    cudaGetSymbolAddress((void**)&pvhi, g_vhi);
    cudaGetSymbolAddress((void**)&pvlo, g_vlo);
    cudaGetSymbolAddress((void**)&pRhi, g_Rhi);
    cudaGetSymbolAddress((void**)&pRlo, g_Rlo);
    cudaGetSymbolAddress((void**)&palnhi, g_alnhi);
    cudaGetSymbolAddress((void**)&palnlo, g_alnlo);
    cudaGetSymbolAddress((void**)&pwxhi, g_wxhi);
    cudaGetSymbolAddress((void**)&pwxlo, g_wxlo);
    cudaGetSymbolAddress((void**)&pwyhi, g_wyhi);
    cudaGetSymbolAddress((void**)&pwylo, g_wylo);
    cudaGetSymbolAddress((void**)&pench, g_ench);
    cudaGetSymbolAddress((void**)&pencl, g_encl);
    cudaGetSymbolAddress((void**)&prdhi, g_rdhi);
    cudaGetSymbolAddress((void**)&prdlo, g_rdlo);
    cudaGetSymbolAddress((void**)&pYf, g_Yf);
    cudaGetSymbolAddress((void**)&pRThi, g_RThi);
    cudaGetSymbolAddress((void**)&pRTlo, g_RTlo);
    cudaGetSymbolAddress((void**)&pVThi, g_VThi);
    cudaGetSymbolAddress((void**)&pVTlo, g_VTlo);
    cudaGetSymbolAddress((void**)&pMhi, g_Mhi);
    cudaGetSymbolAddress((void**)&pMlo, g_Mlo);

    cudaFuncSetAttribute(tc_gemm,
                         cudaFuncAttributeMaxDynamicSharedMemorySize, TCG_SMEM);
    cudaFuncSetAttribute(tc_gemm_f16,
                         cudaFuncAttributeMaxDynamicSharedMemorySize, TCF_SMEM);
    cudaFuncSetAttribute(xy_gemm,
                         cudaFuncAttributeMaxDynamicSharedMemorySize, XY_SMEM);
    cudaFuncSetAttribute(kv_outer_kernel,
                         cudaFuncAttributeMaxDynamicSharedMemorySize, KVO_SMEM);
    cudaFuncSetAttribute(attn_out_kernel,
                         cudaFuncAttributeMaxDynamicSharedMemorySize, AO_SMEM);

    embed_ln_rope_kernel<<<BT, 256>>>(idx, wte, pv, pvhi, pvlo, pRhi, pRlo);
    conv_all_kernel<<<24832, 256>>>(dec_x, dec_y, encoder, readout,
                                    pwxhi, pwxlo, pwyhi, pwylo,
                                    pench, pencl, prdhi, prdlo);

    for (int layer = 0; layer < LL; layer++) {
        split_T_both_kernel<<<dim3(TT / 32, DD / 32, 2 * BB), 256>>>(
            pRhi, pRlo, pvhi, pvlo, pRThi, pRTlo, pVThi, pVTlo);
        kv_outer_kernel<<<dim3(32, BB, 2), 512, KVO_SMEM>>>(pVThi, pVTlo,
                                                            pRThi, pRTlo, pH);
        prefix_split_kernel<<<dim3(256, BB), 256>>>(pH, pMhi, pMlo);
        attn_out_kernel<<<dim3(32, BB), 256, AO_SMEM>>>(pRhi, pRlo, pVThi, pVTlo,
                                                        pMhi, pMlo, palnhi, palnlo);
        xy_gemm<<<dim3(BT / 128, NN / 128), 256, XY_SMEM>>>(
            pvhi, pvlo, palnhi, palnlo, pwxhi, pwxlo, pwyhi, pwylo, pYf);
        tc_gemm_f16<<<dim3(DD / 128, BT / 128, SPLITK), 256, TCF_SMEM>>>(
            pYf, pench, pencl, NN / SPLITK, NN, NN, pup, DD, (size_t)BT * DD);
        ln_add_rope_kernel<<<BT, 256>>>(pup, pv, pvhi, pvlo, pRhi, pRlo);
    }

    tc_gemm<<<dim3(VOCAB / 128, BT / 128, 1), 256, TCG_SMEM>>>(
        pvhi, pvlo, prdhi, prdlo, DD, DD, DD, out, VOCAB, 0);
}

// round 16
// speedup vs baseline: 1.3627x; 1.2072x over previous
#include <cuda_runtime.h>
#include <cuda_bf16.h>
#include <cuda_fp16.h>
#include <math.h>
#include <stdint.h>

// Problem constants
#define BB 4
#define TT 2048
#define BT 8192      // B*T
#define DD 256
#define NN 8192
#define HH 4
#define MM 2048      // N/H
#define LL 6
#define VOCAB 256
#define EPS 1e-5f
#define SPLITK 8

// single dynamic-smem declaration shared by all kernels
extern __shared__ char dynsm[];

// ---------------- scratch buffers (device globals, no allocations) --------
__device__ float g_v[BT * DD];
__device__ float g_upart[SPLITK * BT * DD];                   // split-K partials
__device__ __nv_bfloat16 g_vhi[BT * DD], g_vlo[BT * DD];      // bf16 (readout)
__device__ __half g_vh16[BT * DD], g_vl16[BT * DD];           // fp16 (xy)
__device__ __nv_bfloat16 g_Rhi[BT * DD], g_Rlo[BT * DD];
__device__ __nv_bfloat16 g_alnhi[BT * DD], g_alnlo[BT * DD];
__device__ __half g_alnh16[BT * DD], g_alnl16[BT * DD];       // fp16 (xy)
__device__ __half g_wx[NN * DD], g_wy[NN * DD];               // fp16 single weights
__device__ __half g_ench[DD * NN], g_encl[DD * NN];           // fp16 enc hi/lo
__device__ __nv_bfloat16 g_rdhi[VOCAB * DD], g_rdlo[VOCAB * DD];
__device__ __half g_Yf[(size_t)BT * NN];                      // 128 MB, fp16 Y
// linear-attention scratch (bf16 — needs range)
__device__ __nv_bfloat16 g_RThi[BB * DD * TT], g_RTlo[BB * DD * TT];
__device__ __nv_bfloat16 g_VThi[BB * DD * TT], g_VTlo[BB * DD * TT];
__device__ float g_H[(size_t)BB * 32 * DD * DD];
__device__ __nv_bfloat16 g_Mhi[(size_t)BB * 32 * DD * DD];
__device__ __nv_bfloat16 g_Mlo[(size_t)BB * 32 * DD * DD];

// ---------------- PTX helpers ----------------------------------------------
__device__ __forceinline__ uint32_t smem_u32(const void* p) {
    uint32_t a;
    asm("{ .reg .u64 t; cvta.to.shared.u64 t, %1; cvt.u32.u64 %0, t; }"
        : "=r"(a) : "l"(p));
    return a;
}

#define LDSM_X4(r0, r1, r2, r3, addr) \
    asm volatile("ldmatrix.sync.aligned.m8n8.x4.shared.b16 {%0,%1,%2,%3}, [%4];" \
        : "=r"(r0), "=r"(r1), "=r"(r2), "=r"(r3) : "r"(addr))

#define MMA_BF16(d, a, b) \
    asm volatile( \
        "mma.sync.aligned.m16n8k16.row.col.f32.bf16.bf16.f32 " \
        "{%0,%1,%2,%3}, {%4,%5,%6,%7}, {%8,%9}, {%0,%1,%2,%3};" \
        : "+f"((d)[0]), "+f"((d)[1]), "+f"((d)[2]), "+f"((d)[3]) \
        : "r"((a)[0]), "r"((a)[1]), "r"((a)[2]), "r"((a)[3]), \
          "r"((b)[0]), "r"((b)[1]))

#define MMA_F16(d, a, b) \
    asm volatile( \
        "mma.sync.aligned.m16n8k16.row.col.f32.f16.f16.f32 " \
        "{%0,%1,%2,%3}, {%4,%5,%6,%7}, {%8,%9}, {%0,%1,%2,%3};" \
        : "+f"((d)[0]), "+f"((d)[1]), "+f"((d)[2]), "+f"((d)[3]) \
        : "r"((a)[0]), "r"((a)[1]), "r"((a)[2]), "r"((a)[3]), \
          "r"((b)[0]), "r"((b)[1]))

#define CP_ASYNC16(dst, src) \
    asm volatile("cp.async.cg.shared.global [%0], [%1], 16;" \
        :: "r"(dst), "l"(src) : "memory")
#define CP_COMMIT() asm volatile("cp.async.commit_group;" ::: "memory")
#define CP_WAIT(N)  asm volatile("cp.async.wait_group %0;" :: "n"(N) : "memory")

// ---------------- misc helpers ----------------------------------------------
__device__ __forceinline__ float warp_sum(float v) {
#pragma unroll
    for (int o = 16; o > 0; o >>= 1) v += __shfl_xor_sync(0xffffffffu, v, o);
    return v;
}
__device__ __forceinline__ void split2(float x, __nv_bfloat16& h, __nv_bfloat16& l) {
    __nv_bfloat16 hh = __float2bfloat16(x);
    h = hh;
    l = __float2bfloat16(x - __bfloat162float(hh));
}
__device__ __forceinline__ void split2h(float x, __half& h, __half& l) {
    __half hh = __float2half(x);
    h = hh;
    l = __float2half(x - __half2float(hh));
}
__device__ __forceinline__ float rope_val(const float* rowbuf, int d, int t) {
    float x = rowbuf[d];
    float xr = (d < 128) ? -rowbuf[d + 128] : rowbuf[d - 128];
    int j = d & 127;
    float inv = expf(-(float)j * (2.f / 256.f) * 9.210340371976184f);
    float ang = (float)t * inv;
    const float TWO_PI_HI = 6.28318548202514648f;
    const float TWO_PI_LO = -1.74845553e-7f;
    float k = rintf(ang * 0.15915494309189535f);
    float r = fmaf(-k, TWO_PI_HI, ang);
    r = fmaf(-k, TWO_PI_LO, r);
    float sn = sinf(r), cs = cosf(r);
    return x * cs + xr * sn;
}

// ---------------- all weight conversions in one kernel ----------------------
__global__ void conv_all_kernel(const float* __restrict__ dec_x,
                                const float* __restrict__ dec_y,
                                const float* __restrict__ enc,
                                const float* __restrict__ rd,
                                __half* __restrict__ wx, __half* __restrict__ wy,
                                __half* __restrict__ ench, __half* __restrict__ encl,
                                __nv_bfloat16* __restrict__ rdhi,
                                __nv_bfloat16* __restrict__ rdlo) {
    int bid = blockIdx.x;
    if (bid < 8192) {
        size_t i = (size_t)bid * 256 + threadIdx.x;
        int d = (int)(i & 255);
        size_t n = i >> 8;
        int h = (int)(n >> 11), m = (int)(n & 2047);
        wx[i] = __float2half(dec_x[((size_t)h * DD + d) * MM + m]);
    } else if (bid < 16384) {
        size_t i = (size_t)(bid - 8192) * 256 + threadIdx.x;
        int d = (int)(i & 255);
        size_t n = i >> 8;
        int h = (int)(n >> 11), m = (int)(n & 2047);
        wy[i] = __float2half(dec_y[((size_t)h * DD + d) * MM + m]);
    } else if (bid < 24576) {
        size_t i = (size_t)(bid - 16384) * 256 + threadIdx.x;
        int n = (int)(i & 8191);
        int d = (int)(i >> 13);
        float x = enc[(size_t)n * DD + d];
        split2h(x, ench[i], encl[i]);
    } else {
        size_t i = (size_t)(bid - 24576) * 256 + threadIdx.x;
        int d = (int)(i & 255);
        int v = (int)(i >> 8);
        split2(rd[(size_t)d * VOCAB + v], rdhi[i], rdlo[i]);
    }
}

// ---------------- embed + LN + RoPE ------------------------------------------
__global__ void embed_ln_rope_kernel(const int* __restrict__ idx,
                                     const float* __restrict__ wte,
                                     float* __restrict__ out,
                                     __nv_bfloat16* __restrict__ ohi,
                                     __nv_bfloat16* __restrict__ olo,
                                     __half* __restrict__ oh16,
                                     __half* __restrict__ ol16,
                                     __nv_bfloat16* __restrict__ Rhi,
                                     __nv_bfloat16* __restrict__ Rlo) {
    __shared__ float sh[8];
    __shared__ float rowbuf[256];
    int row = blockIdx.x;
    int d = threadIdx.x;
    float x = wte[idx[row] * DD + d];
    int wid = d >> 5, lane = d & 31;
    float s = warp_sum(x);
    if (lane == 0) sh[wid] = s;
    __syncthreads();
    float tot = 0.f;
#pragma unroll
    for (int i = 0; i < 8; i++) tot += sh[i];
    float mu = tot * (1.f / 256.f);
    __syncthreads();
    float dx = x - mu;
    s = warp_sum(dx * dx);
    if (lane == 0) sh[wid] = s;
    __syncthreads();
    tot = 0.f;
#pragma unroll
    for (int i = 0; i < 8; i++) tot += sh[i];
    float r = dx * rsqrtf(tot * (1.f / 256.f) + EPS);
    int o = row * DD + d;
    out[o] = r;
    split2(r, ohi[o], olo[o]);
    split2h(r, oh16[o], ol16[o]);
    rowbuf[d] = r;
    __syncthreads();
    float val = rope_val(rowbuf, d, row & (TT - 1));
    split2(val, Rhi[o], Rlo[o]);
}

// ---------------- LN + residual add (sums SPLITK partials) + RoPE -----------
__global__ void ln_add_rope_kernel(const float* __restrict__ up,
                                   float* __restrict__ v,
                                   __nv_bfloat16* __restrict__ vhi,
                                   __nv_bfloat16* __restrict__ vlo,
                                   __half* __restrict__ vh16,
                                   __half* __restrict__ vl16,
                                   __nv_bfloat16* __restrict__ Rhi,
                                   __nv_bfloat16* __restrict__ Rlo) {
    __shared__ float sh[8];
    __shared__ float rowbuf[256];
    int row = blockIdx.x;
    int d = threadIdx.x;
    int o = row * DD + d;
    float x = 0.f;
#pragma unroll
    for (int p = 0; p < SPLITK; p++) x += up[(size_t)p * BT * DD + o];
    int wid = d >> 5, lane = d & 31;
    float s = warp_sum(x);
    if (lane == 0) sh[wid] = s;
    __syncthreads();
    float tot = 0.f;
#pragma unroll
    for (int i = 0; i < 8; i++) tot += sh[i];
    float mu = tot * (1.f / 256.f);
    __syncthreads();
    float dx = x - mu;
    s = warp_sum(dx * dx);
    if (lane == 0) sh[wid] = s;
    __syncthreads();
    tot = 0.f;
#pragma unroll
    for (int i = 0; i < 8; i++) tot += sh[i];
    float nv = v[o] + dx * rsqrtf(tot * (1.f / 256.f) + EPS);
    v[o] = nv;
    split2(nv, vhi[o], vlo[o]);
    split2h(nv, vh16[o], vl16[o]);
    rowbuf[d] = nv;
    __syncthreads();
    float val = rope_val(rowbuf, d, row & (TT - 1));
    split2(val, Rhi[o], Rlo[o]);
}

// ---------------- transpose (pure bf16 permute) for R and v hi/lo -----------
__global__ void split_T_both_kernel(const __nv_bfloat16* __restrict__ Rhi,
                                    const __nv_bfloat16* __restrict__ Rlo,
                                    const __nv_bfloat16* __restrict__ vhi,
                                    const __nv_bfloat16* __restrict__ vlo,
                                    __nv_bfloat16* __restrict__ RThi,
                                    __nv_bfloat16* __restrict__ RTlo,
                                    __nv_bfloat16* __restrict__ VThi,
                                    __nv_bfloat16* __restrict__ VTlo) {
    __shared__ __nv_bfloat16 th[32][34];
    __shared__ __nv_bfloat16 tl[32][34];
    int zb = blockIdx.z;
    int b = zb & 3;
    const __nv_bfloat16* hi_in = (zb < 4) ? Rhi : vhi;
    const __nv_bfloat16* lo_in = (zb < 4) ? Rlo : vlo;
    __nv_bfloat16* hi_out = (zb < 4) ? RThi : VThi;
    __nv_bfloat16* lo_out = (zb < 4) ? RTlo : VTlo;
    int t0 = blockIdx.x * 32;
    int d0 = blockIdx.y * 32;
    int tx = threadIdx.x & 31, ty = threadIdx.x >> 5;
#pragma unroll
    for (int i = 0; i < 4; i++) {
        int t = ty + i * 8;
        size_t g = ((size_t)(b * TT + t0 + t)) * DD + d0 + tx;
        th[t][tx] = hi_in[g];
        tl[t][tx] = lo_in[g];
    }
    __syncthreads();
#pragma unroll
    for (int i = 0; i < 4; i++) {
        int d = ty + i * 8;
        size_t o = ((size_t)(b * DD + d0 + d)) * TT + t0 + tx;
        hi_out[o] = th[tx][d];
        lo_out[o] = tl[tx][d];
    }
}

// ---------------- kv_outer: H[b][i] = V_i^T K_i (256x256, k=64) -------------
#define KVO_SMEM 110592
__global__ void __launch_bounds__(512, 1)
kv_outer_kernel(const __nv_bfloat16* __restrict__ VThi,
                const __nv_bfloat16* __restrict__ VTlo,
                const __nv_bfloat16* __restrict__ RThi,
                const __nv_bfloat16* __restrict__ RTlo,
                float* __restrict__ H) {
    char* smc = dynsm;
    uint32_t sb = smem_u32(smc);
    int i = blockIdx.x, b = blockIdx.y, e0 = blockIdx.z * 128;
    int s0 = i * 64;
    int tid = threadIdx.x;
    int wid = tid >> 5, lane = tid & 31;
    int wm = wid & 3, wn = wid >> 2;

    for (int l = tid; l < 1024; l += 512) {
        int r = l >> 3, c = l & 7;
        size_t g = ((size_t)(b * DD + e0 + r)) * TT + s0 + c * 8;
        uint32_t so = (uint32_t)(r * 144 + c * 16);
        *(uint4*)(smc + so) = *(const uint4*)(VThi + g);
        *(uint4*)(smc + 18432 + so) = *(const uint4*)(VTlo + g);
    }
    for (int l = tid; l < 2048; l += 512) {
        int r = l >> 3, c = l & 7;
        size_t g = ((size_t)(b * DD + r)) * TT + s0 + c * 8;
        uint32_t so = (uint32_t)(36864 + r * 144 + c * 16);
        *(uint4*)(smc + so) = *(const uint4*)(RThi + g);
        *(uint4*)(smc + 36864 + so) = *(const uint4*)(RTlo + g);
    }
    __syncthreads();

    uint32_t a_row_l = (uint32_t)(lane & 15);
    uint32_t a_col_l = (uint32_t)((lane >> 4) << 3);
    uint32_t b_row_l = (uint32_t)(((lane & 16) >> 1) + (lane & 7));
    uint32_t b_col_l = (uint32_t)(lane & 8);

    float acc[2][8][4] = {};
#pragma unroll
    for (int ks = 0; ks < 4; ks++) {
        uint32_t ah[2][4], al[2][4];
#pragma unroll
        for (int mi = 0; mi < 2; mi++) {
            uint32_t ad = sb + (uint32_t)(wm * 32 + mi * 16 + a_row_l) * 144
                        + (uint32_t)(ks * 16 + a_col_l) * 2;
            LDSM_X4(ah[mi][0], ah[mi][1], ah[mi][2], ah[mi][3], ad);
            LDSM_X4(al[mi][0], al[mi][1], al[mi][2], al[mi][3], ad + 18432);
        }
        uint32_t bh[8][2], bl[8][2];
#pragma unroll
        for (int p = 0; p < 4; p++) {
            uint32_t bd = sb + 36864 + (uint32_t)(wn * 64 + p * 16 + b_row_l) * 144
                        + (uint32_t)(ks * 16 + b_col_l) * 2;
            uint32_t q0, q1, q2, q3;
            LDSM_X4(q0, q1, q2, q3, bd);
            bh[2 * p][0] = q0; bh[2 * p][1] = q1;
            bh[2 * p + 1][0] = q2; bh[2 * p + 1][1] = q3;
            LDSM_X4(q0, q1, q2, q3, bd + 36864);
            bl[2 * p][0] = q0; bl[2 * p][1] = q1;
            bl[2 * p + 1][0] = q2; bl[2 * p + 1][1] = q3;
        }
#pragma unroll
        for (int mi = 0; mi < 2; mi++)
#pragma unroll
            for (int nt = 0; nt < 8; nt++)
                MMA_BF16(acc[mi][nt], ah[mi], bh[nt]);
#pragma unroll
        for (int mi = 0; mi < 2; mi++)
#pragma unroll
            for (int nt = 0; nt < 8; nt++)
                MMA_BF16(acc[mi][nt], ah[mi], bl[nt]);
#pragma unroll
        for (int mi = 0; mi < 2; mi++)
#pragma unroll
            for (int nt = 0; nt < 8; nt++)
                MMA_BF16(acc[mi][nt], al[mi], bh[nt]);
    }

    int tr = lane >> 2, tc = (lane & 3) * 2;
    size_t base = ((size_t)(b * 32 + i)) * 65536;
#pragma unroll
    for (int mi = 0; mi < 2; mi++) {
        int e = e0 + wm * 32 + mi * 16 + tr;
#pragma unroll
        for (int nt = 0; nt < 8; nt++) {
            int d = wn * 64 + nt * 8 + tc;
            *(float2*)&H[base + (size_t)e * 256 + d] =
                make_float2(acc[mi][nt][0], acc[mi][nt][1]);
            *(float2*)&H[base + (size_t)(e + 8) * 256 + d] =
                make_float2(acc[mi][nt][2], acc[mi][nt][3]);
        }
    }
}

// ---------------- exclusive prefix over chunks + bf16 split -----------------
__global__ void prefix_split_kernel(const float* __restrict__ H,
                                    __nv_bfloat16* __restrict__ Mhi,
                                    __nv_bfloat16* __restrict__ Mlo) {
    int b = blockIdx.y;
    int j = blockIdx.x * 256 + threadIdx.x;
    size_t base = (size_t)b * 32 * 65536 + j;
    float acc = 0.f;
#pragma unroll 4
    for (int i = 0; i < 32; i++) {
        size_t off = base + (size_t)i * 65536;
        __nv_bfloat16 h, l;
        split2(acc, h, l);
        Mhi[off] = h;
        Mlo[off] = l;
        acc += H[off];
    }
}

// ---------------- attn_out + fused row-LN ------------------------------------
#define AO_Q    0
#define AO_QLO  33792
#define AO_B    67584
#define AO_BLO  104448
#define AO_S    141312
#define AO_SLO  150528
#define AO_OBUF 67584
#define AO_SMEM 159744
__global__ void __launch_bounds__(256, 1)
attn_out_kernel(const __nv_bfloat16* __restrict__ Rhi,
                const __nv_bfloat16* __restrict__ Rlo,
                const __nv_bfloat16* __restrict__ VThi,
                const __nv_bfloat16* __restrict__ VTlo,
                const __nv_bfloat16* __restrict__ Mhi,
                const __nv_bfloat16* __restrict__ Mlo,
                __half* __restrict__ alnh16,
                __half* __restrict__ alnl16) {
    char* smc = dynsm;
    uint32_t sb = smem_u32(smc);
    int i = blockIdx.x, b = blockIdx.y;
    int q0 = i * 64;
    int tid = threadIdx.x;
    int wid = tid >> 5, lane = tid & 31;

    for (int l = tid; l < 2048; l += 256) {
        int r = l >> 5, c = l & 31;
        size_t g = ((size_t)(b * TT + q0 + r)) * DD + c * 8;
        uint32_t so = (uint32_t)(r * 528 + c * 16);
        *(uint4*)(smc + AO_Q + so) = *(const uint4*)(Rhi + g);
        *(uint4*)(smc + AO_QLO + so) = *(const uint4*)(Rlo + g);
    }
    for (int l = tid; l < 2048; l += 256) {
        int r = l >> 3, c = l & 7;
        size_t g = ((size_t)(b * DD + r)) * TT + q0 + c * 8;
        uint32_t so = (uint32_t)(r * 144 + c * 16);
        *(uint4*)(smc + AO_B + so) = *(const uint4*)(VThi + g);
        *(uint4*)(smc + AO_BLO + so) = *(const uint4*)(VTlo + g);
    }
    __syncthreads();

    uint32_t a_row_l = (uint32_t)(lane & 15);
    uint32_t a_col_l = (uint32_t)((lane >> 4) << 3);
    uint32_t b_row_l = (uint32_t)(((lane & 16) >> 1) + (lane & 7));
    uint32_t b_col_l = (uint32_t)(lane & 8);
    int tr = lane >> 2, tc = (lane & 3) * 2;

    int wt = wid & 1, ws = wid >> 1;
    {
        float sacc[2][2][4] = {};
#pragma unroll
        for (int ks = 0; ks < 16; ks++) {
            uint32_t ah[2][4], al[2][4];
#pragma unroll
            for (int mi = 0; mi < 2; mi++) {
                uint32_t ad = sb + AO_Q + (uint32_t)(wt * 32 + mi * 16 + a_row_l) * 528
                            + (uint32_t)(ks * 16 + a_col_l) * 2;
                LDSM_X4(ah[mi][0], ah[mi][1], ah[mi][2], ah[mi][3], ad);
                LDSM_X4(al[mi][0], al[mi][1], al[mi][2], al[mi][3], ad + 33792);
            }
            uint32_t bh[2][2], bl[2][2];
            {
                uint32_t bd = sb + AO_Q + (uint32_t)(ws * 16 + b_row_l) * 528
                            + (uint32_t)(ks * 16 + b_col_l) * 2;
                uint32_t p0, p1, p2, p3;
                LDSM_X4(p0, p1, p2, p3, bd);
                bh[0][0] = p0; bh[0][1] = p1; bh[1][0] = p2; bh[1][1] = p3;
                LDSM_X4(p0, p1, p2, p3, bd + 33792);
                bl[0][0] = p0; bl[0][1] = p1; bl[1][0] = p2; bl[1][1] = p3;
            }
#pragma unroll
            for (int mi = 0; mi < 2; mi++)
#pragma unroll
                for (int ni = 0; ni < 2; ni++) {
                    MMA_BF16(sacc[mi][ni], ah[mi], bh[ni]);
                    MMA_BF16(sacc[mi][ni], ah[mi], bl[ni]);
                    MMA_BF16(sacc[mi][ni], al[mi], bh[ni]);
                }
        }
#pragma unroll
        for (int mi = 0; mi < 2; mi++)
#pragma unroll
            for (int ni = 0; ni < 2; ni++) {
                int t0l = wt * 32 + mi * 16 + tr;
                int sl = ws * 16 + ni * 8 + tc;
                float s0v = (sl > t0l) ? 0.f : sacc[mi][ni][0];
                float s1v = (sl + 1 > t0l) ? 0.f : sacc[mi][ni][1];
                float s2v = (sl > t0l + 8) ? 0.f : sacc[mi][ni][2];
                float s3v = (sl + 1 > t0l + 8) ? 0.f : sacc[mi][ni][3];
                __nv_bfloat16 h0, l0, h1, l1;
                split2(s0v, h0, l0); split2(s1v, h1, l1);
                *(__nv_bfloat162*)(smc + AO_S + t0l * 144 + sl * 2) = __halves2bfloat162(h0, h1);
                *(__nv_bfloat162*)(smc + AO_SLO + t0l * 144 + sl * 2) = __halves2bfloat162(l0, l1);
                split2(s2v, h0, l0); split2(s3v, h1, l1);
                *(__nv_bfloat162*)(smc + AO_S + (t0l + 8) * 144 + sl * 2) = __halves2bfloat162(h0, h1);
                *(__nv_bfloat162*)(smc + AO_SLO + (t0l + 8) * 144 + sl * 2) = __halves2bfloat162(l0, l1);
            }
    }
    __syncthreads();

    int we = wid >> 1;
    float oacc[2][8][4] = {};
#pragma unroll
    for (int ks = 0; ks < 4; ks++) {
        uint32_t ah[2][4], al[2][4];
#pragma unroll
        for (int mi = 0; mi < 2; mi++) {
            uint32_t ad = sb + AO_S + (uint32_t)(wt * 32 + mi * 16 + a_row_l) * 144
                        + (uint32_t)(ks * 16 + a_col_l) * 2;
            LDSM_X4(ah[mi][0], ah[mi][1], ah[mi][2], ah[mi][3], ad);
            LDSM_X4(al[mi][0], al[mi][1], al[mi][2], al[mi][3], ad + 9216);
        }
        uint32_t bh[8][2], bl[8][2];
#pragma unroll
        for (int p = 0; p < 4; p++) {
            uint32_t bd = sb + AO_B + (uint32_t)(we * 64 + p * 16 + b_row_l) * 144
                        + (uint32_t)(ks * 16 + b_col_l) * 2;
            uint32_t p0, p1, p2, p3;
            LDSM_X4(p0, p1, p2, p3, bd);
            bh[2 * p][0] = p0; bh[2 * p][1] = p1;
            bh[2 * p + 1][0] = p2; bh[2 * p + 1][1] = p3;
            LDSM_X4(p0, p1, p2, p3, bd + 36864);
            bl[2 * p][0] = p0; bl[2 * p][1] = p1;
            bl[2 * p + 1][0] = p2; bl[2 * p + 1][1] = p3;
        }
#pragma unroll
        for (int mi = 0; mi < 2; mi++)
#pragma unroll
            for (int nt = 0; nt < 8; nt++) {
                MMA_BF16(oacc[mi][nt], ah[mi], bh[nt]);
                MMA_BF16(oacc[mi][nt], ah[mi], bl[nt]);
                MMA_BF16(oacc[mi][nt], al[mi], bh[nt]);
            }
    }
    __syncthreads();

    size_t mbase = ((size_t)(b * 32 + i)) * 65536;
    for (int dc = 0; dc < 4; dc++) {
        for (int l = tid; l < 2048; l += 256) {
            int r = l >> 3, c = l & 7;
            size_t g = mbase + (size_t)r * 256 + dc * 64 + c * 8;
            uint32_t so = (uint32_t)(r * 144 + c * 16);
            *(uint4*)(smc + AO_B + so) = *(const uint4*)(Mhi + g);
            *(uint4*)(smc + AO_BLO + so) = *(const uint4*)(Mlo + g);
        }
        __syncthreads();
#pragma unroll
        for (int ks = 0; ks < 4; ks++) {
            int ksg = dc * 4 + ks;
            uint32_t ah[2][4], al[2][4];
#pragma unroll
            for (int mi = 0; mi < 2; mi++) {
                uint32_t ad = sb + AO_Q + (uint32_t)(wt * 32 + mi * 16 + a_row_l) * 528
                            + (uint32_t)(ksg * 16 + a_col_l) * 2;
                LDSM_X4(ah[mi][0], ah[mi][1], ah[mi][2], ah[mi][3], ad);
                LDSM_X4(al[mi][0], al[mi][1], al[mi][2], al[mi][3], ad + 33792);
            }
            uint32_t bh[8][2], bl[8][2];
#pragma unroll
            for (int p = 0; p < 4; p++) {
                uint32_t bd = sb + AO_B + (uint32_t)(we * 64 + p * 16 + b_row_l) * 144
                            + (uint32_t)(ks * 16 + b_col_l) * 2;
                uint32_t p0, p1, p2, p3;
                LDSM_X4(p0, p1, p2, p3, bd);
                bh[2 * p][0] = p0; bh[2 * p][1] = p1;
                bh[2 * p + 1][0] = p2; bh[2 * p + 1][1] = p3;
                LDSM_X4(p0, p1, p2, p3, bd + 36864);
                bl[2 * p][0] = p0; bl[2 * p][1] = p1;
                bl[2 * p + 1][0] = p2; bl[2 * p + 1][1] = p3;
            }
#pragma unroll
            for (int mi = 0; mi < 2; mi++)
#pragma unroll
                for (int nt = 0; nt < 8; nt++) {
                    MMA_BF16(oacc[mi][nt], ah[mi], bh[nt]);
                    MMA_BF16(oacc[mi][nt], ah[mi], bl[nt]);
                    MMA_BF16(oacc[mi][nt], al[mi], bh[nt]);
                }
        }
        __syncthreads();
    }

    float* obuf = (float*)(smc + AO_OBUF);
#pragma unroll
    for (int mi = 0; mi < 2; mi++) {
        int rl = wt * 32 + mi * 16 + tr;
#pragma unroll
        for (int nt = 0; nt < 8; nt++) {
            int col = we * 64 + nt * 8 + tc;
            obuf[rl * 260 + col] = oacc[mi][nt][0];
            obuf[rl * 260 + col + 1] = oacc[mi][nt][1];
            obuf[(rl + 8) * 260 + col] = oacc[mi][nt][2];
            obuf[(rl + 8) * 260 + col + 1] = oacc[mi][nt][3];
        }
    }
    __syncthreads();

    for (int rr2 = 0; rr2 < 8; rr2++) {
        int r = wid * 8 + rr2;
        float vals[8];
        float s = 0.f;
#pragma unroll
        for (int k = 0; k < 8; k++) {
            vals[k] = obuf[r * 260 + lane + 32 * k];
            s += vals[k];
        }
        s = warp_sum(s);
        float mu = s * (1.f / 256.f);
        float q = 0.f;
#pragma unroll
        for (int k = 0; k < 8; k++) {
            float dxx = vals[k] - mu;
            q += dxx * dxx;
        }
        q = warp_sum(q);
        float rstd = rsqrtf(q * (1.f / 256.f) + EPS);
        size_t gbase = ((size_t)(b * TT + q0 + r)) * DD;
#pragma unroll
        for (int k = 0; k < 8; k++) {
            __half h, l;
            split2h((vals[k] - mu) * rstd, h, l);
            alnh16[gbase + lane + 32 * k] = h;
            alnl16[gbase + lane + 32 * k] = l;
        }
    }
}

// ---------------- fused XY GEMM: fp16 hi/lo activations x fp16 single W ------
// grid: (BT/128, NN/128); 6 tiles: vh, vl, alnh, alnl, wx, wy
// X = (vh+vl)@wx^T (2 MMAs), Y2 = (alnh+alnl)@wy^T (2 MMAs); Y=relu*relu -> fp16
#define XT 10240                // 128 rows * 80B (32 fp16 cols padded)
#define XSTG (6 * XT)           // 61440
#define XY_SMEM (2 * XSTG)      // 122880
__global__ void __launch_bounds__(256, 1)
xy_gemm(const __half* __restrict__ vhi, const __half* __restrict__ vlo,
        const __half* __restrict__ alnhi, const __half* __restrict__ alnlo,
        const __half* __restrict__ wx, const __half* __restrict__ wy,
        __half* __restrict__ Yf) {
    char* smc = dynsm;
    uint32_t sb = smem_u32(smc);

    int tid = threadIdx.x;
    int wid = tid >> 5;
    int lane = tid & 31;
    int warp_m = wid & 3;
    int warp_n = wid >> 2;

    int m0 = blockIdx.x * 128;
    int n0 = blockIdx.y * 128;

    float accx[2][8][4] = {};
    float accy[2][8][4] = {};

    uint32_t a_row_l = (uint32_t)(lane & 15);
    uint32_t a_col_l = (uint32_t)((lane >> 4) << 3);
    uint32_t b_row_l = (uint32_t)(((lane & 16) >> 1) + (lane & 7));
    uint32_t b_col_l = (uint32_t)(lane & 8);

// 6 tiles x 512 uint4 each = 3072 loads; 12 per thread
#define XY_ISSUE(st, kc) do {                                                  \
    uint32_t sbase = sb + (uint32_t)(st) * XSTG;                               \
    _Pragma("unroll")                                                          \
    for (int q = 0; q < 12; q++) {                                             \
        int l = tid + q * 256;                                                 \
        int tile = l >> 9;                                                     \
        int idx = l & 511;                                                     \
        int r = idx >> 2, c = idx & 3;                                         \
        const __half* mat;                                                     \
        int rb;                                                                \
        switch (tile) {                                                        \
            case 0: mat = vhi;   rb = m0; break;                               \
            case 1: mat = vlo;   rb = m0; break;                               \
            case 2: mat = alnhi; rb = m0; break;                               \
            case 3: mat = alnlo; rb = m0; break;                               \
            case 4: mat = wx;    rb = n0; break;                               \
            default: mat = wy;   rb = n0; break;                               \
        }                                                                      \
        size_t g = (size_t)(rb + r) * DD + (kc) + c * 8;                       \
        uint32_t dst = sbase + (uint32_t)tile * XT + (uint32_t)(r * 80 + c * 16); \
        CP_ASYNC16(dst, (const void*)(mat + g));                               \
    }                                                                          \
} while (0)

    XY_ISSUE(0, 0);
    CP_COMMIT();

    for (int ch = 0; ch < 8; ch++) {
        if (ch + 1 < 8) {
            XY_ISSUE((ch + 1) & 1, (ch + 1) << 5);
            CP_COMMIT();
            CP_WAIT(1);
        } else {
            CP_WAIT(0);
        }
        __syncthreads();

        uint32_t S = sb + (uint32_t)(ch & 1) * XSTG;
#pragma unroll
        for (int ks = 0; ks < 2; ks++) {
            uint32_t arow_off = (uint32_t)(warp_m * 32 + a_row_l) * 80
                              + (uint32_t)(ks * 16 + a_col_l) * 2;
            uint32_t brow_off = (uint32_t)(warp_n * 64 + b_row_l) * 80
                              + (uint32_t)(ks * 16 + b_col_l) * 2;
            uint32_t ah[2][4], al[2][4], bw[8][2];
            // ---- X: A = v (hi/lo), B = wx (single) ----
#pragma unroll
            for (int mt = 0; mt < 2; mt++) {
                uint32_t ad = S + arow_off + (uint32_t)(mt * 16 * 80);
                LDSM_X4(ah[mt][0], ah[mt][1], ah[mt][2], ah[mt][3], ad);
                LDSM_X4(al[mt][0], al[mt][1], al[mt][2], al[mt][3], ad + XT);
            }
#pragma unroll
            for (int p = 0; p < 4; p++) {
                uint32_t bd = S + 4 * XT + brow_off + (uint32_t)(p * 16 * 80);
                uint32_t q0, q1, q2, q3;
                LDSM_X4(q0, q1, q2, q3, bd);
                bw[2 * p][0] = q0; bw[2 * p][1] = q1;
                bw[2 * p + 1][0] = q2; bw[2 * p + 1][1] = q3;
            }
#pragma unroll
            for (int mt = 0; mt < 2; mt++)
#pragma unroll
                for (int nt = 0; nt < 8; nt++)
                    MMA_F16(accx[mt][nt], ah[mt], bw[nt]);
#pragma unroll
            for (int mt = 0; mt < 2; mt++)
#pragma unroll
                for (int nt = 0; nt < 8; nt++)
                    MMA_F16(accx[mt][nt], al[mt], bw[nt]);
            // ---- Y: A = aln (hi/lo), B = wy (single) ----
#pragma unroll
            for (int mt = 0; mt < 2; mt++) {
                uint32_t ad = S + 2 * XT + arow_off + (uint32_t)(mt * 16 * 80);
                LDSM_X4(ah[mt][0], ah[mt][1], ah[mt][2], ah[mt][3], ad);
                LDSM_X4(al[mt][0], al[mt][1], al[mt][2], al[mt][3], ad + XT);
            }
#pragma unroll
            for (int p = 0; p < 4; p++) {
                uint32_t bd = S + 5 * XT + brow_off + (uint32_t)(p * 16 * 80);
                uint32_t q0, q1, q2, q3;
                LDSM_X4(q0, q1, q2, q3, bd);
                bw[2 * p][0] = q0; bw[2 * p][1] = q1;
                bw[2 * p + 1][0] = q2; bw[2 * p + 1][1] = q3;
            }
#pragma unroll
            for (int mt = 0; mt < 2; mt++)
#pragma unroll
                for (int nt = 0; nt < 8; nt++)
                    MMA_F16(accy[mt][nt], ah[mt], bw[nt]);
#pragma unroll
            for (int mt = 0; mt < 2; mt++)
#pragma unroll
                for (int nt = 0; nt < 8; nt++)
                    MMA_F16(accy[mt][nt], al[mt], bw[nt]);
        }
        __syncthreads();
    }

    int tr = lane >> 2;
    int tc = (lane & 3) * 2;
#pragma unroll
    for (int mt = 0; mt < 2; mt++) {
        int row = m0 + warp_m * 32 + mt * 16 + tr;
#pragma unroll
        for (int nt = 0; nt < 8; nt++) {
            int col = n0 + warp_n * 64 + nt * 8 + tc;
            size_t i0 = (size_t)row * NN + col;
            size_t i1 = (size_t)(row + 8) * NN + col;
            float g0 = fmaxf(accx[mt][nt][0], 0.f) * fmaxf(accy[mt][nt][0], 0.f);
            float g1 = fmaxf(accx[mt][nt][1], 0.f) * fmaxf(accy[mt][nt][1], 0.f);
            float g2 = fmaxf(accx[mt][nt][2], 0.f) * fmaxf(accy[mt][nt][2], 0.f);
            float g3 = fmaxf(accx[mt][nt][3], 0.f) * fmaxf(accy[mt][nt][3], 0.f);
            *(__half2*)(Yf + i0) = __floats2half2_rn(g0, g1);
            *(__half2*)(Yf + i1) = __floats2half2_rn(g2, g3);
        }
    }
}

// ---------------- bf16 3-term GEMM (readout) ---------------------------------
#define TILE_B 18432
#define STAGE_B (4 * TILE_B)
#define TCG_SMEM (2 * STAGE_B)
__global__ void __launch_bounds__(256, 1)
tc_gemm(const __nv_bfloat16* __restrict__ Ahi, const __nv_bfloat16* __restrict__ Alo,
        const __nv_bfloat16* __restrict__ Bhi, const __nv_bfloat16* __restrict__ Blo,
        int Kslice, int lda, int ldb,
        float* __restrict__ C, int ldc, size_t cstride) {
    char* smc = dynsm;
    uint32_t sb = smem_u32(smc);

    int tid = threadIdx.x;
    int wid = tid >> 5;
    int lane = tid & 31;
    int warp_m = wid & 3;
    int warp_n = wid >> 2;

    int m0 = blockIdx.y * 128;
    int n0 = blockIdx.x * 128;
    int koff = blockIdx.z * Kslice;
    C += (size_t)blockIdx.z * cstride;

    float acc[2][8][4] = {};

    uint32_t a_row_l = (uint32_t)(lane & 15);
    uint32_t a_col_l = (uint32_t)((lane >> 4) << 3);
    uint32_t b_row_l = (uint32_t)(((lane & 16) >> 1) + (lane & 7));
    uint32_t b_col_l = (uint32_t)(lane & 8);

    int lr[4], lcc[4];
#pragma unroll
    for (int q = 0; q < 4; q++) {
        int l = tid + q * 256;
        lr[q] = l >> 3;
        lcc[q] = l & 7;
    }

    int nchunks = Kslice >> 6;

    auto issue = [&](int st, int kc) {
        uint32_t sbase = sb + (uint32_t)st * STAGE_B;
#pragma unroll
        for (int q = 0; q < 4; q++) {
            int r = lr[q], c = lcc[q];
            uint32_t so = sbase + (uint32_t)(r * 144 + c * 16);
            size_t ga = (size_t)(m0 + r) * lda + koff + kc + c * 8;
            size_t gb = (size_t)(n0 + r) * ldb + koff + kc + c * 8;
            CP_ASYNC16(so + 0 * TILE_B, (const void*)(Ahi + ga));
            CP_ASYNC16(so + 1 * TILE_B, (const void*)(Alo + ga));
            CP_ASYNC16(so + 2 * TILE_B, (const void*)(Bhi + gb));
            CP_ASYNC16(so + 3 * TILE_B, (const void*)(Blo + gb));
        }
    };

    issue(0, 0);
    CP_COMMIT();

    for (int ch = 0; ch < nchunks; ch++) {
        if (ch + 1 < nchunks) {
            issue((ch + 1) & 1, (ch + 1) << 6);
            CP_COMMIT();
            CP_WAIT(1);
        } else {
            CP_WAIT(0);
        }
        __syncthreads();

        uint32_t sA = sb + (uint32_t)(ch & 1) * STAGE_B;
        uint32_t sB = sA + 2 * TILE_B;
#pragma unroll
        for (int ks = 0; ks < 4; ks++) {
            uint32_t ah[2][4], al[2][4];
#pragma unroll
            for (int mt = 0; mt < 2; mt++) {
                uint32_t ad = sA + (uint32_t)(warp_m * 32 + mt * 16 + a_row_l) * 144
                            + (uint32_t)(ks * 16 + a_col_l) * 2;
                LDSM_X4(ah[mt][0], ah[mt][1], ah[mt][2], ah[mt][3], ad);
                LDSM_X4(al[mt][0], al[mt][1], al[mt][2], al[mt][3], ad + TILE_B);
            }
            uint32_t bh[8][2], bl[8][2];
#pragma unroll
            for (int p = 0; p < 4; p++) {
                uint32_t bd = sB + (uint32_t)(warp_n * 64 + p * 16 + b_row_l) * 144
                            + (uint32_t)(ks * 16 + b_col_l) * 2;
                uint32_t q0, q1, q2, q3;
                LDSM_X4(q0, q1, q2, q3, bd);
                bh[2 * p][0] = q0; bh[2 * p][1] = q1;
                bh[2 * p + 1][0] = q2; bh[2 * p + 1][1] = q3;
                LDSM_X4(q0, q1, q2, q3, bd + TILE_B);
                bl[2 * p][0] = q0; bl[2 * p][1] = q1;
                bl[2 * p + 1][0] = q2; bl[2 * p + 1][1] = q3;
            }
#pragma unroll
            for (int mt = 0; mt < 2; mt++)
#pragma unroll
                for (int nt = 0; nt < 8; nt++)
                    MMA_BF16(acc[mt][nt], ah[mt], bh[nt]);
#pragma unroll
            for (int mt = 0; mt < 2; mt++)
#pragma unroll
                for (int nt = 0; nt < 8; nt++)
                    MMA_BF16(acc[mt][nt], ah[mt], bl[nt]);
#pragma unroll
            for (int mt = 0; mt < 2; mt++)
#pragma unroll
                for (int nt = 0; nt < 8; nt++)
                    MMA_BF16(acc[mt][nt], al[mt], bh[nt]);
        }
        __syncthreads();
    }

    int tr = lane >> 2;
    int tc = (lane & 3) * 2;
#pragma unroll
    for (int mt = 0; mt < 2; mt++) {
        int row = m0 + warp_m * 32 + mt * 16 + tr;
#pragma unroll
        for (int nt = 0; nt < 8; nt++) {
            int col = n0 + warp_n * 64 + nt * 8 + tc;
            *(float2*)&C[(size_t)row * ldc + col] =
                make_float2(acc[mt][nt][0], acc[mt][nt][1]);
            *(float2*)&C[(size_t)(row + 8) * ldc + col] =
                make_float2(acc[mt][nt][2], acc[mt][nt][3]);
        }
    }
}

// ---------------- fp16 HMMA GEMM, 2-term (upd: u = Y @ enc), split-K --------
#define STAGE_F (3 * TILE_B)        // 55296
#define TCF_SMEM (2 * STAGE_F)      // 110592
__global__ void __launch_bounds__(256, 1)
tc_gemm_f16(const __half* __restrict__ A,
            const __half* __restrict__ Bhi, const __half* __restrict__ Blo,
            int Kslice, int lda, int ldb,
            float* __restrict__ C, int ldc, size_t cstride) {
    char* smc = dynsm;
    uint32_t sb = smem_u32(smc);

    int tid = threadIdx.x;
    int wid = tid >> 5;
    int lane = tid & 31;
    int warp_m = wid & 3;
    int warp_n = wid >> 2;

    int m0 = blockIdx.y * 128;
    int n0 = blockIdx.x * 128;
    int koff = blockIdx.z * Kslice;
    C += (size_t)blockIdx.z * cstride;

    float acc[2][8][4] = {};

    uint32_t a_row_l = (uint32_t)(lane & 15);
    uint32_t a_col_l = (uint32_t)((lane >> 4) << 3);
    uint32_t b_row_l = (uint32_t)(((lane & 16) >> 1) + (lane & 7));
    uint32_t b_col_l = (uint32_t)(lane & 8);

    int lr[4], lcc[4];
#pragma unroll
    for (int q = 0; q < 4; q++) {
        int l = tid + q * 256;
        lr[q] = l >> 3;
        lcc[q] = l & 7;
    }

    int nchunks = Kslice >> 6;

    auto issue = [&](int st, int kc) {
        uint32_t sbase = sb + (uint32_t)st * STAGE_F;
#pragma unroll
        for (int q = 0; q < 4; q++) {
            int r = lr[q], c = lcc[q];
            uint32_t so = sbase + (uint32_t)(r * 144 + c * 16);
            size_t ga = (size_t)(m0 + r) * lda + koff + kc + c * 8;
            size_t gb = (size_t)(n0 + r) * ldb + koff + kc + c * 8;
            CP_ASYNC16(so + 0 * TILE_B, (const void*)(A + ga));
            CP_ASYNC16(so + 1 * TILE_B, (const void*)(Bhi + gb));
            CP_ASYNC16(so + 2 * TILE_B, (const void*)(Blo + gb));
        }
    };

    issue(0, 0);
    CP_COMMIT();

    for (int ch = 0; ch < nchunks; ch++) {
        if (ch + 1 < nchunks) {
            issue((ch + 1) & 1, (ch + 1) << 6);
            CP_COMMIT();
            CP_WAIT(1);
        } else {
            CP_WAIT(0);
        }
        __syncthreads();

        uint32_t sA = sb + (uint32_t)(ch & 1) * STAGE_F;
        uint32_t sB = sA + TILE_B;
#pragma unroll
        for (int ks = 0; ks < 4; ks++) {
            uint32_t aa[2][4];
#pragma unroll
            for (int mt = 0; mt < 2; mt++) {
                uint32_t ad = sA + (uint32_t)(warp_m * 32 + mt * 16 + a_row_l) * 144
                            + (uint32_t)(ks * 16 + a_col_l) * 2;
                LDSM_X4(aa[mt][0], aa[mt][1], aa[mt][2], aa[mt][3], ad);
            }
            uint32_t bh[8][2], bl[8][2];
#pragma unroll
            for (int p = 0; p < 4; p++) {
                uint32_t bd = sB + (uint32_t)(warp_n * 64 + p * 16 + b_row_l) * 144
                            + (uint32_t)(ks * 16 + b_col_l) * 2;
                uint32_t q0, q1, q2, q3;
                LDSM_X4(q0, q1, q2, q3, bd);
                bh[2 * p][0] = q0; bh[2 * p][1] = q1;
                bh[2 * p + 1][0] = q2; bh[2 * p + 1][1] = q3;
                LDSM_X4(q0, q1, q2, q3, bd + TILE_B);
                bl[2 * p][0] = q0; bl[2 * p][1] = q1;
                bl[2 * p + 1][0] = q2; bl[2 * p + 1][1] = q3;
            }
#pragma unroll
            for (int mt = 0; mt < 2; mt++)
#pragma unroll
                for (int nt = 0; nt < 8; nt++)
                    MMA_F16(acc[mt][nt], aa[mt], bh[nt]);
#pragma unroll
            for (int mt = 0; mt < 2; mt++)
#pragma unroll
                for (int nt = 0; nt < 8; nt++)
                    MMA_F16(acc[mt][nt], aa[mt], bl[nt]);
        }
        __syncthreads();
    }

    int tr = lane >> 2;
    int tc = (lane & 3) * 2;
#pragma unroll
    for (int mt = 0; mt < 2; mt++) {
        int row = m0 + warp_m * 32 + mt * 16 + tr;
#pragma unroll
        for (int nt = 0; nt < 8; nt++) {
            int col = n0 + warp_n * 64 + nt * 8 + tc;
            *(float2*)&C[(size_t)row * ldc + col] =
                make_float2(acc[mt][nt][0], acc[mt][nt][1]);
            *(float2*)&C[(size_t)(row + 8) * ldc + col] =
                make_float2(acc[mt][nt][2], acc[mt][nt][3]);
        }
    }
}

// ---------------- launch -----------------------------------------------------
extern "C" void kernel_launch(void* const* d_in, const int* in_sizes, int n_in,
                              void* d_out, int out_size) {
    const int* idx = (const int*)d_in[0];
    const float* wte = (const float*)d_in[1];
    const float* encoder = (const float*)d_in[2];
    const float* dec_x = (const float*)d_in[3];
    const float* dec_y = (const float*)d_in[4];
    const float* readout = (const float*)d_in[5];
    float* out = (float*)d_out;

    float *pv, *pH, *pup;
    __nv_bfloat16 *pvhi, *pvlo, *pRhi, *pRlo, *prdhi, *prdlo;
    __half *pvh16, *pvl16, *palnh16, *palnl16;
    __half *pwx, *pwy, *pench, *pencl, *pYf;
    __nv_bfloat16 *pRThi, *pRTlo, *pVThi, *pVTlo, *pMhi, *pMlo;
    cudaGetSymbolAddress((void**)&pv, g_v);
    cudaGetSymbolAddress((void**)&pH, g_H);
    cudaGetSymbolAddress((void**)&pup, g_upart);
    cudaGetSymbolAddress((void**)&pvhi, g_vhi);
    cudaGetSymbolAddress((void**)&pvlo, g_vlo);
    cudaGetSymbolAddress((void**)&pvh16, g_vh16);
    cudaGetSymbolAddress((void**)&pvl16, g_vl16);
    cudaGetSymbolAddress((void**)&pRhi, g_Rhi);
    cudaGetSymbolAddress((void**)&pRlo, g_Rlo);
    cudaGetSymbolAddress((void**)&palnh16, g_alnh16);
    cudaGetSymbolAddress((void**)&palnl16, g_alnl16);
    cudaGetSymbolAddress((void**)&pwx, g_wx);
    cudaGetSymbolAddress((void**)&pwy, g_wy);
    cudaGetSymbolAddress((void**)&pench, g_ench);
    cudaGetSymbolAddress((void**)&pencl, g_encl);
    cudaGetSymbolAddress((void**)&prdhi, g_rdhi);
    cudaGetSymbolAddress((void**)&prdlo, g_rdlo);
    cudaGetSymbolAddress((void**)&pYf, g_Yf);
    cudaGetSymbolAddress((void**)&pRThi, g_RThi);
    cudaGetSymbolAddress((void**)&pRTlo, g_RTlo);
    cudaGetSymbolAddress((void**)&pVThi, g_VThi);
    cudaGetSymbolAddress((void**)&pVTlo, g_VTlo);
    cudaGetSymbolAddress((void**)&pMhi, g_Mhi);
    cudaGetSymbolAddress((void**)&pMlo, g_Mlo);

    cudaFuncSetAttribute(tc_gemm,
                         cudaFuncAttributeMaxDynamicSharedMemorySize, TCG_SMEM);
    cudaFuncSetAttribute(tc_gemm_f16,
                         cudaFuncAttributeMaxDynamicSharedMemorySize, TCF_SMEM);
    cudaFuncSetAttribute(xy_gemm,
                         cudaFuncAttributeMaxDynamicSharedMemorySize, XY_SMEM);
    cudaFuncSetAttribute(kv_outer_kernel,
                         cudaFuncAttributeMaxDynamicSharedMemorySize, KVO_SMEM);
    cudaFuncSetAttribute(attn_out_kernel,
                         cudaFuncAttributeMaxDynamicSharedMemorySize, AO_SMEM);

    embed_ln_rope_kernel<<<BT, 256>>>(idx, wte, pv, pvhi, pvlo, pvh16, pvl16,
                                      pRhi, pRlo);
    conv_all_kernel<<<24832, 256>>>(dec_x, dec_y, encoder, readout,
                                    pwx, pwy, pench, pencl, prdhi, prdlo);

    for (int layer = 0; layer < LL; layer++) {
        split_T_both_kernel<<<dim3(TT / 32, DD / 32, 2 * BB), 256>>>(
            pRhi, pRlo, pvhi, pvlo, pRThi, pRTlo, pVThi, pVTlo);
        kv_outer_kernel<<<dim3(32, BB, 2), 512, KVO_SMEM>>>(pVThi, pVTlo,
                                                            pRThi, pRTlo, pH);
        prefix_split_kernel<<<dim3(256, BB), 256>>>(pH, pMhi, pMlo);
        attn_out_kernel<<<dim3(32, BB), 256, AO_SMEM>>>(pRhi, pRlo, pVThi, pVTlo,
                                                        pMhi, pMlo,
                                                        palnh16, palnl16);
        xy_gemm<<<dim3(BT / 128, NN / 128), 256, XY_SMEM>>>(
            pvh16, pvl16, palnh16, palnl16, pwx, pwy, pYf);
        tc_gemm_f16<<<dim3(DD / 128, BT / 128, SPLITK), 256, TCF_SMEM>>>(
            pYf, pench, pencl, NN / SPLITK, NN, NN, pup, DD, (size_t)BT * DD);
        ln_add_rope_kernel<<<BT, 256>>>(pup, pv, pvhi, pvlo, pvh16, pvl16,
                                        pRhi, pRlo);
    }

    tc_gemm<<<dim3(VOCAB / 128, BT / 128, 1), 256, TCG_SMEM>>>(
        pvhi, pvlo, prdhi, prdlo, DD, DD, DD, out, VOCAB, 0);
}

// round 17
// speedup vs baseline: 1.4940x; 1.0964x over previous
#include <cuda_runtime.h>
#include <cuda_bf16.h>
#include <cuda_fp16.h>
#include <math.h>
#include <stdint.h>

// Problem constants
#define BB 4
#define TT 2048
#define BT 8192      // B*T
#define DD 256
#define NN 8192
#define HH 4
#define MM 2048      // N/H
#define LL 6
#define VOCAB 256
#define EPS 1e-5f
#define SPLITK 8

// single dynamic-smem declaration shared by all kernels
extern __shared__ char dynsm[];

// ---------------- scratch buffers (device globals, no allocations) --------
__device__ float g_v[BT * DD];
__device__ float g_upart[SPLITK * BT * DD];                   // split-K partials
__device__ __nv_bfloat16 g_vhi[BT * DD], g_vlo[BT * DD];      // bf16 (readout)
__device__ __half g_vh16[BT * DD], g_vl16[BT * DD];           // fp16 (xy)
__device__ __nv_bfloat16 g_Rhi[BT * DD], g_Rlo[BT * DD];
__device__ __half g_alnh16[BT * DD], g_alnl16[BT * DD];       // fp16 (xy)
__device__ __half g_wx[NN * DD], g_wy[NN * DD];               // fp16 single weights
__device__ __half g_ench[DD * NN];                            // fp16 enc single
__device__ __nv_bfloat16 g_rdhi[VOCAB * DD], g_rdlo[VOCAB * DD];
__device__ __half g_Yf[(size_t)BT * NN];                      // 128 MB, fp16 Y
// linear-attention scratch (bf16 — needs range)
__device__ __nv_bfloat16 g_RThi[BB * DD * TT], g_RTlo[BB * DD * TT];
__device__ __nv_bfloat16 g_VThi[BB * DD * TT], g_VTlo[BB * DD * TT];
__device__ float g_H[(size_t)BB * 32 * DD * DD];
__device__ __nv_bfloat16 g_Mhi[(size_t)BB * 32 * DD * DD];
__device__ __nv_bfloat16 g_Mlo[(size_t)BB * 32 * DD * DD];

// ---------------- PTX helpers ----------------------------------------------
__device__ __forceinline__ uint32_t smem_u32(const void* p) {
    uint32_t a;
    asm("{ .reg .u64 t; cvta.to.shared.u64 t, %1; cvt.u32.u64 %0, t; }"
        : "=r"(a) : "l"(p));
    return a;
}

#define LDSM_X4(r0, r1, r2, r3, addr) \
    asm volatile("ldmatrix.sync.aligned.m8n8.x4.shared.b16 {%0,%1,%2,%3}, [%4];" \
        : "=r"(r0), "=r"(r1), "=r"(r2), "=r"(r3) : "r"(addr))

#define MMA_BF16(d, a, b) \
    asm volatile( \
        "mma.sync.aligned.m16n8k16.row.col.f32.bf16.bf16.f32 " \
        "{%0,%1,%2,%3}, {%4,%5,%6,%7}, {%8,%9}, {%0,%1,%2,%3};" \
        : "+f"((d)[0]), "+f"((d)[1]), "+f"((d)[2]), "+f"((d)[3]) \
        : "r"((a)[0]), "r"((a)[1]), "r"((a)[2]), "r"((a)[3]), \
          "r"((b)[0]), "r"((b)[1]))

#define MMA_F16(d, a, b) \
    asm volatile( \
        "mma.sync.aligned.m16n8k16.row.col.f32.f16.f16.f32 " \
        "{%0,%1,%2,%3}, {%4,%5,%6,%7}, {%8,%9}, {%0,%1,%2,%3};" \
        : "+f"((d)[0]), "+f"((d)[1]), "+f"((d)[2]), "+f"((d)[3]) \
        : "r"((a)[0]), "r"((a)[1]), "r"((a)[2]), "r"((a)[3]), \
          "r"((b)[0]), "r"((b)[1]))

#define CP_ASYNC16(dst, src) \
    asm volatile("cp.async.cg.shared.global [%0], [%1], 16;" \
        :: "r"(dst), "l"(src) : "memory")
#define CP_COMMIT() asm volatile("cp.async.commit_group;" ::: "memory")
#define CP_WAIT(N)  asm volatile("cp.async.wait_group %0;" :: "n"(N) : "memory")

// ---------------- misc helpers ----------------------------------------------
__device__ __forceinline__ float warp_sum(float v) {
#pragma unroll
    for (int o = 16; o > 0; o >>= 1) v += __shfl_xor_sync(0xffffffffu, v, o);
    return v;
}
__device__ __forceinline__ void split2(float x, __nv_bfloat16& h, __nv_bfloat16& l) {
    __nv_bfloat16 hh = __float2bfloat16(x);
    h = hh;
    l = __float2bfloat16(x - __bfloat162float(hh));
}
__device__ __forceinline__ void split2h(float x, __half& h, __half& l) {
    __half hh = __float2half(x);
    h = hh;
    l = __float2half(x - __half2float(hh));
}
__device__ __forceinline__ float rope_val(const float* rowbuf, int d, int t) {
    float x = rowbuf[d];
    float xr = (d < 128) ? -rowbuf[d + 128] : rowbuf[d - 128];
    int j = d & 127;
    float inv = expf(-(float)j * (2.f / 256.f) * 9.210340371976184f);
    float ang = (float)t * inv;
    const float TWO_PI_HI = 6.28318548202514648f;
    const float TWO_PI_LO = -1.74845553e-7f;
    float k = rintf(ang * 0.15915494309189535f);
    float r = fmaf(-k, TWO_PI_HI, ang);
    r = fmaf(-k, TWO_PI_LO, r);
    float sn = sinf(r), cs = cosf(r);
    return x * cs + xr * sn;
}

// ---------------- all weight conversions in one kernel ----------------------
__global__ void conv_all_kernel(const float* __restrict__ dec_x,
                                const float* __restrict__ dec_y,
                                const float* __restrict__ enc,
                                const float* __restrict__ rd,
                                __half* __restrict__ wx, __half* __restrict__ wy,
                                __half* __restrict__ ench,
                                __nv_bfloat16* __restrict__ rdhi,
                                __nv_bfloat16* __restrict__ rdlo) {
    int bid = blockIdx.x;
    if (bid < 8192) {
        size_t i = (size_t)bid * 256 + threadIdx.x;
        int d = (int)(i & 255);
        size_t n = i >> 8;
        int h = (int)(n >> 11), m = (int)(n & 2047);
        wx[i] = __float2half(dec_x[((size_t)h * DD + d) * MM + m]);
    } else if (bid < 16384) {
        size_t i = (size_t)(bid - 8192) * 256 + threadIdx.x;
        int d = (int)(i & 255);
        size_t n = i >> 8;
        int h = (int)(n >> 11), m = (int)(n & 2047);
        wy[i] = __float2half(dec_y[((size_t)h * DD + d) * MM + m]);
    } else if (bid < 24576) {
        size_t i = (size_t)(bid - 16384) * 256 + threadIdx.x;
        int n = (int)(i & 8191);
        int d = (int)(i >> 13);
        ench[i] = __float2half(enc[(size_t)n * DD + d]);
    } else {
        size_t i = (size_t)(bid - 24576) * 256 + threadIdx.x;
        int d = (int)(i & 255);
        int v = (int)(i >> 8);
        split2(rd[(size_t)d * VOCAB + v], rdhi[i], rdlo[i]);
    }
}

// ---------------- embed + LN + RoPE ------------------------------------------
__global__ void embed_ln_rope_kernel(const int* __restrict__ idx,
                                     const float* __restrict__ wte,
                                     float* __restrict__ out,
                                     __nv_bfloat16* __restrict__ ohi,
                                     __nv_bfloat16* __restrict__ olo,
                                     __half* __restrict__ oh16,
                                     __half* __restrict__ ol16,
                                     __nv_bfloat16* __restrict__ Rhi,
                                     __nv_bfloat16* __restrict__ Rlo) {
    __shared__ float sh[8];
    __shared__ float rowbuf[256];
    int row = blockIdx.x;
    int d = threadIdx.x;
    float x = wte[idx[row] * DD + d];
    int wid = d >> 5, lane = d & 31;
    float s = warp_sum(x);
    if (lane == 0) sh[wid] = s;
    __syncthreads();
    float tot = 0.f;
#pragma unroll
    for (int i = 0; i < 8; i++) tot += sh[i];
    float mu = tot * (1.f / 256.f);
    __syncthreads();
    float dx = x - mu;
    s = warp_sum(dx * dx);
    if (lane == 0) sh[wid] = s;
    __syncthreads();
    tot = 0.f;
#pragma unroll
    for (int i = 0; i < 8; i++) tot += sh[i];
    float r = dx * rsqrtf(tot * (1.f / 256.f) + EPS);
    int o = row * DD + d;
    out[o] = r;
    split2(r, ohi[o], olo[o]);
    split2h(r, oh16[o], ol16[o]);
    rowbuf[d] = r;
    __syncthreads();
    float val = rope_val(rowbuf, d, row & (TT - 1));
    split2(val, Rhi[o], Rlo[o]);
}

// ---------------- LN + residual add (sums SPLITK partials) + RoPE -----------
__global__ void ln_add_rope_kernel(const float* __restrict__ up,
                                   float* __restrict__ v,
                                   __nv_bfloat16* __restrict__ vhi,
                                   __nv_bfloat16* __restrict__ vlo,
                                   __half* __restrict__ vh16,
                                   __half* __restrict__ vl16,
                                   __nv_bfloat16* __restrict__ Rhi,
                                   __nv_bfloat16* __restrict__ Rlo) {
    __shared__ float sh[8];
    __shared__ float rowbuf[256];
    int row = blockIdx.x;
    int d = threadIdx.x;
    int o = row * DD + d;
    float x = 0.f;
#pragma unroll
    for (int p = 0; p < SPLITK; p++) x += up[(size_t)p * BT * DD + o];
    int wid = d >> 5, lane = d & 31;
    float s = warp_sum(x);
    if (lane == 0) sh[wid] = s;
    __syncthreads();
    float tot = 0.f;
#pragma unroll
    for (int i = 0; i < 8; i++) tot += sh[i];
    float mu = tot * (1.f / 256.f);
    __syncthreads();
    float dx = x - mu;
    s = warp_sum(dx * dx);
    if (lane == 0) sh[wid] = s;
    __syncthreads();
    tot = 0.f;
#pragma unroll
    for (int i = 0; i < 8; i++) tot += sh[i];
    float nv = v[o] + dx * rsqrtf(tot * (1.f / 256.f) + EPS);
    v[o] = nv;
    split2(nv, vhi[o], vlo[o]);
    split2h(nv, vh16[o], vl16[o]);
    rowbuf[d] = nv;
    __syncthreads();
    float val = rope_val(rowbuf, d, row & (TT - 1));
    split2(val, Rhi[o], Rlo[o]);
}

// ---------------- transpose (pure bf16 permute) for R and v hi/lo -----------
__global__ void split_T_both_kernel(const __nv_bfloat16* __restrict__ Rhi,
                                    const __nv_bfloat16* __restrict__ Rlo,
                                    const __nv_bfloat16* __restrict__ vhi,
                                    const __nv_bfloat16* __restrict__ vlo,
                                    __nv_bfloat16* __restrict__ RThi,
                                    __nv_bfloat16* __restrict__ RTlo,
                                    __nv_bfloat16* __restrict__ VThi,
                                    __nv_bfloat16* __restrict__ VTlo) {
    __shared__ __nv_bfloat16 th[32][34];
    __shared__ __nv_bfloat16 tl[32][34];
    int zb = blockIdx.z;
    int b = zb & 3;
    const __nv_bfloat16* hi_in = (zb < 4) ? Rhi : vhi;
    const __nv_bfloat16* lo_in = (zb < 4) ? Rlo : vlo;
    __nv_bfloat16* hi_out = (zb < 4) ? RThi : VThi;
    __nv_bfloat16* lo_out = (zb < 4) ? RTlo : VTlo;
    int t0 = blockIdx.x * 32;
    int d0 = blockIdx.y * 32;
    int tx = threadIdx.x & 31, ty = threadIdx.x >> 5;
#pragma unroll
    for (int i = 0; i < 4; i++) {
        int t = ty + i * 8;
        size_t g = ((size_t)(b * TT + t0 + t)) * DD + d0 + tx;
        th[t][tx] = hi_in[g];
        tl[t][tx] = lo_in[g];
    }
    __syncthreads();
#pragma unroll
    for (int i = 0; i < 4; i++) {
        int d = ty + i * 8;
        size_t o = ((size_t)(b * DD + d0 + d)) * TT + t0 + tx;
        hi_out[o] = th[tx][d];
        lo_out[o] = tl[tx][d];
    }
}

// ---------------- kv_outer: H[b][i] = V_i^T K_i (256x256, k=64) -------------
#define KVO_SMEM 110592
__global__ void __launch_bounds__(512, 1)
kv_outer_kernel(const __nv_bfloat16* __restrict__ VThi,
                const __nv_bfloat16* __restrict__ VTlo,
                const __nv_bfloat16* __restrict__ RThi,
                const __nv_bfloat16* __restrict__ RTlo,
                float* __restrict__ H) {
    char* smc = dynsm;
    uint32_t sb = smem_u32(smc);
    int i = blockIdx.x, b = blockIdx.y, e0 = blockIdx.z * 128;
    int s0 = i * 64;
    int tid = threadIdx.x;
    int wid = tid >> 5, lane = tid & 31;
    int wm = wid & 3, wn = wid >> 2;

    for (int l = tid; l < 1024; l += 512) {
        int r = l >> 3, c = l & 7;
        size_t g = ((size_t)(b * DD + e0 + r)) * TT + s0 + c * 8;
        uint32_t so = (uint32_t)(r * 144 + c * 16);
        *(uint4*)(smc + so) = *(const uint4*)(VThi + g);
        *(uint4*)(smc + 18432 + so) = *(const uint4*)(VTlo + g);
    }
    for (int l = tid; l < 2048; l += 512) {
        int r = l >> 3, c = l & 7;
        size_t g = ((size_t)(b * DD + r)) * TT + s0 + c * 8;
        uint32_t so = (uint32_t)(36864 + r * 144 + c * 16);
        *(uint4*)(smc + so) = *(const uint4*)(RThi + g);
        *(uint4*)(smc + 36864 + so) = *(const uint4*)(RTlo + g);
    }
    __syncthreads();

    uint32_t a_row_l = (uint32_t)(lane & 15);
    uint32_t a_col_l = (uint32_t)((lane >> 4) << 3);
    uint32_t b_row_l = (uint32_t)(((lane & 16) >> 1) + (lane & 7));
    uint32_t b_col_l = (uint32_t)(lane & 8);

    float acc[2][8][4] = {};
#pragma unroll
    for (int ks = 0; ks < 4; ks++) {
        uint32_t ah[2][4], al[2][4];
#pragma unroll
        for (int mi = 0; mi < 2; mi++) {
            uint32_t ad = sb + (uint32_t)(wm * 32 + mi * 16 + a_row_l) * 144
                        + (uint32_t)(ks * 16 + a_col_l) * 2;
            LDSM_X4(ah[mi][0], ah[mi][1], ah[mi][2], ah[mi][3], ad);
            LDSM_X4(al[mi][0], al[mi][1], al[mi][2], al[mi][3], ad + 18432);
        }
        uint32_t bh[8][2], bl[8][2];
#pragma unroll
        for (int p = 0; p < 4; p++) {
            uint32_t bd = sb + 36864 + (uint32_t)(wn * 64 + p * 16 + b_row_l) * 144
                        + (uint32_t)(ks * 16 + b_col_l) * 2;
            uint32_t q0, q1, q2, q3;
            LDSM_X4(q0, q1, q2, q3, bd);
            bh[2 * p][0] = q0; bh[2 * p][1] = q1;
            bh[2 * p + 1][0] = q2; bh[2 * p + 1][1] = q3;
            LDSM_X4(q0, q1, q2, q3, bd + 36864);
            bl[2 * p][0] = q0; bl[2 * p][1] = q1;
            bl[2 * p + 1][0] = q2; bl[2 * p + 1][1] = q3;
        }
#pragma unroll
        for (int mi = 0; mi < 2; mi++)
#pragma unroll
            for (int nt = 0; nt < 8; nt++)
                MMA_BF16(acc[mi][nt], ah[mi], bh[nt]);
#pragma unroll
        for (int mi = 0; mi < 2; mi++)
#pragma unroll
            for (int nt = 0; nt < 8; nt++)
                MMA_BF16(acc[mi][nt], ah[mi], bl[nt]);
#pragma unroll
        for (int mi = 0; mi < 2; mi++)
#pragma unroll
            for (int nt = 0; nt < 8; nt++)
                MMA_BF16(acc[mi][nt], al[mi], bh[nt]);
    }

    int tr = lane >> 2, tc = (lane & 3) * 2;
    size_t base = ((size_t)(b * 32 + i)) * 65536;
#pragma unroll
    for (int mi = 0; mi < 2; mi++) {
        int e = e0 + wm * 32 + mi * 16 + tr;
#pragma unroll
        for (int nt = 0; nt < 8; nt++) {
            int d = wn * 64 + nt * 8 + tc;
            *(float2*)&H[base + (size_t)e * 256 + d] =
                make_float2(acc[mi][nt][0], acc[mi][nt][1]);
            *(float2*)&H[base + (size_t)(e + 8) * 256 + d] =
                make_float2(acc[mi][nt][2], acc[mi][nt][3]);
        }
    }
}

// ---------------- exclusive prefix over chunks + bf16 split -----------------
__global__ void prefix_split_kernel(const float* __restrict__ H,
                                    __nv_bfloat16* __restrict__ Mhi,
                                    __nv_bfloat16* __restrict__ Mlo) {
    int b = blockIdx.y;
    int j = blockIdx.x * 256 + threadIdx.x;
    size_t base = (size_t)b * 32 * 65536 + j;
    float acc = 0.f;
#pragma unroll 4
    for (int i = 0; i < 32; i++) {
        size_t off = base + (size_t)i * 65536;
        __nv_bfloat16 h, l;
        split2(acc, h, l);
        Mhi[off] = h;
        Mlo[off] = l;
        acc += H[off];
    }
}

// ---------------- attn_out + fused row-LN ------------------------------------
#define AO_Q    0
#define AO_QLO  33792
#define AO_B    67584
#define AO_BLO  104448
#define AO_S    141312
#define AO_SLO  150528
#define AO_OBUF 67584
#define AO_SMEM 159744
__global__ void __launch_bounds__(256, 1)
attn_out_kernel(const __nv_bfloat16* __restrict__ Rhi,
                const __nv_bfloat16* __restrict__ Rlo,
                const __nv_bfloat16* __restrict__ VThi,
                const __nv_bfloat16* __restrict__ VTlo,
                const __nv_bfloat16* __restrict__ Mhi,
                const __nv_bfloat16* __restrict__ Mlo,
                __half* __restrict__ alnh16,
                __half* __restrict__ alnl16) {
    char* smc = dynsm;
    uint32_t sb = smem_u32(smc);
    int i = blockIdx.x, b = blockIdx.y;
    int q0 = i * 64;
    int tid = threadIdx.x;
    int wid = tid >> 5, lane = tid & 31;

    for (int l = tid; l < 2048; l += 256) {
        int r = l >> 5, c = l & 31;
        size_t g = ((size_t)(b * TT + q0 + r)) * DD + c * 8;
        uint32_t so = (uint32_t)(r * 528 + c * 16);
        *(uint4*)(smc + AO_Q + so) = *(const uint4*)(Rhi + g);
        *(uint4*)(smc + AO_QLO + so) = *(const uint4*)(Rlo + g);
    }
    for (int l = tid; l < 2048; l += 256) {
        int r = l >> 3, c = l & 7;
        size_t g = ((size_t)(b * DD + r)) * TT + q0 + c * 8;
        uint32_t so = (uint32_t)(r * 144 + c * 16);
        *(uint4*)(smc + AO_B + so) = *(const uint4*)(VThi + g);
        *(uint4*)(smc + AO_BLO + so) = *(const uint4*)(VTlo + g);
    }
    __syncthreads();

    uint32_t a_row_l = (uint32_t)(lane & 15);
    uint32_t a_col_l = (uint32_t)((lane >> 4) << 3);
    uint32_t b_row_l = (uint32_t)(((lane & 16) >> 1) + (lane & 7));
    uint32_t b_col_l = (uint32_t)(lane & 8);
    int tr = lane >> 2, tc = (lane & 3) * 2;

    int wt = wid & 1, ws = wid >> 1;
    {
        float sacc[2][2][4] = {};
#pragma unroll
        for (int ks = 0; ks < 16; ks++) {
            uint32_t ah[2][4], al[2][4];
#pragma unroll
            for (int mi = 0; mi < 2; mi++) {
                uint32_t ad = sb + AO_Q + (uint32_t)(wt * 32 + mi * 16 + a_row_l) * 528
                            + (uint32_t)(ks * 16 + a_col_l) * 2;
                LDSM_X4(ah[mi][0], ah[mi][1], ah[mi][2], ah[mi][3], ad);
                LDSM_X4(al[mi][0], al[mi][1], al[mi][2], al[mi][3], ad + 33792);
            }
            uint32_t bh[2][2], bl[2][2];
            {
                uint32_t bd = sb + AO_Q + (uint32_t)(ws * 16 + b_row_l) * 528
                            + (uint32_t)(ks * 16 + b_col_l) * 2;
                uint32_t p0, p1, p2, p3;
                LDSM_X4(p0, p1, p2, p3, bd);
                bh[0][0] = p0; bh[0][1] = p1; bh[1][0] = p2; bh[1][1] = p3;
                LDSM_X4(p0, p1, p2, p3, bd + 33792);
                bl[0][0] = p0; bl[0][1] = p1; bl[1][0] = p2; bl[1][1] = p3;
            }
#pragma unroll
            for (int mi = 0; mi < 2; mi++)
#pragma unroll
                for (int ni = 0; ni < 2; ni++) {
                    MMA_BF16(sacc[mi][ni], ah[mi], bh[ni]);
                    MMA_BF16(sacc[mi][ni], ah[mi], bl[ni]);
                    MMA_BF16(sacc[mi][ni], al[mi], bh[ni]);
                }
        }
#pragma unroll
        for (int mi = 0; mi < 2; mi++)
#pragma unroll
            for (int ni = 0; ni < 2; ni++) {
                int t0l = wt * 32 + mi * 16 + tr;
                int sl = ws * 16 + ni * 8 + tc;
                float s0v = (sl > t0l) ? 0.f : sacc[mi][ni][0];
                float s1v = (sl + 1 > t0l) ? 0.f : sacc[mi][ni][1];
                float s2v = (sl > t0l + 8) ? 0.f : sacc[mi][ni][2];
                float s3v = (sl + 1 > t0l + 8) ? 0.f : sacc[mi][ni][3];
                __nv_bfloat16 h0, l0, h1, l1;
                split2(s0v, h0, l0); split2(s1v, h1, l1);
                *(__nv_bfloat162*)(smc + AO_S + t0l * 144 + sl * 2) = __halves2bfloat162(h0, h1);
                *(__nv_bfloat162*)(smc + AO_SLO + t0l * 144 + sl * 2) = __halves2bfloat162(l0, l1);
                split2(s2v, h0, l0); split2(s3v, h1, l1);
                *(__nv_bfloat162*)(smc + AO_S + (t0l + 8) * 144 + sl * 2) = __halves2bfloat162(h0, h1);
                *(__nv_bfloat162*)(smc + AO_SLO + (t0l + 8) * 144 + sl * 2) = __halves2bfloat162(l0, l1);
            }
    }
    __syncthreads();

    int we = wid >> 1;
    float oacc[2][8][4] = {};
#pragma unroll
    for (int ks = 0; ks < 4; ks++) {
        uint32_t ah[2][4], al[2][4];
#pragma unroll
        for (int mi = 0; mi < 2; mi++) {
            uint32_t ad = sb + AO_S + (uint32_t)(wt * 32 + mi * 16 + a_row_l) * 144
                        + (uint32_t)(ks * 16 + a_col_l) * 2;
            LDSM_X4(ah[mi][0], ah[mi][1], ah[mi][2], ah[mi][3], ad);
            LDSM_X4(al[mi][0], al[mi][1], al[mi][2], al[mi][3], ad + 9216);
        }
        uint32_t bh[8][2], bl[8][2];
#pragma unroll
        for (int p = 0; p < 4; p++) {
            uint32_t bd = sb + AO_B + (uint32_t)(we * 64 + p * 16 + b_row_l) * 144
                        + (uint32_t)(ks * 16 + b_col_l) * 2;
            uint32_t p0, p1, p2, p3;
            LDSM_X4(p0, p1, p2, p3, bd);
            bh[2 * p][0] = p0; bh[2 * p][1] = p1;
            bh[2 * p + 1][0] = p2; bh[2 * p + 1][1] = p3;
            LDSM_X4(p0, p1, p2, p3, bd + 36864);
            bl[2 * p][0] = p0; bl[2 * p][1] = p1;
            bl[2 * p + 1][0] = p2; bl[2 * p + 1][1] = p3;
        }
#pragma unroll
        for (int mi = 0; mi < 2; mi++)
#pragma unroll
            for (int nt = 0; nt < 8; nt++) {
                MMA_BF16(oacc[mi][nt], ah[mi], bh[nt]);
                MMA_BF16(oacc[mi][nt], ah[mi], bl[nt]);
                MMA_BF16(oacc[mi][nt], al[mi], bh[nt]);
            }
    }
    __syncthreads();

    size_t mbase = ((size_t)(b * 32 + i)) * 65536;
    for (int dc = 0; dc < 4; dc++) {
        for (int l = tid; l < 2048; l += 256) {
            int r = l >> 3, c = l & 7;
            size_t g = mbase + (size_t)r * 256 + dc * 64 + c * 8;
            uint32_t so = (uint32_t)(r * 144 + c * 16);
            *(uint4*)(smc + AO_B + so) = *(const uint4*)(Mhi + g);
            *(uint4*)(smc + AO_BLO + so) = *(const uint4*)(Mlo + g);
        }
        __syncthreads();
#pragma unroll
        for (int ks = 0; ks < 4; ks++) {
            int ksg = dc * 4 + ks;
            uint32_t ah[2][4], al[2][4];
#pragma unroll
            for (int mi = 0; mi < 2; mi++) {
                uint32_t ad = sb + AO_Q + (uint32_t)(wt * 32 + mi * 16 + a_row_l) * 528
                            + (uint32_t)(ksg * 16 + a_col_l) * 2;
                LDSM_X4(ah[mi][0], ah[mi][1], ah[mi][2], ah[mi][3], ad);
                LDSM_X4(al[mi][0], al[mi][1], al[mi][2], al[mi][3], ad + 33792);
            }
            uint32_t bh[8][2], bl[8][2];
#pragma unroll
            for (int p = 0; p < 4; p++) {
                uint32_t bd = sb + AO_B + (uint32_t)(we * 64 + p * 16 + b_row_l) * 144
                            + (uint32_t)(ks * 16 + b_col_l) * 2;
                uint32_t p0, p1, p2, p3;
                LDSM_X4(p0, p1, p2, p3, bd);
                bh[2 * p][0] = p0; bh[2 * p][1] = p1;
                bh[2 * p + 1][0] = p2; bh[2 * p + 1][1] = p3;
                LDSM_X4(p0, p1, p2, p3, bd + 36864);
                bl[2 * p][0] = p0; bl[2 * p][1] = p1;
                bl[2 * p + 1][0] = p2; bl[2 * p + 1][1] = p3;
            }
#pragma unroll
            for (int mi = 0; mi < 2; mi++)
#pragma unroll
                for (int nt = 0; nt < 8; nt++) {
                    MMA_BF16(oacc[mi][nt], ah[mi], bh[nt]);
                    MMA_BF16(oacc[mi][nt], ah[mi], bl[nt]);
                    MMA_BF16(oacc[mi][nt], al[mi], bh[nt]);
                }
        }
        __syncthreads();
    }

    float* obuf = (float*)(smc + AO_OBUF);
#pragma unroll
    for (int mi = 0; mi < 2; mi++) {
        int rl = wt * 32 + mi * 16 + tr;
#pragma unroll
        for (int nt = 0; nt < 8; nt++) {
            int col = we * 64 + nt * 8 + tc;
            obuf[rl * 260 + col] = oacc[mi][nt][0];
            obuf[rl * 260 + col + 1] = oacc[mi][nt][1];
            obuf[(rl + 8) * 260 + col] = oacc[mi][nt][2];
            obuf[(rl + 8) * 260 + col + 1] = oacc[mi][nt][3];
        }
    }
    __syncthreads();

    for (int rr2 = 0; rr2 < 8; rr2++) {
        int r = wid * 8 + rr2;
        float vals[8];
        float s = 0.f;
#pragma unroll
        for (int k = 0; k < 8; k++) {
            vals[k] = obuf[r * 260 + lane + 32 * k];
            s += vals[k];
        }
        s = warp_sum(s);
        float mu = s * (1.f / 256.f);
        float q = 0.f;
#pragma unroll
        for (int k = 0; k < 8; k++) {
            float dxx = vals[k] - mu;
            q += dxx * dxx;
        }
        q = warp_sum(q);
        float rstd = rsqrtf(q * (1.f / 256.f) + EPS);
        size_t gbase = ((size_t)(b * TT + q0 + r)) * DD;
#pragma unroll
        for (int k = 0; k < 8; k++) {
            __half h, l;
            split2h((vals[k] - mu) * rstd, h, l);
            alnh16[gbase + lane + 32 * k] = h;
            alnl16[gbase + lane + 32 * k] = l;
        }
    }
}

// ---------------- fused XY GEMM: fp16 hi/lo activations x fp16 single W ------
#define XT 10240                // 128 rows * 80B (32 fp16 cols padded)
#define XSTG (6 * XT)           // 61440
#define XY_SMEM (2 * XSTG)      // 122880
__global__ void __launch_bounds__(256, 1)
xy_gemm(const __half* __restrict__ vhi, const __half* __restrict__ vlo,
        const __half* __restrict__ alnhi, const __half* __restrict__ alnlo,
        const __half* __restrict__ wx, const __half* __restrict__ wy,
        __half* __restrict__ Yf) {
    char* smc = dynsm;
    uint32_t sb = smem_u32(smc);

    int tid = threadIdx.x;
    int wid = tid >> 5;
    int lane = tid & 31;
    int warp_m = wid & 3;
    int warp_n = wid >> 2;

    int m0 = blockIdx.x * 128;
    int n0 = blockIdx.y * 128;

    float accx[2][8][4] = {};
    float accy[2][8][4] = {};

    uint32_t a_row_l = (uint32_t)(lane & 15);
    uint32_t a_col_l = (uint32_t)((lane >> 4) << 3);
    uint32_t b_row_l = (uint32_t)(((lane & 16) >> 1) + (lane & 7));
    uint32_t b_col_l = (uint32_t)(lane & 8);

#define XY_ISSUE(st, kc) do {                                                  \
    uint32_t sbase = sb + (uint32_t)(st) * XSTG;                               \
    _Pragma("unroll")                                                          \
    for (int q = 0; q < 12; q++) {                                             \
        int l = tid + q * 256;                                                 \
        int tile = l >> 9;                                                     \
        int idx = l & 511;                                                     \
        int r = idx >> 2, c = idx & 3;                                         \
        const __half* mat;                                                     \
        int rb;                                                                \
        switch (tile) {                                                        \
            case 0: mat = vhi;   rb = m0; break;                               \
            case 1: mat = vlo;   rb = m0; break;                               \
            case 2: mat = alnhi; rb = m0; break;                               \
            case 3: mat = alnlo; rb = m0; break;                               \
            case 4: mat = wx;    rb = n0; break;                               \
            default: mat = wy;   rb = n0; break;                               \
        }                                                                      \
        size_t g = (size_t)(rb + r) * DD + (kc) + c * 8;                       \
        uint32_t dst = sbase + (uint32_t)tile * XT + (uint32_t)(r * 80 + c * 16); \
        CP_ASYNC16(dst, (const void*)(mat + g));                               \
    }                                                                          \
} while (0)

    XY_ISSUE(0, 0);
    CP_COMMIT();

    for (int ch = 0; ch < 8; ch++) {
        if (ch + 1 < 8) {
            XY_ISSUE((ch + 1) & 1, (ch + 1) << 5);
            CP_COMMIT();
            CP_WAIT(1);
        } else {
            CP_WAIT(0);
        }
        __syncthreads();

        uint32_t S = sb + (uint32_t)(ch & 1) * XSTG;
#pragma unroll
        for (int ks = 0; ks < 2; ks++) {
            uint32_t arow_off = (uint32_t)(warp_m * 32 + a_row_l) * 80
                              + (uint32_t)(ks * 16 + a_col_l) * 2;
            uint32_t brow_off = (uint32_t)(warp_n * 64 + b_row_l) * 80
                              + (uint32_t)(ks * 16 + b_col_l) * 2;
            uint32_t ah[2][4], al[2][4], bw[8][2];
            // ---- X: A = v (hi/lo), B = wx (single) ----
#pragma unroll
            for (int mt = 0; mt < 2; mt++) {
                uint32_t ad = S + arow_off + (uint32_t)(mt * 16 * 80);
                LDSM_X4(ah[mt][0], ah[mt][1], ah[mt][2], ah[mt][3], ad);
                LDSM_X4(al[mt][0], al[mt][1], al[mt][2], al[mt][3], ad + XT);
            }
#pragma unroll
            for (int p = 0; p < 4; p++) {
                uint32_t bd = S + 4 * XT + brow_off + (uint32_t)(p * 16 * 80);
                uint32_t q0, q1, q2, q3;
                LDSM_X4(q0, q1, q2, q3, bd);
                bw[2 * p][0] = q0; bw[2 * p][1] = q1;
                bw[2 * p + 1][0] = q2; bw[2 * p + 1][1] = q3;
            }
#pragma unroll
            for (int mt = 0; mt < 2; mt++)
#pragma unroll
                for (int nt = 0; nt < 8; nt++)
                    MMA_F16(accx[mt][nt], ah[mt], bw[nt]);
#pragma unroll
            for (int mt = 0; mt < 2; mt++)
#pragma unroll
                for (int nt = 0; nt < 8; nt++)
                    MMA_F16(accx[mt][nt], al[mt], bw[nt]);
            // ---- Y: A = aln (hi/lo), B = wy (single) ----
#pragma unroll
            for (int mt = 0; mt < 2; mt++) {
                uint32_t ad = S + 2 * XT + arow_off + (uint32_t)(mt * 16 * 80);
                LDSM_X4(ah[mt][0], ah[mt][1], ah[mt][2], ah[mt][3], ad);
                LDSM_X4(al[mt][0], al[mt][1], al[mt][2], al[mt][3], ad + XT);
            }
#pragma unroll
            for (int p = 0; p < 4; p++) {
                uint32_t bd = S + 5 * XT + brow_off + (uint32_t)(p * 16 * 80);
                uint32_t q0, q1, q2, q3;
                LDSM_X4(q0, q1, q2, q3, bd);
                bw[2 * p][0] = q0; bw[2 * p][1] = q1;
                bw[2 * p + 1][0] = q2; bw[2 * p + 1][1] = q3;
            }
#pragma unroll
            for (int mt = 0; mt < 2; mt++)
#pragma unroll
                for (int nt = 0; nt < 8; nt++)
                    MMA_F16(accy[mt][nt], ah[mt], bw[nt]);
#pragma unroll
            for (int mt = 0; mt < 2; mt++)
#pragma unroll
                for (int nt = 0; nt < 8; nt++)
                    MMA_F16(accy[mt][nt], al[mt], bw[nt]);
        }
        __syncthreads();
    }

    int tr = lane >> 2;
    int tc = (lane & 3) * 2;
#pragma unroll
    for (int mt = 0; mt < 2; mt++) {
        int row = m0 + warp_m * 32 + mt * 16 + tr;
#pragma unroll
        for (int nt = 0; nt < 8; nt++) {
            int col = n0 + warp_n * 64 + nt * 8 + tc;
            size_t i0 = (size_t)row * NN + col;
            size_t i1 = (size_t)(row + 8) * NN + col;
            float g0 = fmaxf(accx[mt][nt][0], 0.f) * fmaxf(accy[mt][nt][0], 0.f);
            float g1 = fmaxf(accx[mt][nt][1], 0.f) * fmaxf(accy[mt][nt][1], 0.f);
            float g2 = fmaxf(accx[mt][nt][2], 0.f) * fmaxf(accy[mt][nt][2], 0.f);
            float g3 = fmaxf(accx[mt][nt][3], 0.f) * fmaxf(accy[mt][nt][3], 0.f);
            *(__half2*)(Yf + i0) = __floats2half2_rn(g0, g1);
            *(__half2*)(Yf + i1) = __floats2half2_rn(g2, g3);
        }
    }
}

// ---------------- bf16 3-term GEMM (readout) ---------------------------------
#define TILE_B 18432
#define STAGE_B (4 * TILE_B)
#define TCG_SMEM (2 * STAGE_B)
__global__ void __launch_bounds__(256, 1)
tc_gemm(const __nv_bfloat16* __restrict__ Ahi, const __nv_bfloat16* __restrict__ Alo,
        const __nv_bfloat16* __restrict__ Bhi, const __nv_bfloat16* __restrict__ Blo,
        int Kslice, int lda, int ldb,
        float* __restrict__ C, int ldc, size_t cstride) {
    char* smc = dynsm;
    uint32_t sb = smem_u32(smc);

    int tid = threadIdx.x;
    int wid = tid >> 5;
    int lane = tid & 31;
    int warp_m = wid & 3;
    int warp_n = wid >> 2;

    int m0 = blockIdx.y * 128;
    int n0 = blockIdx.x * 128;
    int koff = blockIdx.z * Kslice;
    C += (size_t)blockIdx.z * cstride;

    float acc[2][8][4] = {};

    uint32_t a_row_l = (uint32_t)(lane & 15);
    uint32_t a_col_l = (uint32_t)((lane >> 4) << 3);
    uint32_t b_row_l = (uint32_t)(((lane & 16) >> 1) + (lane & 7));
    uint32_t b_col_l = (uint32_t)(lane & 8);

    int lr[4], lcc[4];
#pragma unroll
    for (int q = 0; q < 4; q++) {
        int l = tid + q * 256;
        lr[q] = l >> 3;
        lcc[q] = l & 7;
    }

    int nchunks = Kslice >> 6;

    auto issue = [&](int st, int kc) {
        uint32_t sbase = sb + (uint32_t)st * STAGE_B;
#pragma unroll
        for (int q = 0; q < 4; q++) {
            int r = lr[q], c = lcc[q];
            uint32_t so = sbase + (uint32_t)(r * 144 + c * 16);
            size_t ga = (size_t)(m0 + r) * lda + koff + kc + c * 8;
            size_t gb = (size_t)(n0 + r) * ldb + koff + kc + c * 8;
            CP_ASYNC16(so + 0 * TILE_B, (const void*)(Ahi + ga));
            CP_ASYNC16(so + 1 * TILE_B, (const void*)(Alo + ga));
            CP_ASYNC16(so + 2 * TILE_B, (const void*)(Bhi + gb));
            CP_ASYNC16(so + 3 * TILE_B, (const void*)(Blo + gb));
        }
    };

    issue(0, 0);
    CP_COMMIT();

    for (int ch = 0; ch < nchunks; ch++) {
        if (ch + 1 < nchunks) {
            issue((ch + 1) & 1, (ch + 1) << 6);
            CP_COMMIT();
            CP_WAIT(1);
        } else {
            CP_WAIT(0);
        }
        __syncthreads();

        uint32_t sA = sb + (uint32_t)(ch & 1) * STAGE_B;
        uint32_t sB = sA + 2 * TILE_B;
#pragma unroll
        for (int ks = 0; ks < 4; ks++) {
            uint32_t ah[2][4], al[2][4];
#pragma unroll
            for (int mt = 0; mt < 2; mt++) {
                uint32_t ad = sA + (uint32_t)(warp_m * 32 + mt * 16 + a_row_l) * 144
                            + (uint32_t)(ks * 16 + a_col_l) * 2;
                LDSM_X4(ah[mt][0], ah[mt][1], ah[mt][2], ah[mt][3], ad);
                LDSM_X4(al[mt][0], al[mt][1], al[mt][2], al[mt][3], ad + TILE_B);
            }
            uint32_t bh[8][2], bl[8][2];
#pragma unroll
            for (int p = 0; p < 4; p++) {
                uint32_t bd = sB + (uint32_t)(warp_n * 64 + p * 16 + b_row_l) * 144
                            + (uint32_t)(ks * 16 + b_col_l) * 2;
                uint32_t q0, q1, q2, q3;
                LDSM_X4(q0, q1, q2, q3, bd);
                bh[2 * p][0] = q0; bh[2 * p][1] = q1;
                bh[2 * p + 1][0] = q2; bh[2 * p + 1][1] = q3;
                LDSM_X4(q0, q1, q2, q3, bd + TILE_B);
                bl[2 * p][0] = q0; bl[2 * p][1] = q1;
                bl[2 * p + 1][0] = q2; bl[2 * p + 1][1] = q3;
            }
#pragma unroll
            for (int mt = 0; mt < 2; mt++)
#pragma unroll
                for (int nt = 0; nt < 8; nt++)
                    MMA_BF16(acc[mt][nt], ah[mt], bh[nt]);
#pragma unroll
            for (int mt = 0; mt < 2; mt++)
#pragma unroll
                for (int nt = 0; nt < 8; nt++)
                    MMA_BF16(acc[mt][nt], ah[mt], bl[nt]);
#pragma unroll
            for (int mt = 0; mt < 2; mt++)
#pragma unroll
                for (int nt = 0; nt < 8; nt++)
                    MMA_BF16(acc[mt][nt], al[mt], bh[nt]);
        }
        __syncthreads();
    }

    int tr = lane >> 2;
    int tc = (lane & 3) * 2;
#pragma unroll
    for (int mt = 0; mt < 2; mt++) {
        int row = m0 + warp_m * 32 + mt * 16 + tr;
#pragma unroll
        for (int nt = 0; nt < 8; nt++) {
            int col = n0 + warp_n * 64 + nt * 8 + tc;
            *(float2*)&C[(size_t)row * ldc + col] =
                make_float2(acc[mt][nt][0], acc[mt][nt][1]);
            *(float2*)&C[(size_t)(row + 8) * ldc + col] =
                make_float2(acc[mt][nt][2], acc[mt][nt][3]);
        }
    }
}

// ---------------- fp16 1-term GEMM (upd: u = Y @ enc), split-K --------------
#define STAGE_F (2 * TILE_B)        // 36864
#define TCF_SMEM (2 * STAGE_F)      // 73728
__global__ void __launch_bounds__(256, 1)
tc_gemm_f16(const __half* __restrict__ A,
            const __half* __restrict__ B,
            int Kslice, int lda, int ldb,
            float* __restrict__ C, int ldc, size_t cstride) {
    char* smc = dynsm;
    uint32_t sb = smem_u32(smc);

    int tid = threadIdx.x;
    int wid = tid >> 5;
    int lane = tid & 31;
    int warp_m = wid & 3;
    int warp_n = wid >> 2;

    int m0 = blockIdx.y * 128;
    int n0 = blockIdx.x * 128;
    int koff = blockIdx.z * Kslice;
    C += (size_t)blockIdx.z * cstride;

    float acc[2][8][4] = {};

    uint32_t a_row_l = (uint32_t)(lane & 15);
    uint32_t a_col_l = (uint32_t)((lane >> 4) << 3);
    uint32_t b_row_l = (uint32_t)(((lane & 16) >> 1) + (lane & 7));
    uint32_t b_col_l = (uint32_t)(lane & 8);

    int lr[4], lcc[4];
#pragma unroll
    for (int q = 0; q < 4; q++) {
        int l = tid + q * 256;
        lr[q] = l >> 3;
        lcc[q] = l & 7;
    }

    int nchunks = Kslice >> 6;

    auto issue = [&](int st, int kc) {
        uint32_t sbase = sb + (uint32_t)st * STAGE_F;
#pragma unroll
        for (int q = 0; q < 4; q++) {
            int r = lr[q], c = lcc[q];
            uint32_t so = sbase + (uint32_t)(r * 144 + c * 16);
            size_t ga = (size_t)(m0 + r) * lda + koff + kc + c * 8;
            size_t gb = (size_t)(n0 + r) * ldb + koff + kc + c * 8;
            CP_ASYNC16(so + 0 * TILE_B, (const void*)(A + ga));
            CP_ASYNC16(so + 1 * TILE_B, (const void*)(B + gb));
        }
    };

    issue(0, 0);
    CP_COMMIT();

    for (int ch = 0; ch < nchunks; ch++) {
        if (ch + 1 < nchunks) {
            issue((ch + 1) & 1, (ch + 1) << 6);
            CP_COMMIT();
            CP_WAIT(1);
        } else {
            CP_WAIT(0);
        }
        __syncthreads();

        uint32_t sA = sb + (uint32_t)(ch & 1) * STAGE_F;
        uint32_t sB = sA + TILE_B;
#pragma unroll
        for (int ks = 0; ks < 4; ks++) {
            uint32_t aa[2][4];
#pragma unroll
            for (int mt = 0; mt < 2; mt++) {
                uint32_t ad = sA + (uint32_t)(warp_m * 32 + mt * 16 + a_row_l) * 144
                            + (uint32_t)(ks * 16 + a_col_l) * 2;
                LDSM_X4(aa[mt][0], aa[mt][1], aa[mt][2], aa[mt][3], ad);
            }
            uint32_t bw[8][2];
#pragma unroll
            for (int p = 0; p < 4; p++) {
                uint32_t bd = sB + (uint32_t)(warp_n * 64 + p * 16 + b_row_l) * 144
                            + (uint32_t)(ks * 16 + b_col_l) * 2;
                uint32_t q0, q1, q2, q3;
                LDSM_X4(q0, q1, q2, q3, bd);
                bw[2 * p][0] = q0; bw[2 * p][1] = q1;
                bw[2 * p + 1][0] = q2; bw[2 * p + 1][1] = q3;
            }
#pragma unroll
            for (int mt = 0; mt < 2; mt++)
#pragma unroll
                for (int nt = 0; nt < 8; nt++)
                    MMA_F16(acc[mt][nt], aa[mt], bw[nt]);
        }
        __syncthreads();
    }

    int tr = lane >> 2;
    int tc = (lane & 3) * 2;
#pragma unroll
    for (int mt = 0; mt < 2; mt++) {
        int row = m0 + warp_m * 32 + mt * 16 + tr;
#pragma unroll
        for (int nt = 0; nt < 8; nt++) {
            int col = n0 + warp_n * 64 + nt * 8 + tc;
            *(float2*)&C[(size_t)row * ldc + col] =
                make_float2(acc[mt][nt][0], acc[mt][nt][1]);
            *(float2*)&C[(size_t)(row + 8) * ldc + col] =
                make_float2(acc[mt][nt][2], acc[mt][nt][3]);
        }
    }
}

// ---------------- launch -----------------------------------------------------
extern "C" void kernel_launch(void* const* d_in, const int* in_sizes, int n_in,
                              void* d_out, int out_size) {
    const int* idx = (const int*)d_in[0];
    const float* wte = (const float*)d_in[1];
    const float* encoder = (const float*)d_in[2];
    const float* dec_x = (const float*)d_in[3];
    const float* dec_y = (const float*)d_in[4];
    const float* readout = (const float*)d_in[5];
    float* out = (float*)d_out;

    float *pv, *pH, *pup;
    __nv_bfloat16 *pvhi, *pvlo, *pRhi, *pRlo, *prdhi, *prdlo;
    __half *pvh16, *pvl16, *palnh16, *palnl16;
    __half *pwx, *pwy, *pench, *pYf;
    __nv_bfloat16 *pRThi, *pRTlo, *pVThi, *pVTlo, *pMhi, *pMlo;
    cudaGetSymbolAddress((void**)&pv, g_v);
    cudaGetSymbolAddress((void**)&pH, g_H);
    cudaGetSymbolAddress((void**)&pup, g_upart);
    cudaGetSymbolAddress((void**)&pvhi, g_vhi);
    cudaGetSymbolAddress((void**)&pvlo, g_vlo);
    cudaGetSymbolAddress((void**)&pvh16, g_vh16);
    cudaGetSymbolAddress((void**)&pvl16, g_vl16);
    cudaGetSymbolAddress((void**)&pRhi, g_Rhi);
    cudaGetSymbolAddress((void**)&pRlo, g_Rlo);
    cudaGetSymbolAddress((void**)&palnh16, g_alnh16);
    cudaGetSymbolAddress((void**)&palnl16, g_alnl16);
    cudaGetSymbolAddress((void**)&pwx, g_wx);
    cudaGetSymbolAddress((void**)&pwy, g_wy);
    cudaGetSymbolAddress((void**)&pench, g_ench);
    cudaGetSymbolAddress((void**)&prdhi, g_rdhi);
    cudaGetSymbolAddress((void**)&prdlo, g_rdlo);
    cudaGetSymbolAddress((void**)&pYf, g_Yf);
    cudaGetSymbolAddress((void**)&pRThi, g_RThi);
    cudaGetSymbolAddress((void**)&pRTlo, g_RTlo);
    cudaGetSymbolAddress((void**)&pVThi, g_VThi);
    cudaGetSymbolAddress((void**)&pVTlo, g_VTlo);
    cudaGetSymbolAddress((void**)&pMhi, g_Mhi);
    cudaGetSymbolAddress((void**)&pMlo, g_Mlo);

    cudaFuncSetAttribute(tc_gemm,
                         cudaFuncAttributeMaxDynamicSharedMemorySize, TCG_SMEM);
    cudaFuncSetAttribute(tc_gemm_f16,
                         cudaFuncAttributeMaxDynamicSharedMemorySize, TCF_SMEM);
    cudaFuncSetAttribute(xy_gemm,
                         cudaFuncAttributeMaxDynamicSharedMemorySize, XY_SMEM);
    cudaFuncSetAttribute(kv_outer_kernel,
                         cudaFuncAttributeMaxDynamicSharedMemorySize, KVO_SMEM);
    cudaFuncSetAttribute(attn_out_kernel,
                         cudaFuncAttributeMaxDynamicSharedMemorySize, AO_SMEM);

    embed_ln_rope_kernel<<<BT, 256>>>(idx, wte, pv, pvhi, pvlo, pvh16, pvl16,
                                      pRhi, pRlo);
    conv_all_kernel<<<24832, 256>>>(dec_x, dec_y, encoder, readout,
                                    pwx, pwy, pench, prdhi, prdlo);

    for (int layer = 0; layer < LL; layer++) {
        split_T_both_kernel<<<dim3(TT / 32, DD / 32, 2 * BB), 256>>>(
            pRhi, pRlo, pvhi, pvlo, pRThi, pRTlo, pVThi, pVTlo);
        kv_outer_kernel<<<dim3(32, BB, 2), 512, KVO_SMEM>>>(pVThi, pVTlo,
                                                            pRThi, pRTlo, pH);
        prefix_split_kernel<<<dim3(256, BB), 256>>>(pH, pMhi, pMlo);
        attn_out_kernel<<<dim3(32, BB), 256, AO_SMEM>>>(pRhi, pRlo, pVThi, pVTlo,
                                                        pMhi, pMlo,
                                                        palnh16, palnl16);
        xy_gemm<<<dim3(BT / 128, NN / 128), 256, XY_SMEM>>>(
            pvh16, pvl16, palnh16, palnl16, pwx, pwy, pYf);
        tc_gemm_f16<<<dim3(DD / 128, BT / 128, SPLITK), 256, TCF_SMEM>>>(
            pYf, pench, NN / SPLITK, NN, NN, pup, DD, (size_t)BT * DD);
        ln_add_rope_kernel<<<BT, 256>>>(pup, pv, pvhi, pvlo, pvh16, pvl16,
                                        pRhi, pRlo);
    }

    tc_gemm<<<dim3(VOCAB / 128, BT / 128, 1), 256, TCG_SMEM>>>(
        pvhi, pvlo, prdhi, prdlo, DD, DD, DD, out, VOCAB, 0);
}